// round 1
// baseline (speedup 1.0000x reference)
#include <cuda_runtime.h>
#include <math.h>

#define S_LEN 2048
#define DM    1024
#define NH    16
#define DK    64
#define SCALE 0.125f
#define EPSN  1e-6f

// Scratch (static __device__ — allocation-free per harness rules)
__device__ float g_Q[(size_t)NH * S_LEN * DK];   // [H][S][64], L2-normalized in place
__device__ float g_K[(size_t)NH * S_LEN * DK];
__device__ float g_V[(size_t)NH * S_LEN * DK];
__device__ float g_att[(size_t)S_LEN * DM];      // attended, [S][H*64]

// ---------------------------------------------------------------------------
// Tiled fp32 GEMM: C[M,N] = A[M,K] @ B[K,N].
// 128x128 block tile, BK=16, 256 threads, 8x8 per thread, float4 smem paths.
// HEAD=true writes C into [h][row][d] layout (h = col/64, d = col%64).
// ---------------------------------------------------------------------------
template<bool HEAD>
__global__ void __launch_bounds__(256)
gemm128(const float* __restrict__ A, const float* __restrict__ B,
        float* __restrict__ C, int M, int N, int K)
{
    __shared__ float As[16][132];   // stored transposed: As[k][m]
    __shared__ float Bs[16][132];   // Bs[k][n]

    const int tid = threadIdx.x;
    const int tx = tid & 15, ty = tid >> 4;
    const int row0 = blockIdx.y * 128, col0 = blockIdx.x * 128;

    float acc[8][8] = {};

    for (int k0 = 0; k0 < K; k0 += 16) {
        // A tile: 128 rows x 16 k (512 float4, 2 per thread), store transposed
        #pragma unroll
        for (int i = 0; i < 2; i++) {
            int lin = tid + i * 256;
            int r = lin >> 2, c4 = (lin & 3) * 4;
            float4 v = *reinterpret_cast<const float4*>(
                &A[(size_t)(row0 + r) * K + k0 + c4]);
            As[c4 + 0][r] = v.x; As[c4 + 1][r] = v.y;
            As[c4 + 2][r] = v.z; As[c4 + 3][r] = v.w;
        }
        // B tile: 16 rows x 128 cols (512 float4, 2 per thread)
        #pragma unroll
        for (int i = 0; i < 2; i++) {
            int lin = tid + i * 256;
            int r = lin >> 5, c4 = (lin & 31) * 4;
            *reinterpret_cast<float4*>(&Bs[r][c4]) =
                *reinterpret_cast<const float4*>(
                    &B[(size_t)(k0 + r) * N + col0 + c4]);
        }
        __syncthreads();

        #pragma unroll
        for (int kk = 0; kk < 16; kk++) {
            float a[8], b[8];
            *reinterpret_cast<float4*>(&a[0]) = *reinterpret_cast<float4*>(&As[kk][ty * 8]);
            *reinterpret_cast<float4*>(&a[4]) = *reinterpret_cast<float4*>(&As[kk][ty * 8 + 4]);
            *reinterpret_cast<float4*>(&b[0]) = *reinterpret_cast<float4*>(&Bs[kk][tx * 8]);
            *reinterpret_cast<float4*>(&b[4]) = *reinterpret_cast<float4*>(&Bs[kk][tx * 8 + 4]);
            #pragma unroll
            for (int i = 0; i < 8; i++)
                #pragma unroll
                for (int j = 0; j < 8; j++)
                    acc[i][j] += a[i] * b[j];
        }
        __syncthreads();
    }

    #pragma unroll
    for (int i = 0; i < 8; i++) {
        int r = row0 + ty * 8 + i;
        #pragma unroll
        for (int j = 0; j < 8; j++) {
            int c = col0 + tx * 8 + j;
            if (HEAD) {
                int h = c >> 6, d = c & 63;
                C[((size_t)h * M + r) * DK + d] = acc[i][j];
            } else {
                C[(size_t)r * N + c] = acc[i][j];
            }
        }
    }
}

// ---------------------------------------------------------------------------
// L2-normalize every 64-element row of g_Q and g_K: x /= (||x|| + eps).
// One warp per row; lane handles 2 contiguous floats.
// ---------------------------------------------------------------------------
__global__ void l2norm_qk()
{
    int gid  = blockIdx.x * blockDim.x + threadIdx.x;
    int warp = gid >> 5, lane = gid & 31;
    float* base = (warp < NH * S_LEN) ? g_Q : g_K;
    int r = warp & (NH * S_LEN - 1);

    float2 v = *reinterpret_cast<float2*>(&base[(size_t)r * DK + lane * 2]);
    float ss = v.x * v.x + v.y * v.y;
    #pragma unroll
    for (int m = 16; m; m >>= 1) ss += __shfl_xor_sync(0xffffffffu, ss, m);
    float inv = 1.0f / (sqrtf(ss) + EPSN);
    v.x *= inv; v.y *= inv;
    *reinterpret_cast<float2*>(&base[(size_t)r * DK + lane * 2]) = v;
}

// ---------------------------------------------------------------------------
// Fused attention, flash-style, per (q-block of 64, head).
// Logits = QK^T * SCALE + bias; bias ~ N(0,1) so |logit| <~ 7 — exp is safe
// in fp32 without max subtraction (mathematically identical softmax).
// Single pass over K tiles: accumulate exp(s)·V and the denominator.
// smem: Q tile (64x68), K tile reused as P tile (64x68), V tile (64x68),
//       denominator reduction buffer (64x16).
// ---------------------------------------------------------------------------
__global__ void __launch_bounds__(256)
attn_kernel(const float* __restrict__ bias)
{
    extern __shared__ float sm[];
    float* Qs  = sm;                 // 64 x 68
    float* Ps  = sm + 64 * 68;       // K tile, then overwritten with P
    float* Vs  = sm + 2 * 64 * 68;   // 64 x 68
    float* den = sm + 3 * 64 * 68;   // 64 x 16

    const int tid = threadIdx.x;
    const int tx = tid & 15, ty = tid >> 4;      // thread covers 4q x 4k (or 4d)
    const int h  = blockIdx.y;
    const int qb = blockIdx.x * 64;

    // Load Q tile once (persists across all K tiles)
    const float* Qp = g_Q + ((size_t)h * S_LEN + qb) * DK;
    #pragma unroll
    for (int i = 0; i < 4; i++) {
        int lin = tid + i * 256;
        int r = lin >> 4, c4 = (lin & 15) * 4;
        *reinterpret_cast<float4*>(&Qs[r * 68 + c4]) =
            *reinterpret_cast<const float4*>(&Qp[r * DK + c4]);
    }

    float o[4][4]  = {};
    float dsum[4]  = {};

    for (int kb = 0; kb < S_LEN; kb += 64) {
        const float* Kp = g_K + ((size_t)h * S_LEN + kb) * DK;
        const float* Vp = g_V + ((size_t)h * S_LEN + kb) * DK;
        #pragma unroll
        for (int i = 0; i < 4; i++) {
            int lin = tid + i * 256;
            int r = lin >> 4, c4 = (lin & 15) * 4;
            *reinterpret_cast<float4*>(&Ps[r * 68 + c4]) =
                *reinterpret_cast<const float4*>(&Kp[r * DK + c4]);
            *reinterpret_cast<float4*>(&Vs[r * 68 + c4]) =
                *reinterpret_cast<const float4*>(&Vp[r * DK + c4]);
        }
        __syncthreads();

        // scores s[4q][4k] = sum_d Q[q][d] * K[k][d]
        float s[4][4] = {};
        #pragma unroll 4
        for (int d = 0; d < 64; d += 4) {
            float4 qa[4], ka[4];
            #pragma unroll
            for (int i = 0; i < 4; i++)
                qa[i] = *reinterpret_cast<float4*>(&Qs[(ty * 4 + i) * 68 + d]);
            #pragma unroll
            for (int j = 0; j < 4; j++)
                ka[j] = *reinterpret_cast<float4*>(&Ps[(tx * 4 + j) * 68 + d]);
            #pragma unroll
            for (int i = 0; i < 4; i++)
                #pragma unroll
                for (int j = 0; j < 4; j++)
                    s[i][j] += qa[i].x * ka[j].x + qa[i].y * ka[j].y
                             + qa[i].z * ka[j].z + qa[i].w * ka[j].w;
        }
        __syncthreads();   // everyone done reading K tile before it becomes P

        // p = exp(s*SCALE + bias); accumulate denominators; store P tile
        #pragma unroll
        for (int i = 0; i < 4; i++) {
            float4 bv = *reinterpret_cast<const float4*>(
                &bias[((size_t)h * S_LEN + qb + ty * 4 + i) * S_LEN + kb + tx * 4]);
            float p0 = expf(s[i][0] * SCALE + bv.x);
            float p1 = expf(s[i][1] * SCALE + bv.y);
            float p2 = expf(s[i][2] * SCALE + bv.z);
            float p3 = expf(s[i][3] * SCALE + bv.w);
            dsum[i] += p0 + p1 + p2 + p3;
            *reinterpret_cast<float4*>(&Ps[(ty * 4 + i) * 68 + tx * 4]) =
                make_float4(p0, p1, p2, p3);
        }
        __syncthreads();

        // O[4q][4d] += P[q][kk] * V[kk][d]
        #pragma unroll 8
        for (int kk = 0; kk < 64; kk++) {
            float4 vv = *reinterpret_cast<float4*>(&Vs[kk * 68 + tx * 4]);
            #pragma unroll
            for (int i = 0; i < 4; i++) {
                float pv = Ps[(ty * 4 + i) * 68 + kk];   // broadcast read
                o[i][0] += pv * vv.x; o[i][1] += pv * vv.y;
                o[i][2] += pv * vv.z; o[i][3] += pv * vv.w;
            }
        }
        __syncthreads();   // before next tile's K/V overwrite
    }

    // Reduce denominators across the 16 tx threads sharing each q row
    #pragma unroll
    for (int i = 0; i < 4; i++) den[(ty * 4 + i) * 16 + tx] = dsum[i];
    __syncthreads();

    #pragma unroll
    for (int i = 0; i < 4; i++) {
        float tot = 0.f;
        #pragma unroll
        for (int t = 0; t < 16; t++) tot += den[(ty * 4 + i) * 16 + t];
        float inv = 1.0f / tot;
        float4 ov = make_float4(o[i][0] * inv, o[i][1] * inv,
                                o[i][2] * inv, o[i][3] * inv);
        *reinterpret_cast<float4*>(
            &g_att[(size_t)(qb + ty * 4 + i) * DM + h * DK + tx * 4]) = ov;
    }
}

// ---------------------------------------------------------------------------
// Launcher
// inputs: 0=Q_input 1=K_input 2=V_input 3=bias 4=W_q 5=W_k 6=W_v 7=W_o
// ---------------------------------------------------------------------------
extern "C" void kernel_launch(void* const* d_in, const int* in_sizes, int n_in,
                              void* d_out, int out_size)
{
    (void)in_sizes; (void)n_in; (void)out_size;
    const float* Qin  = (const float*)d_in[0];
    const float* Kin  = (const float*)d_in[1];
    const float* Vin  = (const float*)d_in[2];
    const float* bias = (const float*)d_in[3];
    const float* Wq   = (const float*)d_in[4];
    const float* Wk   = (const float*)d_in[5];
    const float* Wv   = (const float*)d_in[6];
    const float* Wo   = (const float*)d_in[7];
    float* out = (float*)d_out;

    float *pQ, *pK, *pV, *pA;
    cudaGetSymbolAddress((void**)&pQ, g_Q);
    cudaGetSymbolAddress((void**)&pK, g_K);
    cudaGetSymbolAddress((void**)&pV, g_V);
    cudaGetSymbolAddress((void**)&pA, g_att);

    dim3 gp(DM / 128, S_LEN / 128);   // (8, 16)

    gemm128<true ><<<gp, 256>>>(Qin, Wq, pQ, S_LEN, DM, DM);
    gemm128<true ><<<gp, 256>>>(Kin, Wk, pK, S_LEN, DM, DM);
    gemm128<true ><<<gp, 256>>>(Vin, Wv, pV, S_LEN, DM, DM);

    l2norm_qk<<<(2 * NH * S_LEN * 32) / 256, 256>>>();

    const int smem_bytes = (3 * 64 * 68 + 64 * 16) * (int)sizeof(float); // 56320
    cudaFuncSetAttribute(attn_kernel,
                         cudaFuncAttributeMaxDynamicSharedMemorySize, smem_bytes);
    attn_kernel<<<dim3(S_LEN / 64, NH), 256, smem_bytes>>>(bias);

    gemm128<false><<<gp, 256>>>(pA, Wo, out, S_LEN, DM, DM);
}

// round 3
// speedup vs baseline: 5.2722x; 5.2722x over previous
#include <cuda_runtime.h>
#include <cuda_bf16.h>
#include <math.h>
#include <stdint.h>

#define S_LEN 2048
#define DM    1024
#define NH    16
#define DK    64
#define SCALE 0.125f
#define EPSN  1e-6f

typedef __nv_bfloat16 bf16;

// ---------------- scratch (__device__ globals; allocation-free) ----------------
__device__ float g_Q[(size_t)NH * S_LEN * DK];     // fp32 proj outputs, [h][s][64]
__device__ float g_K[(size_t)NH * S_LEN * DK];
__device__ float g_V[(size_t)NH * S_LEN * DK];

__device__ bf16 b_Qin[(size_t)S_LEN * DM];         // bf16 copies of inputs
__device__ bf16 b_Kin[(size_t)S_LEN * DM];
__device__ bf16 b_Vin_h[(size_t)S_LEN * DM];       // split V input
__device__ bf16 b_Vin_l[(size_t)S_LEN * DM];
__device__ bf16 b_Wq[(size_t)DM * DM];
__device__ bf16 b_Wk[(size_t)DM * DM];
__device__ bf16 b_Wv_h[(size_t)DM * DM];           // split W_v
__device__ bf16 b_Wv_l[(size_t)DM * DM];
__device__ bf16 b_Wo_h[(size_t)DM * DM];           // split W_o
__device__ bf16 b_Wo_l[(size_t)DM * DM];

__device__ bf16 b_Qn[(size_t)NH * S_LEN * DK];     // normalized Q/K, bf16, [h][s][64]
__device__ bf16 b_Kn[(size_t)NH * S_LEN * DK];
__device__ bf16 b_Vt_h[(size_t)NH * DK * S_LEN];   // V transposed + split, [h][64][2048]
__device__ bf16 b_Vt_l[(size_t)NH * DK * S_LEN];

__device__ bf16 b_att_h[(size_t)S_LEN * DM];       // attended, split hi/lo [s][1024]
__device__ bf16 b_att_l[(size_t)S_LEN * DM];

// ---------------- mma / ldmatrix helpers ----------------
__device__ __forceinline__ uint32_t cvta_s(const void* p) {
    return (uint32_t)__cvta_generic_to_shared(p);
}
__device__ __forceinline__ void ldm4(uint32_t& r0, uint32_t& r1, uint32_t& r2, uint32_t& r3,
                                     uint32_t a) {
    asm volatile("ldmatrix.sync.aligned.m8n8.x4.shared.b16 {%0,%1,%2,%3},[%4];"
                 : "=r"(r0), "=r"(r1), "=r"(r2), "=r"(r3) : "r"(a));
}
__device__ __forceinline__ void ldm4t(uint32_t& r0, uint32_t& r1, uint32_t& r2, uint32_t& r3,
                                      uint32_t a) {
    asm volatile("ldmatrix.sync.aligned.m8n8.x4.trans.shared.b16 {%0,%1,%2,%3},[%4];"
                 : "=r"(r0), "=r"(r1), "=r"(r2), "=r"(r3) : "r"(a));
}
__device__ __forceinline__ void mma_bf(float c[4], const uint32_t a[4],
                                       uint32_t b0, uint32_t b1) {
    asm volatile(
        "mma.sync.aligned.m16n8k16.row.col.f32.bf16.bf16.f32 "
        "{%0,%1,%2,%3},{%4,%5,%6,%7},{%8,%9},{%0,%1,%2,%3};"
        : "+f"(c[0]), "+f"(c[1]), "+f"(c[2]), "+f"(c[3])
        : "r"(a[0]), "r"(a[1]), "r"(a[2]), "r"(a[3]), "r"(b0), "r"(b1));
}
// pack two fp32 -> bf16x2 reg; first arg goes in low 16 bits
__device__ __forceinline__ uint32_t packbf(float lo, float hi) {
    uint32_t r;
    asm("cvt.rn.bf16x2.f32 %0,%1,%2;" : "=r"(r) : "f"(hi), "f"(lo));
    return r;
}
__device__ __forceinline__ float rbf(float x) {           // round-to-bf16
    return __bfloat162float(__float2bfloat16(x));
}

// ---------------- elementwise conversions ----------------
__global__ void cvt_bf16_k(const float4* __restrict__ x, uint32_t* __restrict__ y, int n4) {
    int i = blockIdx.x * 256 + threadIdx.x;
    if (i >= n4) return;
    float4 v = x[i];
    y[2 * i + 0] = packbf(v.x, v.y);
    y[2 * i + 1] = packbf(v.z, v.w);
}
__global__ void split_bf16_k(const float4* __restrict__ x, uint32_t* __restrict__ hi,
                             uint32_t* __restrict__ lo, int n4) {
    int i = blockIdx.x * 256 + threadIdx.x;
    if (i >= n4) return;
    float4 v = x[i];
    float hx = rbf(v.x), hy = rbf(v.y), hz = rbf(v.z), hw = rbf(v.w);
    hi[2 * i + 0] = packbf(hx, hy);
    hi[2 * i + 1] = packbf(hz, hw);
    lo[2 * i + 0] = packbf(v.x - hx, v.y - hy);
    lo[2 * i + 1] = packbf(v.z - hz, v.w - hw);
}

// ---------------- GEMM via mma.sync: C[M,N] = A[M,K] @ B[K,N] ----------------
// 128x128 block tile, BK=32, 256 threads (8 warps, 2x4 -> warp tile 64x32).
// NTERM==3: split operands: Ah*Bh + Ah*Bl + Al*Bh.
// HEAD: scatter C columns into [h][row][d] layout.
template<int NTERM, bool HEAD>
__global__ void __launch_bounds__(256)
mma_gemm(const bf16* __restrict__ Ah, const bf16* __restrict__ Al,
         const bf16* __restrict__ Bh, const bf16* __restrict__ Bl,
         float* __restrict__ C, int M, int N, int K)
{
    extern __shared__ bf16 sm_[];
    bf16* sAh = sm_;                    // 128 x 40
    bf16* sBh = sAh + 128 * 40;         // 32 x 136
    bf16* sAl = sBh + 32 * 136;         // (NTERM==3)
    bf16* sBl = sAl + 128 * 40;

    const int tid = threadIdx.x;
    const int w = tid >> 5, l = tid & 31;
    const int wm = (w >> 2) * 64, wn = (w & 3) * 32;
    const int row0 = blockIdx.y * 128, col0 = blockIdx.x * 128;

    float acc[4][4][4];
    #pragma unroll
    for (int a = 0; a < 4; a++)
        #pragma unroll
        for (int b = 0; b < 4; b++)
            #pragma unroll
            for (int c = 0; c < 4; c++) acc[a][b][c] = 0.f;

    for (int k0 = 0; k0 < K; k0 += 32) {
        #pragma unroll
        for (int i = 0; i < 2; i++) {
            int pos = tid + i * 256;
            int r = pos >> 2, c = (pos & 3) * 8;
            *(uint4*)(sAh + r * 40 + c) =
                *(const uint4*)(Ah + (size_t)(row0 + r) * K + k0 + c);
            if (NTERM == 3)
                *(uint4*)(sAl + r * 40 + c) =
                    *(const uint4*)(Al + (size_t)(row0 + r) * K + k0 + c);
        }
        #pragma unroll
        for (int i = 0; i < 2; i++) {
            int pos = tid + i * 256;
            int r = pos >> 4, c = (pos & 15) * 8;
            *(uint4*)(sBh + r * 136 + c) =
                *(const uint4*)(Bh + (size_t)(k0 + r) * N + col0 + c);
            if (NTERM == 3)
                *(uint4*)(sBl + r * 136 + c) =
                    *(const uint4*)(Bl + (size_t)(k0 + r) * N + col0 + c);
        }
        __syncthreads();

        #pragma unroll
        for (int kc = 0; kc < 2; kc++) {
            uint32_t af[4][4], bfh[2][4];
            #pragma unroll
            for (int mt = 0; mt < 4; mt++)
                ldm4(af[mt][0], af[mt][1], af[mt][2], af[mt][3],
                     cvta_s(sAh + (wm + mt * 16 + (l & 15)) * 40 + kc * 16 + ((l >> 4) * 8)));
            #pragma unroll
            for (int np = 0; np < 2; np++)
                ldm4t(bfh[np][0], bfh[np][1], bfh[np][2], bfh[np][3],
                      cvta_s(sBh + (kc * 16 + (l & 15)) * 136 + wn + np * 16 + ((l >> 4) * 8)));
            #pragma unroll
            for (int mt = 0; mt < 4; mt++)
                #pragma unroll
                for (int nt = 0; nt < 4; nt++)
                    mma_bf(acc[mt][nt], af[mt],
                           bfh[nt >> 1][(nt & 1) * 2], bfh[nt >> 1][(nt & 1) * 2 + 1]);

            if (NTERM == 3) {
                uint32_t bfl[2][4];
                #pragma unroll
                for (int np = 0; np < 2; np++)
                    ldm4t(bfl[np][0], bfl[np][1], bfl[np][2], bfl[np][3],
                          cvta_s(sBl + (kc * 16 + (l & 15)) * 136 + wn + np * 16 + ((l >> 4) * 8)));
                #pragma unroll
                for (int mt = 0; mt < 4; mt++)
                    #pragma unroll
                    for (int nt = 0; nt < 4; nt++)
                        mma_bf(acc[mt][nt], af[mt],
                               bfl[nt >> 1][(nt & 1) * 2], bfl[nt >> 1][(nt & 1) * 2 + 1]);
                uint32_t afl[4][4];
                #pragma unroll
                for (int mt = 0; mt < 4; mt++)
                    ldm4(afl[mt][0], afl[mt][1], afl[mt][2], afl[mt][3],
                         cvta_s(sAl + (wm + mt * 16 + (l & 15)) * 40 + kc * 16 + ((l >> 4) * 8)));
                #pragma unroll
                for (int mt = 0; mt < 4; mt++)
                    #pragma unroll
                    for (int nt = 0; nt < 4; nt++)
                        mma_bf(acc[mt][nt], afl[mt],
                               bfh[nt >> 1][(nt & 1) * 2], bfh[nt >> 1][(nt & 1) * 2 + 1]);
            }
        }
        __syncthreads();
    }

    #pragma unroll
    for (int mt = 0; mt < 4; mt++) {
        int r = row0 + wm + mt * 16 + (l >> 2);
        #pragma unroll
        for (int nt = 0; nt < 4; nt++) {
            int c = col0 + wn + nt * 8 + (l & 3) * 2;
            if (HEAD) {
                int h = c >> 6, d = c & 63;
                *(float2*)&C[((size_t)h * M + r) * DK + d] =
                    make_float2(acc[mt][nt][0], acc[mt][nt][1]);
                *(float2*)&C[((size_t)h * M + r + 8) * DK + d] =
                    make_float2(acc[mt][nt][2], acc[mt][nt][3]);
            } else {
                *(float2*)&C[(size_t)r * N + c] =
                    make_float2(acc[mt][nt][0], acc[mt][nt][1]);
                *(float2*)&C[(size_t)(r + 8) * N + c] =
                    make_float2(acc[mt][nt][2], acc[mt][nt][3]);
            }
        }
    }
}

// ---------------- L2-normalize rows of g_Q/g_K -> bf16 b_Qn/b_Kn ----------------
__global__ void l2norm_emit()
{
    int gid  = blockIdx.x * 256 + threadIdx.x;
    int warp = gid >> 5, l = gid & 31;
    const float* src;
    bf16* dst;
    int r = warp & (NH * S_LEN - 1);
    if (warp < NH * S_LEN) { src = g_Q; dst = b_Qn; }
    else                   { src = g_K; dst = b_Kn; }

    float2 v = *(const float2*)&src[(size_t)r * DK + l * 2];
    float ss = v.x * v.x + v.y * v.y;
    #pragma unroll
    for (int m = 16; m; m >>= 1) ss += __shfl_xor_sync(0xffffffffu, ss, m);
    float inv = 1.0f / (sqrtf(ss) + EPSN);
    ((uint32_t*)dst)[(size_t)r * 32 + l] = packbf(v.x * inv, v.y * inv);
}

// --------- V transpose + split: g_V [h][s][64] -> b_Vt_{h,l} [h][64][2048] ---------
__global__ void __launch_bounds__(256) transV()
{
    __shared__ float t[64][65];
    int h = blockIdx.y, s0 = blockIdx.x * 64;
    int tid = threadIdx.x;
    #pragma unroll
    for (int i = 0; i < 16; i++) {
        int pos = tid + i * 256;
        int r = pos >> 6, d = pos & 63;
        t[r][d] = g_V[((size_t)h * S_LEN + s0 + r) * DK + d];
    }
    __syncthreads();
    #pragma unroll
    for (int i = 0; i < 8; i++) {
        int pos = tid + i * 256;
        int d = pos >> 5, jp = pos & 31;
        float a = t[jp * 2][d], b = t[jp * 2 + 1][d];
        float ha = rbf(a), hb = rbf(b);
        size_t idx = ((size_t)h * DK + d) * (S_LEN / 2) + (s0 >> 1) + jp;
        ((uint32_t*)b_Vt_h)[idx] = packbf(ha, hb);
        ((uint32_t*)b_Vt_l)[idx] = packbf(a - ha, b - hb);
    }
}

// ---------------- fused attention with mma.sync, split-precision PV ----------------
// Block = (q-block of 128, head). 8 warps, warp w owns q rows [w*16, w*16+16).
// Per k-tile of 128: S = Q@K^T (bf16 mma), p = exp(S*SCALE + bias),
// O += Ph@Vh + Pl@Vh + Ph@Vl (split bf16, V pre-transposed+split).
__global__ void __launch_bounds__(256) attn_mma(const float* __restrict__ bias)
{
    extern __shared__ bf16 sm_[];
    bf16* sK  = sm_;                    // 128 x 72  (also stages Q)
    bf16* sVh = sm_ + 128 * 72;         // 64 x 136  (V^T hi)
    bf16* sVl = sVh + 64 * 136;         // 64 x 136  (V^T lo)

    const int tid = threadIdx.x, w = tid >> 5, l = tid & 31;
    const int h = blockIdx.y, qb = blockIdx.x * 128;

    // stage Q tile, load Q fragments (persist in regs)
    #pragma unroll
    for (int i = 0; i < 4; i++) {
        int pos = tid + i * 256;
        int r = pos >> 3, c = (pos & 7) * 8;
        *(uint4*)(sK + r * 72 + c) =
            *(const uint4*)(b_Qn + ((size_t)h * S_LEN + qb + r) * DK + c);
    }
    __syncthreads();
    uint32_t qf[4][4];
    #pragma unroll
    for (int dc = 0; dc < 4; dc++)
        ldm4(qf[dc][0], qf[dc][1], qf[dc][2], qf[dc][3],
             cvta_s(sK + (w * 16 + (l & 15)) * 72 + dc * 16 + ((l >> 4) * 8)));
    __syncthreads();

    float oacc[8][4];
    #pragma unroll
    for (int a = 0; a < 8; a++)
        #pragma unroll
        for (int b = 0; b < 4; b++) oacc[a][b] = 0.f;
    float rs_lo = 0.f, rs_hi = 0.f;

    const float* bp = bias + ((size_t)h * S_LEN + qb + w * 16 + (l >> 2)) * S_LEN + (l & 3) * 2;

    for (int kb = 0; kb < S_LEN; kb += 128) {
        #pragma unroll
        for (int i = 0; i < 4; i++) {
            int pos = tid + i * 256;
            {   int r = pos >> 3, c = (pos & 7) * 8;
                *(uint4*)(sK + r * 72 + c) =
                    *(const uint4*)(b_Kn + ((size_t)h * S_LEN + kb + r) * DK + c); }
            {   int r = pos >> 4, c = (pos & 15) * 8;
                size_t g = ((size_t)h * DK + r) * S_LEN + kb + c;
                *(uint4*)(sVh + r * 136 + c) = *(const uint4*)(b_Vt_h + g);
                *(uint4*)(sVl + r * 136 + c) = *(const uint4*)(b_Vt_l + g); }
        }
        __syncthreads();

        // S = Q @ K^T : 16 n8 tiles over this 128-wide k tile
        float s[16][4];
        #pragma unroll
        for (int a = 0; a < 16; a++)
            #pragma unroll
            for (int b = 0; b < 4; b++) s[a][b] = 0.f;
        #pragma unroll
        for (int dc = 0; dc < 4; dc++) {
            #pragma unroll
            for (int np = 0; np < 8; np++) {
                uint32_t r0, r1, r2, r3;
                ldm4(r0, r1, r2, r3,
                     cvta_s(sK + (np * 16 + (l & 15)) * 72 + dc * 16 + ((l >> 4) * 8)));
                mma_bf(s[2 * np],     qf[dc], r0, r2);
                mma_bf(s[2 * np + 1], qf[dc], r1, r3);
            }
        }

        // logits -> p = exp(s*SCALE + bias); accumulate row sums
        #pragma unroll
        for (int nt = 0; nt < 16; nt++) {
            float2 b0 = *(const float2*)(bp + kb + nt * 8);
            float2 b1 = *(const float2*)(bp + kb + nt * 8 + 8 * S_LEN);
            float p0 = __expf(fmaf(s[nt][0], SCALE, b0.x));
            float p1 = __expf(fmaf(s[nt][1], SCALE, b0.y));
            float p2 = __expf(fmaf(s[nt][2], SCALE, b1.x));
            float p3 = __expf(fmaf(s[nt][3], SCALE, b1.y));
            rs_lo += p0 + p1;  rs_hi += p2 + p3;
            s[nt][0] = p0; s[nt][1] = p1; s[nt][2] = p2; s[nt][3] = p3;
        }

        // O += Ph@Vh + Pl@Vh + Ph@Vl  (split P in regs, split V in smem)
        #pragma unroll
        for (int kt = 0; kt < 8; kt++) {
            float x0 = s[2 * kt][0],     x1 = s[2 * kt][1];
            float x2 = s[2 * kt][2],     x3 = s[2 * kt][3];
            float y0 = s[2 * kt + 1][0], y1 = s[2 * kt + 1][1];
            float y2 = s[2 * kt + 1][2], y3 = s[2 * kt + 1][3];
            float hx0 = rbf(x0), hx1 = rbf(x1), hx2 = rbf(x2), hx3 = rbf(x3);
            float hy0 = rbf(y0), hy1 = rbf(y1), hy2 = rbf(y2), hy3 = rbf(y3);
            uint32_t ah[4], al[4];
            ah[0] = packbf(hx0, hx1);           ah[1] = packbf(hx2, hx3);
            ah[2] = packbf(hy0, hy1);           ah[3] = packbf(hy2, hy3);
            al[0] = packbf(x0 - hx0, x1 - hx1); al[1] = packbf(x2 - hx2, x3 - hx3);
            al[2] = packbf(y0 - hy0, y1 - hy1); al[3] = packbf(y2 - hy2, y3 - hy3);
            #pragma unroll
            for (int dp = 0; dp < 4; dp++) {
                uint32_t v0, v1, v2, v3, u0, u1, u2, u3;
                ldm4(v0, v1, v2, v3,
                     cvta_s(sVh + (dp * 16 + (l & 15)) * 136 + kt * 16 + ((l >> 4) * 8)));
                ldm4(u0, u1, u2, u3,
                     cvta_s(sVl + (dp * 16 + (l & 15)) * 136 + kt * 16 + ((l >> 4) * 8)));
                mma_bf(oacc[2 * dp],     ah, v0, v2);
                mma_bf(oacc[2 * dp + 1], ah, v1, v3);
                mma_bf(oacc[2 * dp],     al, v0, v2);
                mma_bf(oacc[2 * dp + 1], al, v1, v3);
                mma_bf(oacc[2 * dp],     ah, u0, u2);
                mma_bf(oacc[2 * dp + 1], ah, u1, u3);
            }
        }
        __syncthreads();
    }

    // finalize: rowsum reduce within quad, normalize, write split bf16
    rs_lo += __shfl_xor_sync(0xffffffffu, rs_lo, 1);
    rs_lo += __shfl_xor_sync(0xffffffffu, rs_lo, 2);
    rs_hi += __shfl_xor_sync(0xffffffffu, rs_hi, 1);
    rs_hi += __shfl_xor_sync(0xffffffffu, rs_hi, 2);
    float il = 1.0f / rs_lo, ih = 1.0f / rs_hi;

    #pragma unroll
    for (int nt = 0; nt < 8; nt++) {
        int r = qb + w * 16 + (l >> 2);
        int c = h * DK + nt * 8 + (l & 3) * 2;
        float x0 = oacc[nt][0] * il, x1 = oacc[nt][1] * il;
        float x2 = oacc[nt][2] * ih, x3 = oacc[nt][3] * ih;
        float h0 = rbf(x0), h1 = rbf(x1), h2 = rbf(x2), h3 = rbf(x3);
        size_t i0 = ((size_t)r * DM + c) >> 1;
        size_t i1 = ((size_t)(r + 8) * DM + c) >> 1;
        ((uint32_t*)b_att_h)[i0] = packbf(h0, h1);
        ((uint32_t*)b_att_l)[i0] = packbf(x0 - h0, x1 - h1);
        ((uint32_t*)b_att_h)[i1] = packbf(h2, h3);
        ((uint32_t*)b_att_l)[i1] = packbf(x2 - h2, x3 - h3);
    }
}

// ---------------- launcher ----------------
extern "C" void kernel_launch(void* const* d_in, const int* in_sizes, int n_in,
                              void* d_out, int out_size)
{
    (void)in_sizes; (void)n_in; (void)out_size;
    const float* Qin  = (const float*)d_in[0];
    const float* Kin  = (const float*)d_in[1];
    const float* Vin  = (const float*)d_in[2];
    const float* bias = (const float*)d_in[3];
    const float* Wq   = (const float*)d_in[4];
    const float* Wk   = (const float*)d_in[5];
    const float* Wv   = (const float*)d_in[6];
    const float* Wo   = (const float*)d_in[7];
    float* out = (float*)d_out;

    float *pQ, *pK, *pV;
    bf16 *pbQin, *pbKin, *pbVinH, *pbVinL, *pbWq, *pbWk, *pbWvH, *pbWvL,
         *pbWoH, *pbWoL, *pAttH, *pAttL;
    cudaGetSymbolAddress((void**)&pQ, g_Q);
    cudaGetSymbolAddress((void**)&pK, g_K);
    cudaGetSymbolAddress((void**)&pV, g_V);
    cudaGetSymbolAddress((void**)&pbQin, b_Qin);
    cudaGetSymbolAddress((void**)&pbKin, b_Kin);
    cudaGetSymbolAddress((void**)&pbVinH, b_Vin_h);
    cudaGetSymbolAddress((void**)&pbVinL, b_Vin_l);
    cudaGetSymbolAddress((void**)&pbWq, b_Wq);
    cudaGetSymbolAddress((void**)&pbWk, b_Wk);
    cudaGetSymbolAddress((void**)&pbWvH, b_Wv_h);
    cudaGetSymbolAddress((void**)&pbWvL, b_Wv_l);
    cudaGetSymbolAddress((void**)&pbWoH, b_Wo_h);
    cudaGetSymbolAddress((void**)&pbWoL, b_Wo_l);
    cudaGetSymbolAddress((void**)&pAttH, b_att_h);
    cudaGetSymbolAddress((void**)&pAttL, b_att_l);

    const int n4_in = S_LEN * DM / 4;   // 524288
    const int n4_w  = DM * DM / 4;      // 262144

    cvt_bf16_k<<<n4_in / 256, 256>>>((const float4*)Qin, (uint32_t*)pbQin, n4_in);
    cvt_bf16_k<<<n4_in / 256, 256>>>((const float4*)Kin, (uint32_t*)pbKin, n4_in);
    split_bf16_k<<<n4_in / 256, 256>>>((const float4*)Vin, (uint32_t*)pbVinH,
                                       (uint32_t*)pbVinL, n4_in);
    cvt_bf16_k<<<n4_w / 256, 256>>>((const float4*)Wq, (uint32_t*)pbWq, n4_w);
    cvt_bf16_k<<<n4_w / 256, 256>>>((const float4*)Wk, (uint32_t*)pbWk, n4_w);
    split_bf16_k<<<n4_w / 256, 256>>>((const float4*)Wv, (uint32_t*)pbWvH,
                                      (uint32_t*)pbWvL, n4_w);
    split_bf16_k<<<n4_w / 256, 256>>>((const float4*)Wo, (uint32_t*)pbWoH,
                                      (uint32_t*)pbWoL, n4_w);

    const int smem1 = (128 * 40 + 32 * 136) * 2;          // 18944 B
    const int smem3 = 2 * (128 * 40 + 32 * 136) * 2;      // 37888 B
    dim3 gp(DM / 128, S_LEN / 128);                        // (8, 16)

    mma_gemm<1, true ><<<gp, 256, smem1>>>(pbQin, nullptr, pbWq, nullptr, pQ, S_LEN, DM, DM);
    mma_gemm<1, true ><<<gp, 256, smem1>>>(pbKin, nullptr, pbWk, nullptr, pK, S_LEN, DM, DM);
    mma_gemm<3, true ><<<gp, 256, smem3>>>(pbVinH, pbVinL, pbWvH, pbWvL, pV, S_LEN, DM, DM);

    l2norm_emit<<<(2 * NH * S_LEN * 32) / 256, 256>>>();
    transV<<<dim3(S_LEN / 64, NH), 256>>>();

    const int smemA = (128 * 72 + 2 * 64 * 136) * 2;       // 53248 B
    cudaFuncSetAttribute(attn_mma,
                         cudaFuncAttributeMaxDynamicSharedMemorySize, smemA);
    attn_mma<<<dim3(S_LEN / 128, NH), 256, smemA>>>(bias);

    mma_gemm<3, false><<<gp, 256, smem3>>>(pAttH, pAttL, pbWoH, pbWoL, out, S_LEN, DM, DM);
}

// round 4
// speedup vs baseline: 6.2899x; 1.1930x over previous
#include <cuda_runtime.h>
#include <cuda_bf16.h>
#include <math.h>
#include <stdint.h>

#define S_LEN 2048
#define DM    1024
#define NH    16
#define DK    64
#define SCALE 0.125f
#define EPSN  1e-6f

typedef __nv_bfloat16 bf16;

// ---------------- scratch (__device__ globals; allocation-free) ----------------
__device__ float g_Q[(size_t)NH * S_LEN * DK];
__device__ float g_K[(size_t)NH * S_LEN * DK];
__device__ float g_V[(size_t)NH * S_LEN * DK];

__device__ bf16 b_Qin[(size_t)S_LEN * DM];
__device__ bf16 b_Kin[(size_t)S_LEN * DM];
__device__ bf16 b_Vin_h[(size_t)S_LEN * DM];
__device__ bf16 b_Vin_l[(size_t)S_LEN * DM];
__device__ bf16 b_Wq[(size_t)DM * DM];
__device__ bf16 b_Wk[(size_t)DM * DM];
__device__ bf16 b_Wv_h[(size_t)DM * DM];
__device__ bf16 b_Wv_l[(size_t)DM * DM];
__device__ bf16 b_Wo_h[(size_t)DM * DM];
__device__ bf16 b_Wo_l[(size_t)DM * DM];

__device__ bf16 b_Qn[(size_t)NH * S_LEN * DK];
__device__ bf16 b_Kn[(size_t)NH * S_LEN * DK];
__device__ bf16 b_Vt_h[(size_t)NH * DK * S_LEN];
__device__ bf16 b_Vt_l[(size_t)NH * DK * S_LEN];

__device__ bf16 b_att_h[(size_t)S_LEN * DM];
__device__ bf16 b_att_l[(size_t)S_LEN * DM];

// ---------------- helpers ----------------
__device__ __forceinline__ uint32_t cvta_s(const void* p) {
    return (uint32_t)__cvta_generic_to_shared(p);
}
__device__ __forceinline__ void cp16(void* s, const void* g) {
    asm volatile("cp.async.cg.shared.global [%0],[%1],16;" ::
                 "r"(cvta_s(s)), "l"(g));
}
__device__ __forceinline__ void cp_commit() {
    asm volatile("cp.async.commit_group;");
}
template<int N>
__device__ __forceinline__ void cp_wait() {
    asm volatile("cp.async.wait_group %0;" :: "n"(N));
}
__device__ __forceinline__ void ldm4(uint32_t& r0, uint32_t& r1, uint32_t& r2, uint32_t& r3,
                                     uint32_t a) {
    asm volatile("ldmatrix.sync.aligned.m8n8.x4.shared.b16 {%0,%1,%2,%3},[%4];"
                 : "=r"(r0), "=r"(r1), "=r"(r2), "=r"(r3) : "r"(a));
}
__device__ __forceinline__ void ldm4t(uint32_t& r0, uint32_t& r1, uint32_t& r2, uint32_t& r3,
                                      uint32_t a) {
    asm volatile("ldmatrix.sync.aligned.m8n8.x4.trans.shared.b16 {%0,%1,%2,%3},[%4];"
                 : "=r"(r0), "=r"(r1), "=r"(r2), "=r"(r3) : "r"(a));
}
__device__ __forceinline__ void mma_bf(float c[4], const uint32_t a[4],
                                       uint32_t b0, uint32_t b1) {
    asm volatile(
        "mma.sync.aligned.m16n8k16.row.col.f32.bf16.bf16.f32 "
        "{%0,%1,%2,%3},{%4,%5,%6,%7},{%8,%9},{%0,%1,%2,%3};"
        : "+f"(c[0]), "+f"(c[1]), "+f"(c[2]), "+f"(c[3])
        : "r"(a[0]), "r"(a[1]), "r"(a[2]), "r"(a[3]), "r"(b0), "r"(b1));
}
// pack two fp32 -> bf16x2; first arg in low 16 bits
__device__ __forceinline__ uint32_t packbf(float lo, float hi) {
    uint32_t r;
    asm("cvt.rn.bf16x2.f32 %0,%1,%2;" : "=r"(r) : "f"(hi), "f"(lo));
    return r;
}
__device__ __forceinline__ float rbf(float x) {
    return __bfloat162float(__float2bfloat16(x));
}

// ---------------- fused conversions (one launch) ----------------
__device__ __forceinline__ void cvt1(const float4* x, uint32_t* y, int i) {
    float4 v = x[i];
    y[2 * i + 0] = packbf(v.x, v.y);
    y[2 * i + 1] = packbf(v.z, v.w);
}
__device__ __forceinline__ void split1(const float4* x, uint32_t* hi, uint32_t* lo, int i) {
    float4 v = x[i];
    float hx = rbf(v.x), hy = rbf(v.y), hz = rbf(v.z), hw = rbf(v.w);
    hi[2 * i + 0] = packbf(hx, hy);
    hi[2 * i + 1] = packbf(hz, hw);
    lo[2 * i + 0] = packbf(v.x - hx, v.y - hy);
    lo[2 * i + 1] = packbf(v.z - hz, v.w - hw);
}
__global__ void prep_all(const float4* Qin, const float4* Kin, const float4* Vin,
                         const float4* Wq, const float4* Wk, const float4* Wv,
                         const float4* Wo)
{
    const int NI = S_LEN * DM / 4;  // 524288
    const int NW = DM * DM / 4;     // 262144
    int i = blockIdx.x * 256 + threadIdx.x;
    if (i < NI) { cvt1(Qin, (uint32_t*)b_Qin, i); return; }
    i -= NI;
    if (i < NI) { cvt1(Kin, (uint32_t*)b_Kin, i); return; }
    i -= NI;
    if (i < NI) { split1(Vin, (uint32_t*)b_Vin_h, (uint32_t*)b_Vin_l, i); return; }
    i -= NI;
    if (i < NW) { cvt1(Wq, (uint32_t*)b_Wq, i); return; }
    i -= NW;
    if (i < NW) { cvt1(Wk, (uint32_t*)b_Wk, i); return; }
    i -= NW;
    if (i < NW) { split1(Wv, (uint32_t*)b_Wv_h, (uint32_t*)b_Wv_l, i); return; }
    i -= NW;
    split1(Wo, (uint32_t*)b_Wo_h, (uint32_t*)b_Wo_l, i);
}

// ---------------- GEMM via mma.sync, 2-stage cp.async pipeline ----------------
// C[M,N] = A @ B. 128x128 tile, BK=32, 256 threads, warp tile 64x32.
// NTERM==3: Ah*Bh + Ah*Bl + Al*Bh.  HEAD: scatter to [h][row][d].
// gridDim.z==2 selects (A2,B2,C2) for z==1 (batched Q/K projections).
template<int NTERM, bool HEAD>
__global__ void __launch_bounds__(256)
mma_gemm(const bf16* __restrict__ Ah, const bf16* __restrict__ Al,
         const bf16* __restrict__ Bh, const bf16* __restrict__ Bl,
         float* __restrict__ C,
         const bf16* __restrict__ A2, const bf16* __restrict__ B2,
         float* __restrict__ C2, int M, int N, int K)
{
    extern __shared__ bf16 sm_[];
    const int SE = (128 * 40 + 32 * 136) * NTERM == 3 ? 0 : 0; // (unused trick guard)
    const int STG = (NTERM == 3) ? 2 * (128 * 40 + 32 * 136) : (128 * 40 + 32 * 136);
    (void)SE;

    const bf16* Ap = (blockIdx.z == 0) ? Ah : A2;
    const bf16* Bp = (blockIdx.z == 0) ? Bh : B2;
    float*      Cp = (blockIdx.z == 0) ? C  : C2;

    const int tid = threadIdx.x;
    const int w = tid >> 5, l = tid & 31;
    const int wm = (w >> 2) * 64, wn = (w & 3) * 32;
    const int row0 = blockIdx.y * 128, col0 = blockIdx.x * 128;
    const int NT = K / 32;

    auto issue = [&](int it, int stg) {
        bf16* dAh = sm_ + stg * STG;
        bf16* dBh = dAh + 128 * 40;
        bf16* dAl = dBh + 32 * 136;
        bf16* dBl = dAl + 128 * 40;
        int k0 = it * 32;
        #pragma unroll
        for (int i = 0; i < 2; i++) {
            int pos = tid + i * 256;
            int r = pos >> 2, c = (pos & 3) * 8;
            cp16(dAh + r * 40 + c, Ap + (size_t)(row0 + r) * K + k0 + c);
            if (NTERM == 3)
                cp16(dAl + r * 40 + c, Al + (size_t)(row0 + r) * K + k0 + c);
        }
        #pragma unroll
        for (int i = 0; i < 2; i++) {
            int pos = tid + i * 256;
            int r = pos >> 4, c = (pos & 15) * 8;
            cp16(dBh + r * 136 + c, Bp + (size_t)(k0 + r) * N + col0 + c);
            if (NTERM == 3)
                cp16(dBl + r * 136 + c, Bl + (size_t)(k0 + r) * N + col0 + c);
        }
        cp_commit();
    };

    float acc[4][4][4];
    #pragma unroll
    for (int a = 0; a < 4; a++)
        #pragma unroll
        for (int b = 0; b < 4; b++)
            #pragma unroll
            for (int c = 0; c < 4; c++) acc[a][b][c] = 0.f;

    issue(0, 0);

    for (int it = 0; it < NT; it++) {
        if (it + 1 < NT) { issue(it + 1, (it + 1) & 1); cp_wait<1>(); }
        else             { cp_wait<0>(); }
        __syncthreads();

        bf16* sAh = sm_ + (it & 1) * STG;
        bf16* sBh = sAh + 128 * 40;
        bf16* sAl = sBh + 32 * 136;
        bf16* sBl = sAl + 128 * 40;

        #pragma unroll
        for (int kc = 0; kc < 2; kc++) {
            uint32_t af[4][4], bfh[2][4];
            #pragma unroll
            for (int mt = 0; mt < 4; mt++)
                ldm4(af[mt][0], af[mt][1], af[mt][2], af[mt][3],
                     cvta_s(sAh + (wm + mt * 16 + (l & 15)) * 40 + kc * 16 + ((l >> 4) * 8)));
            #pragma unroll
            for (int np = 0; np < 2; np++)
                ldm4t(bfh[np][0], bfh[np][1], bfh[np][2], bfh[np][3],
                      cvta_s(sBh + (kc * 16 + (l & 15)) * 136 + wn + np * 16 + ((l >> 4) * 8)));
            #pragma unroll
            for (int mt = 0; mt < 4; mt++)
                #pragma unroll
                for (int nt = 0; nt < 4; nt++)
                    mma_bf(acc[mt][nt], af[mt],
                           bfh[nt >> 1][(nt & 1) * 2], bfh[nt >> 1][(nt & 1) * 2 + 1]);

            if (NTERM == 3) {
                uint32_t bfl[2][4];
                #pragma unroll
                for (int np = 0; np < 2; np++)
                    ldm4t(bfl[np][0], bfl[np][1], bfl[np][2], bfl[np][3],
                          cvta_s(sBl + (kc * 16 + (l & 15)) * 136 + wn + np * 16 + ((l >> 4) * 8)));
                #pragma unroll
                for (int mt = 0; mt < 4; mt++)
                    #pragma unroll
                    for (int nt = 0; nt < 4; nt++)
                        mma_bf(acc[mt][nt], af[mt],
                               bfl[nt >> 1][(nt & 1) * 2], bfl[nt >> 1][(nt & 1) * 2 + 1]);
                uint32_t afl[4][4];
                #pragma unroll
                for (int mt = 0; mt < 4; mt++)
                    ldm4(afl[mt][0], afl[mt][1], afl[mt][2], afl[mt][3],
                         cvta_s(sAl + (wm + mt * 16 + (l & 15)) * 40 + kc * 16 + ((l >> 4) * 8)));
                #pragma unroll
                for (int mt = 0; mt < 4; mt++)
                    #pragma unroll
                    for (int nt = 0; nt < 4; nt++)
                        mma_bf(acc[mt][nt], afl[mt],
                               bfh[nt >> 1][(nt & 1) * 2], bfh[nt >> 1][(nt & 1) * 2 + 1]);
            }
        }
        __syncthreads();
    }

    #pragma unroll
    for (int mt = 0; mt < 4; mt++) {
        int r = row0 + wm + mt * 16 + (l >> 2);
        #pragma unroll
        for (int nt = 0; nt < 4; nt++) {
            int c = col0 + wn + nt * 8 + (l & 3) * 2;
            if (HEAD) {
                int h = c >> 6, d = c & 63;
                *(float2*)&Cp[((size_t)h * M + r) * DK + d] =
                    make_float2(acc[mt][nt][0], acc[mt][nt][1]);
                *(float2*)&Cp[((size_t)h * M + r + 8) * DK + d] =
                    make_float2(acc[mt][nt][2], acc[mt][nt][3]);
            } else {
                *(float2*)&Cp[(size_t)r * N + c] =
                    make_float2(acc[mt][nt][0], acc[mt][nt][1]);
                *(float2*)&Cp[(size_t)(r + 8) * N + c] =
                    make_float2(acc[mt][nt][2], acc[mt][nt][3]);
            }
        }
    }
}

// ---------------- L2-normalize rows -> bf16 ----------------
__global__ void l2norm_emit()
{
    int gid  = blockIdx.x * 256 + threadIdx.x;
    int warp = gid >> 5, l = gid & 31;
    const float* src;
    bf16* dst;
    int r = warp & (NH * S_LEN - 1);
    if (warp < NH * S_LEN) { src = g_Q; dst = b_Qn; }
    else                   { src = g_K; dst = b_Kn; }

    float2 v = *(const float2*)&src[(size_t)r * DK + l * 2];
    float ss = v.x * v.x + v.y * v.y;
    #pragma unroll
    for (int m = 16; m; m >>= 1) ss += __shfl_xor_sync(0xffffffffu, ss, m);
    float inv = 1.0f / (sqrtf(ss) + EPSN);
    ((uint32_t*)dst)[(size_t)r * 32 + l] = packbf(v.x * inv, v.y * inv);
}

// --------- V transpose + split ---------
__global__ void __launch_bounds__(256) transV()
{
    __shared__ float t[64][65];
    int h = blockIdx.y, s0 = blockIdx.x * 64;
    int tid = threadIdx.x;
    #pragma unroll
    for (int i = 0; i < 16; i++) {
        int pos = tid + i * 256;
        int r = pos >> 6, d = pos & 63;
        t[r][d] = g_V[((size_t)h * S_LEN + s0 + r) * DK + d];
    }
    __syncthreads();
    #pragma unroll
    for (int i = 0; i < 8; i++) {
        int pos = tid + i * 256;
        int d = pos >> 5, jp = pos & 31;
        float a = t[jp * 2][d], b = t[jp * 2 + 1][d];
        float ha = rbf(a), hb = rbf(b);
        size_t idx = ((size_t)h * DK + d) * (S_LEN / 2) + (s0 >> 1) + jp;
        ((uint32_t*)b_Vt_h)[idx] = packbf(ha, hb);
        ((uint32_t*)b_Vt_l)[idx] = packbf(a - ha, b - hb);
    }
}

// ---------------- fused attention, 2-stage cp.async + bias reg-prefetch ----------------
#define ASTG (128 * 72 + 2 * 64 * 136)   // elems per stage: 26624

__global__ void __launch_bounds__(256) attn_mma(const float* __restrict__ bias)
{
    extern __shared__ bf16 sm_[];

    const int tid = threadIdx.x, w = tid >> 5, l = tid & 31;
    const int h = blockIdx.y, qb = blockIdx.x * 128;

    // stage Q through stage-0 K buffer, grab fragments
    #pragma unroll
    for (int i = 0; i < 4; i++) {
        int pos = tid + i * 256;
        int r = pos >> 3, c = (pos & 7) * 8;
        *(uint4*)(sm_ + r * 72 + c) =
            *(const uint4*)(b_Qn + ((size_t)h * S_LEN + qb + r) * DK + c);
    }
    __syncthreads();
    uint32_t qf[4][4];
    #pragma unroll
    for (int dc = 0; dc < 4; dc++)
        ldm4(qf[dc][0], qf[dc][1], qf[dc][2], qf[dc][3],
             cvta_s(sm_ + (w * 16 + (l & 15)) * 72 + dc * 16 + ((l >> 4) * 8)));
    __syncthreads();

    auto issue = [&](int it, int stg) {
        bf16* dK  = sm_ + stg * ASTG;
        bf16* dVh = dK + 128 * 72;
        bf16* dVl = dVh + 64 * 136;
        int kb = it * 128;
        #pragma unroll
        for (int i = 0; i < 4; i++) {
            int pos = tid + i * 256;
            {   int r = pos >> 3, c = (pos & 7) * 8;
                cp16(dK + r * 72 + c, b_Kn + ((size_t)h * S_LEN + kb + r) * DK + c); }
            {   int r = pos >> 4, c = (pos & 15) * 8;
                size_t g = ((size_t)h * DK + r) * S_LEN + kb + c;
                cp16(dVh + r * 136 + c, b_Vt_h + g);
                cp16(dVl + r * 136 + c, b_Vt_l + g); }
        }
        cp_commit();
    };

    float oacc[8][4];
    #pragma unroll
    for (int a = 0; a < 8; a++)
        #pragma unroll
        for (int b = 0; b < 4; b++) oacc[a][b] = 0.f;
    float rs_lo = 0.f, rs_hi = 0.f;

    const float* bp = bias + ((size_t)h * S_LEN + qb + w * 16 + (l >> 2)) * S_LEN + (l & 3) * 2;

    issue(0, 0);

    for (int it = 0; it < S_LEN / 128; it++) {
        const int kb = it * 128;
        if (it + 1 < S_LEN / 128) { issue(it + 1, (it + 1) & 1); cp_wait<1>(); }
        else                      { cp_wait<0>(); }
        __syncthreads();

        bf16* sK  = sm_ + (it & 1) * ASTG;
        bf16* sVh = sK + 128 * 72;
        bf16* sVl = sVh + 64 * 136;

        // prefetch bias for this tile (latency hides under the S mma below)
        float2 bv0[16], bv1[16];
        #pragma unroll
        for (int nt = 0; nt < 16; nt++) {
            bv0[nt] = *(const float2*)(bp + kb + nt * 8);
            bv1[nt] = *(const float2*)(bp + kb + nt * 8 + 8 * S_LEN);
        }

        // S = Q @ K^T
        float s[16][4];
        #pragma unroll
        for (int a = 0; a < 16; a++)
            #pragma unroll
            for (int b = 0; b < 4; b++) s[a][b] = 0.f;
        #pragma unroll
        for (int dc = 0; dc < 4; dc++) {
            #pragma unroll
            for (int np = 0; np < 8; np++) {
                uint32_t r0, r1, r2, r3;
                ldm4(r0, r1, r2, r3,
                     cvta_s(sK + (np * 16 + (l & 15)) * 72 + dc * 16 + ((l >> 4) * 8)));
                mma_bf(s[2 * np],     qf[dc], r0, r2);
                mma_bf(s[2 * np + 1], qf[dc], r1, r3);
            }
        }

        // p = exp(s*SCALE + bias); row sums
        #pragma unroll
        for (int nt = 0; nt < 16; nt++) {
            float p0 = __expf(fmaf(s[nt][0], SCALE, bv0[nt].x));
            float p1 = __expf(fmaf(s[nt][1], SCALE, bv0[nt].y));
            float p2 = __expf(fmaf(s[nt][2], SCALE, bv1[nt].x));
            float p3 = __expf(fmaf(s[nt][3], SCALE, bv1[nt].y));
            rs_lo += p0 + p1;  rs_hi += p2 + p3;
            s[nt][0] = p0; s[nt][1] = p1; s[nt][2] = p2; s[nt][3] = p3;
        }

        // O += Ph@Vh + Pl@Vh + Ph@Vl
        #pragma unroll
        for (int kt = 0; kt < 8; kt++) {
            float x0 = s[2 * kt][0],     x1 = s[2 * kt][1];
            float x2 = s[2 * kt][2],     x3 = s[2 * kt][3];
            float y0 = s[2 * kt + 1][0], y1 = s[2 * kt + 1][1];
            float y2 = s[2 * kt + 1][2], y3 = s[2 * kt + 1][3];
            float hx0 = rbf(x0), hx1 = rbf(x1), hx2 = rbf(x2), hx3 = rbf(x3);
            float hy0 = rbf(y0), hy1 = rbf(y1), hy2 = rbf(y2), hy3 = rbf(y3);
            uint32_t ah[4], al[4];
            ah[0] = packbf(hx0, hx1);           ah[1] = packbf(hx2, hx3);
            ah[2] = packbf(hy0, hy1);           ah[3] = packbf(hy2, hy3);
            al[0] = packbf(x0 - hx0, x1 - hx1); al[1] = packbf(x2 - hx2, x3 - hx3);
            al[2] = packbf(y0 - hy0, y1 - hy1); al[3] = packbf(y2 - hy2, y3 - hy3);
            #pragma unroll
            for (int dp = 0; dp < 4; dp++) {
                uint32_t v0, v1, v2, v3, u0, u1, u2, u3;
                ldm4(v0, v1, v2, v3,
                     cvta_s(sVh + (dp * 16 + (l & 15)) * 136 + kt * 16 + ((l >> 4) * 8)));
                ldm4(u0, u1, u2, u3,
                     cvta_s(sVl + (dp * 16 + (l & 15)) * 136 + kt * 16 + ((l >> 4) * 8)));
                mma_bf(oacc[2 * dp],     ah, v0, v2);
                mma_bf(oacc[2 * dp + 1], ah, v1, v3);
                mma_bf(oacc[2 * dp],     al, v0, v2);
                mma_bf(oacc[2 * dp + 1], al, v1, v3);
                mma_bf(oacc[2 * dp],     ah, u0, u2);
                mma_bf(oacc[2 * dp + 1], ah, u1, u3);
            }
        }
        __syncthreads();
    }

    // finalize
    rs_lo += __shfl_xor_sync(0xffffffffu, rs_lo, 1);
    rs_lo += __shfl_xor_sync(0xffffffffu, rs_lo, 2);
    rs_hi += __shfl_xor_sync(0xffffffffu, rs_hi, 1);
    rs_hi += __shfl_xor_sync(0xffffffffu, rs_hi, 2);
    float il = 1.0f / rs_lo, ih = 1.0f / rs_hi;

    #pragma unroll
    for (int nt = 0; nt < 8; nt++) {
        int r = qb + w * 16 + (l >> 2);
        int c = h * DK + nt * 8 + (l & 3) * 2;
        float x0 = oacc[nt][0] * il, x1 = oacc[nt][1] * il;
        float x2 = oacc[nt][2] * ih, x3 = oacc[nt][3] * ih;
        float h0 = rbf(x0), h1 = rbf(x1), h2 = rbf(x2), h3 = rbf(x3);
        size_t i0 = ((size_t)r * DM + c) >> 1;
        size_t i1 = ((size_t)(r + 8) * DM + c) >> 1;
        ((uint32_t*)b_att_h)[i0] = packbf(h0, h1);
        ((uint32_t*)b_att_l)[i0] = packbf(x0 - h0, x1 - h1);
        ((uint32_t*)b_att_h)[i1] = packbf(h2, h3);
        ((uint32_t*)b_att_l)[i1] = packbf(x2 - h2, x3 - h3);
    }
}

// ---------------- launcher ----------------
extern "C" void kernel_launch(void* const* d_in, const int* in_sizes, int n_in,
                              void* d_out, int out_size)
{
    (void)in_sizes; (void)n_in; (void)out_size;
    const float* Qin  = (const float*)d_in[0];
    const float* Kin  = (const float*)d_in[1];
    const float* Vin  = (const float*)d_in[2];
    const float* bias = (const float*)d_in[3];
    const float* Wq   = (const float*)d_in[4];
    const float* Wk   = (const float*)d_in[5];
    const float* Wv   = (const float*)d_in[6];
    const float* Wo   = (const float*)d_in[7];
    float* out = (float*)d_out;

    float *pQ, *pK, *pV;
    bf16 *pbQin, *pbKin, *pbVinH, *pbVinL, *pbWq, *pbWk, *pbWvH, *pbWvL,
         *pbWoH, *pbWoL, *pAttH, *pAttL;
    cudaGetSymbolAddress((void**)&pQ, g_Q);
    cudaGetSymbolAddress((void**)&pK, g_K);
    cudaGetSymbolAddress((void**)&pV, g_V);
    cudaGetSymbolAddress((void**)&pbQin, b_Qin);
    cudaGetSymbolAddress((void**)&pbKin, b_Kin);
    cudaGetSymbolAddress((void**)&pbVinH, b_Vin_h);
    cudaGetSymbolAddress((void**)&pbVinL, b_Vin_l);
    cudaGetSymbolAddress((void**)&pbWq, b_Wq);
    cudaGetSymbolAddress((void**)&pbWk, b_Wk);
    cudaGetSymbolAddress((void**)&pbWvH, b_Wv_h);
    cudaGetSymbolAddress((void**)&pbWvL, b_Wv_l);
    cudaGetSymbolAddress((void**)&pbWoH, b_Wo_h);
    cudaGetSymbolAddress((void**)&pbWoL, b_Wo_l);
    cudaGetSymbolAddress((void**)&pAttH, b_att_h);
    cudaGetSymbolAddress((void**)&pAttL, b_att_l);

    // fused conversions: 3*524288 + 4*262144 float4 slots
    const int NPREP = 3 * (S_LEN * DM / 4) + 4 * (DM * DM / 4);
    prep_all<<<NPREP / 256, 256>>>((const float4*)Qin, (const float4*)Kin,
                                   (const float4*)Vin, (const float4*)Wq,
                                   (const float4*)Wk, (const float4*)Wv,
                                   (const float4*)Wo);

    const int smem1 = 2 * (128 * 40 + 32 * 136) * 2;       // 37888 B
    const int smem3 = 2 * 2 * (128 * 40 + 32 * 136) * 2;   // 75776 B
    dim3 gp(DM / 128, S_LEN / 128);                         // (8, 16)
    dim3 gp2(DM / 128, S_LEN / 128, 2);

    cudaFuncSetAttribute(mma_gemm<3, true>,
                         cudaFuncAttributeMaxDynamicSharedMemorySize, smem3);
    cudaFuncSetAttribute(mma_gemm<3, false>,
                         cudaFuncAttributeMaxDynamicSharedMemorySize, smem3);

    // batched Q & K projections (z=0 -> Q, z=1 -> K)
    mma_gemm<1, true ><<<gp2, 256, smem1>>>(pbQin, nullptr, pbWq, nullptr, pQ,
                                            pbKin, pbWk, pK, S_LEN, DM, DM);
    // V projection (split, 3-term)
    mma_gemm<3, true ><<<gp, 256, smem3>>>(pbVinH, pbVinL, pbWvH, pbWvL, pV,
                                           nullptr, nullptr, nullptr, S_LEN, DM, DM);

    l2norm_emit<<<(2 * NH * S_LEN * 32) / 256, 256>>>();
    transV<<<dim3(S_LEN / 64, NH), 256>>>();

    const int smemA = 2 * ASTG * 2;                         // 106496 B
    cudaFuncSetAttribute(attn_mma,
                         cudaFuncAttributeMaxDynamicSharedMemorySize, smemA);
    attn_mma<<<dim3(S_LEN / 128, NH), 256, smemA>>>(bias);

    mma_gemm<3, false><<<gp, 256, smem3>>>(pAttH, pAttL, pbWoH, pbWoL, out,
                                           nullptr, nullptr, nullptr, S_LEN, DM, DM);
}

// round 5
// speedup vs baseline: 6.4308x; 1.0224x over previous
#include <cuda_runtime.h>
#include <cuda_bf16.h>
#include <math.h>
#include <stdint.h>

#define S_LEN 2048
#define DM    1024
#define NH    16
#define DK    64
#define SCALE 0.125f
#define EPSN  1e-6f

typedef __nv_bfloat16 bf16;

// ---------------- scratch (__device__ globals; allocation-free) ----------------
__device__ bf16 b_Qin[(size_t)S_LEN * DM];
__device__ bf16 b_Kin[(size_t)S_LEN * DM];
__device__ bf16 b_Vin_h[(size_t)S_LEN * DM];
__device__ bf16 b_Vin_l[(size_t)S_LEN * DM];
__device__ bf16 b_Wq[(size_t)DM * DM];
__device__ bf16 b_Wk[(size_t)DM * DM];
__device__ bf16 b_Wv_h[(size_t)DM * DM];
__device__ bf16 b_Wv_l[(size_t)DM * DM];
__device__ bf16 b_Wo_h[(size_t)DM * DM];
__device__ bf16 b_Wo_l[(size_t)DM * DM];

__device__ bf16 b_Qn[(size_t)NH * S_LEN * DK];     // normalized Q, [h][s][64]
__device__ bf16 b_Kn[(size_t)NH * S_LEN * DK];
__device__ bf16 b_Vt_h[(size_t)NH * DK * S_LEN];   // V^T split, [h][64][2048]
__device__ bf16 b_Vt_l[(size_t)NH * DK * S_LEN];

__device__ bf16 b_att_h[(size_t)S_LEN * DM];
__device__ bf16 b_att_l[(size_t)S_LEN * DM];

// ---------------- helpers ----------------
__device__ __forceinline__ uint32_t cvta_s(const void* p) {
    return (uint32_t)__cvta_generic_to_shared(p);
}
__device__ __forceinline__ void cp16(void* s, const void* g) {
    asm volatile("cp.async.cg.shared.global [%0],[%1],16;" ::
                 "r"(cvta_s(s)), "l"(g));
}
__device__ __forceinline__ void cp_commit() {
    asm volatile("cp.async.commit_group;");
}
template<int N>
__device__ __forceinline__ void cp_wait() {
    asm volatile("cp.async.wait_group %0;" :: "n"(N));
}
__device__ __forceinline__ void ldm4(uint32_t& r0, uint32_t& r1, uint32_t& r2, uint32_t& r3,
                                     uint32_t a) {
    asm volatile("ldmatrix.sync.aligned.m8n8.x4.shared.b16 {%0,%1,%2,%3},[%4];"
                 : "=r"(r0), "=r"(r1), "=r"(r2), "=r"(r3) : "r"(a));
}
__device__ __forceinline__ void ldm4t(uint32_t& r0, uint32_t& r1, uint32_t& r2, uint32_t& r3,
                                      uint32_t a) {
    asm volatile("ldmatrix.sync.aligned.m8n8.x4.trans.shared.b16 {%0,%1,%2,%3},[%4];"
                 : "=r"(r0), "=r"(r1), "=r"(r2), "=r"(r3) : "r"(a));
}
__device__ __forceinline__ void mma_bf(float c[4], const uint32_t a[4],
                                       uint32_t b0, uint32_t b1) {
    asm volatile(
        "mma.sync.aligned.m16n8k16.row.col.f32.bf16.bf16.f32 "
        "{%0,%1,%2,%3},{%4,%5,%6,%7},{%8,%9},{%0,%1,%2,%3};"
        : "+f"(c[0]), "+f"(c[1]), "+f"(c[2]), "+f"(c[3])
        : "r"(a[0]), "r"(a[1]), "r"(a[2]), "r"(a[3]), "r"(b0), "r"(b1));
}
// pack two fp32 -> bf16x2; first arg in low 16 bits
__device__ __forceinline__ uint32_t packbf(float lo, float hi) {
    uint32_t r;
    asm("cvt.rn.bf16x2.f32 %0,%1,%2;" : "=r"(r) : "f"(hi), "f"(lo));
    return r;
}
__device__ __forceinline__ float rbf(float x) {
    return __bfloat162float(__float2bfloat16(x));
}

// ---------------- fused conversions (one launch) ----------------
__device__ __forceinline__ void cvt1(const float4* x, uint32_t* y, int i) {
    float4 v = x[i];
    y[2 * i + 0] = packbf(v.x, v.y);
    y[2 * i + 1] = packbf(v.z, v.w);
}
__device__ __forceinline__ void split1(const float4* x, uint32_t* hi, uint32_t* lo, int i) {
    float4 v = x[i];
    float hx = rbf(v.x), hy = rbf(v.y), hz = rbf(v.z), hw = rbf(v.w);
    hi[2 * i + 0] = packbf(hx, hy);
    hi[2 * i + 1] = packbf(hz, hw);
    lo[2 * i + 0] = packbf(v.x - hx, v.y - hy);
    lo[2 * i + 1] = packbf(v.z - hz, v.w - hw);
}
__global__ void prep_all(const float4* Qin, const float4* Kin, const float4* Vin,
                         const float4* Wq, const float4* Wk, const float4* Wv,
                         const float4* Wo)
{
    const int NI = S_LEN * DM / 4;
    const int NW = DM * DM / 4;
    int i = blockIdx.x * 256 + threadIdx.x;
    if (i < NI) { cvt1(Qin, (uint32_t*)b_Qin, i); return; }
    i -= NI;
    if (i < NI) { cvt1(Kin, (uint32_t*)b_Kin, i); return; }
    i -= NI;
    if (i < NI) { split1(Vin, (uint32_t*)b_Vin_h, (uint32_t*)b_Vin_l, i); return; }
    i -= NI;
    if (i < NW) { cvt1(Wq, (uint32_t*)b_Wq, i); return; }
    i -= NW;
    if (i < NW) { cvt1(Wk, (uint32_t*)b_Wk, i); return; }
    i -= NW;
    if (i < NW) { split1(Wv, (uint32_t*)b_Wv_h, (uint32_t*)b_Wv_l, i); return; }
    i -= NW;
    split1(Wo, (uint32_t*)b_Wo_h, (uint32_t*)b_Wo_l, i);
}

// ---------------- GEMM via mma.sync, 2-stage cp.async pipeline ----------------
// C = A @ B. 128x128 tile, BK=32, 256 threads, warp tile 64x32.
// NTERM==3: Ah*Bh + Ah*Bl + Al*Bh.
// EPI==0: plain fp32 C store.
// EPI==1: fused L2-normalize over each 64-wide head + bf16 emit to eQ (z=0)/eK (z=1).
// EPI==2: fused transpose + bf16 split emit to b_Vt_h/b_Vt_l ([h][d][s]).
// gridDim.z==2 selects (A2,B2) for z==1 (batched Q/K projections).
template<int NTERM, int EPI>
__global__ void __launch_bounds__(256)
mma_gemm(const bf16* __restrict__ Ah, const bf16* __restrict__ Al,
         const bf16* __restrict__ Bh, const bf16* __restrict__ Bl,
         float* __restrict__ C,
         const bf16* __restrict__ A2, const bf16* __restrict__ B2,
         bf16* __restrict__ eQ, bf16* __restrict__ eK,
         int M, int N, int K)
{
    extern __shared__ bf16 sm_[];
    const int STG = (NTERM == 3) ? 2 * (128 * 40 + 32 * 136) : (128 * 40 + 32 * 136);

    const bf16* Ap = (blockIdx.z == 0) ? Ah : A2;
    const bf16* Bp = (blockIdx.z == 0) ? Bh : B2;

    const int tid = threadIdx.x;
    const int w = tid >> 5, l = tid & 31;
    const int wm = (w >> 2) * 64, wn = (w & 3) * 32;
    const int row0 = blockIdx.y * 128, col0 = blockIdx.x * 128;
    const int NT = K / 32;

    auto issue = [&](int it, int stg) {
        bf16* dAh = sm_ + stg * STG;
        bf16* dBh = dAh + 128 * 40;
        bf16* dAl = dBh + 32 * 136;
        bf16* dBl = dAl + 128 * 40;
        int k0 = it * 32;
        #pragma unroll
        for (int i = 0; i < 2; i++) {
            int pos = tid + i * 256;
            int r = pos >> 2, c = (pos & 3) * 8;
            cp16(dAh + r * 40 + c, Ap + (size_t)(row0 + r) * K + k0 + c);
            if (NTERM == 3)
                cp16(dAl + r * 40 + c, Al + (size_t)(row0 + r) * K + k0 + c);
        }
        #pragma unroll
        for (int i = 0; i < 2; i++) {
            int pos = tid + i * 256;
            int r = pos >> 4, c = (pos & 15) * 8;
            cp16(dBh + r * 136 + c, Bp + (size_t)(k0 + r) * N + col0 + c);
            if (NTERM == 3)
                cp16(dBl + r * 136 + c, Bl + (size_t)(k0 + r) * N + col0 + c);
        }
        cp_commit();
    };

    float acc[4][4][4];
    #pragma unroll
    for (int a = 0; a < 4; a++)
        #pragma unroll
        for (int b = 0; b < 4; b++)
            #pragma unroll
            for (int c = 0; c < 4; c++) acc[a][b][c] = 0.f;

    issue(0, 0);

    for (int it = 0; it < NT; it++) {
        if (it + 1 < NT) { issue(it + 1, (it + 1) & 1); cp_wait<1>(); }
        else             { cp_wait<0>(); }
        __syncthreads();

        bf16* sAh = sm_ + (it & 1) * STG;
        bf16* sBh = sAh + 128 * 40;
        bf16* sAl = sBh + 32 * 136;
        bf16* sBl = sAl + 128 * 40;

        #pragma unroll
        for (int kc = 0; kc < 2; kc++) {
            uint32_t af[4][4], bfh[2][4];
            #pragma unroll
            for (int mt = 0; mt < 4; mt++)
                ldm4(af[mt][0], af[mt][1], af[mt][2], af[mt][3],
                     cvta_s(sAh + (wm + mt * 16 + (l & 15)) * 40 + kc * 16 + ((l >> 4) * 8)));
            #pragma unroll
            for (int np = 0; np < 2; np++)
                ldm4t(bfh[np][0], bfh[np][1], bfh[np][2], bfh[np][3],
                      cvta_s(sBh + (kc * 16 + (l & 15)) * 136 + wn + np * 16 + ((l >> 4) * 8)));
            #pragma unroll
            for (int mt = 0; mt < 4; mt++)
                #pragma unroll
                for (int nt = 0; nt < 4; nt++)
                    mma_bf(acc[mt][nt], af[mt],
                           bfh[nt >> 1][(nt & 1) * 2], bfh[nt >> 1][(nt & 1) * 2 + 1]);

            if (NTERM == 3) {
                uint32_t bfl[2][4];
                #pragma unroll
                for (int np = 0; np < 2; np++)
                    ldm4t(bfl[np][0], bfl[np][1], bfl[np][2], bfl[np][3],
                          cvta_s(sBl + (kc * 16 + (l & 15)) * 136 + wn + np * 16 + ((l >> 4) * 8)));
                #pragma unroll
                for (int mt = 0; mt < 4; mt++)
                    #pragma unroll
                    for (int nt = 0; nt < 4; nt++)
                        mma_bf(acc[mt][nt], af[mt],
                               bfl[nt >> 1][(nt & 1) * 2], bfl[nt >> 1][(nt & 1) * 2 + 1]);
                uint32_t afl[4][4];
                #pragma unroll
                for (int mt = 0; mt < 4; mt++)
                    ldm4(afl[mt][0], afl[mt][1], afl[mt][2], afl[mt][3],
                         cvta_s(sAl + (wm + mt * 16 + (l & 15)) * 40 + kc * 16 + ((l >> 4) * 8)));
                #pragma unroll
                for (int mt = 0; mt < 4; mt++)
                    #pragma unroll
                    for (int nt = 0; nt < 4; nt++)
                        mma_bf(acc[mt][nt], afl[mt],
                               bfh[nt >> 1][(nt & 1) * 2], bfh[nt >> 1][(nt & 1) * 2 + 1]);
            }
        }
        __syncthreads();
    }

    if (EPI == 0) {
        // plain fp32 output
        #pragma unroll
        for (int mt = 0; mt < 4; mt++) {
            int r = row0 + wm + mt * 16 + (l >> 2);
            #pragma unroll
            for (int nt = 0; nt < 4; nt++) {
                int c = col0 + wn + nt * 8 + (l & 3) * 2;
                *(float2*)&C[(size_t)r * N + c] =
                    make_float2(acc[mt][nt][0], acc[mt][nt][1]);
                *(float2*)&C[(size_t)(r + 8) * N + c] =
                    make_float2(acc[mt][nt][2], acc[mt][nt][3]);
            }
        }
    } else if (EPI == 1) {
        // fused L2 norm over d (64-wide head fits inside this block's columns)
        float* sq = (float*)sm_;                 // 128 rows x 16 (2 heads x 8 partials)
        const int cw = w & 3;
        const int hl = cw >> 1;                  // head-local 0/1
        const int slot = (cw & 1) * 4 + (l & 3);
        #pragma unroll
        for (int mt = 0; mt < 4; mt++) {
            float p0 = 0.f, p1 = 0.f;
            #pragma unroll
            for (int nt = 0; nt < 4; nt++) {
                p0 += acc[mt][nt][0] * acc[mt][nt][0] + acc[mt][nt][1] * acc[mt][nt][1];
                p1 += acc[mt][nt][2] * acc[mt][nt][2] + acc[mt][nt][3] * acc[mt][nt][3];
            }
            int rl = wm + mt * 16 + (l >> 2);
            sq[rl * 16 + hl * 8 + slot] = p0;
            sq[(rl + 8) * 16 + hl * 8 + slot] = p1;
        }
        __syncthreads();

        bf16* dst = (blockIdx.z == 0) ? eQ : eK;
        const int hg = (col0 >> 6) + hl;
        #pragma unroll
        for (int mt = 0; mt < 4; mt++) {
            int rl = wm + mt * 16 + (l >> 2);
            float ss0 = 0.f, ss1 = 0.f;
            #pragma unroll
            for (int s = 0; s < 8; s++) {
                ss0 += sq[rl * 16 + hl * 8 + s];
                ss1 += sq[(rl + 8) * 16 + hl * 8 + s];
            }
            float inv0 = 1.0f / (sqrtf(ss0) + EPSN);
            float inv1 = 1.0f / (sqrtf(ss1) + EPSN);
            #pragma unroll
            for (int nt = 0; nt < 4; nt++) {
                int d = (wn & 63) + nt * 8 + (l & 3) * 2;
                ((uint32_t*)dst)[((size_t)hg * S_LEN + row0 + rl) * 32 + (d >> 1)] =
                    packbf(acc[mt][nt][0] * inv0, acc[mt][nt][1] * inv0);
                ((uint32_t*)dst)[((size_t)hg * S_LEN + row0 + rl + 8) * 32 + (d >> 1)] =
                    packbf(acc[mt][nt][2] * inv1, acc[mt][nt][3] * inv1);
            }
        }
    } else {
        // EPI == 2: transpose + split, emit b_Vt_h/b_Vt_l [h][d][s]
        bf16* sh = sm_;                          // 128 cols x 136 rows(s)
        bf16* sl = sm_ + 128 * 136;
        #pragma unroll
        for (int mt = 0; mt < 4; mt++) {
            int rl = wm + mt * 16 + (l >> 2);
            #pragma unroll
            for (int nt = 0; nt < 4; nt++) {
                int c0 = wn + nt * 8 + (l & 3) * 2;
                #pragma unroll
                for (int j = 0; j < 2; j++) {
                    float v0 = acc[mt][nt][j];
                    float v1 = acc[mt][nt][2 + j];
                    float h0 = rbf(v0), h1 = rbf(v1);
                    sh[(c0 + j) * 136 + rl] = __float2bfloat16(h0);
                    sl[(c0 + j) * 136 + rl] = __float2bfloat16(v0 - h0);
                    sh[(c0 + j) * 136 + rl + 8] = __float2bfloat16(h1);
                    sl[(c0 + j) * 136 + rl + 8] = __float2bfloat16(v1 - h1);
                }
            }
        }
        __syncthreads();
        int cl = tid >> 1, soff = (tid & 1) * 64;
        int hg = (col0 + cl) >> 6, d = (col0 + cl) & 63;
        size_t gbase = ((size_t)hg * DK + d) * S_LEN + row0 + soff;
        const uint4* srch = (const uint4*)(sh + cl * 136 + soff);
        const uint4* srcl = (const uint4*)(sl + cl * 136 + soff);
        uint4* gh = (uint4*)(b_Vt_h + gbase);
        uint4* gl = (uint4*)(b_Vt_l + gbase);
        #pragma unroll
        for (int i = 0; i < 8; i++) gh[i] = srch[i];
        #pragma unroll
        for (int i = 0; i < 8; i++) gl[i] = srcl[i];
    }
}

// ---------------- fused attention, 2-stage cp.async + bias reg-prefetch ----------------
#define ASTG (128 * 72 + 2 * 64 * 136)   // elems per stage: 26624

__global__ void __launch_bounds__(256) attn_mma(const float* __restrict__ bias)
{
    extern __shared__ bf16 sm_[];

    const int tid = threadIdx.x, w = tid >> 5, l = tid & 31;
    const int h = blockIdx.y, qb = blockIdx.x * 128;

    // stage Q through stage-0 K buffer, grab fragments
    #pragma unroll
    for (int i = 0; i < 4; i++) {
        int pos = tid + i * 256;
        int r = pos >> 3, c = (pos & 7) * 8;
        *(uint4*)(sm_ + r * 72 + c) =
            *(const uint4*)(b_Qn + ((size_t)h * S_LEN + qb + r) * DK + c);
    }
    __syncthreads();
    uint32_t qf[4][4];
    #pragma unroll
    for (int dc = 0; dc < 4; dc++)
        ldm4(qf[dc][0], qf[dc][1], qf[dc][2], qf[dc][3],
             cvta_s(sm_ + (w * 16 + (l & 15)) * 72 + dc * 16 + ((l >> 4) * 8)));
    __syncthreads();

    auto issue = [&](int it, int stg) {
        bf16* dK  = sm_ + stg * ASTG;
        bf16* dVh = dK + 128 * 72;
        bf16* dVl = dVh + 64 * 136;
        int kb = it * 128;
        #pragma unroll
        for (int i = 0; i < 4; i++) {
            int pos = tid + i * 256;
            {   int r = pos >> 3, c = (pos & 7) * 8;
                cp16(dK + r * 72 + c, b_Kn + ((size_t)h * S_LEN + kb + r) * DK + c); }
            {   int r = pos >> 4, c = (pos & 15) * 8;
                size_t g = ((size_t)h * DK + r) * S_LEN + kb + c;
                cp16(dVh + r * 136 + c, b_Vt_h + g);
                cp16(dVl + r * 136 + c, b_Vt_l + g); }
        }
        cp_commit();
    };

    float oacc[8][4];
    #pragma unroll
    for (int a = 0; a < 8; a++)
        #pragma unroll
        for (int b = 0; b < 4; b++) oacc[a][b] = 0.f;
    float rs_lo = 0.f, rs_hi = 0.f;

    const float* bp = bias + ((size_t)h * S_LEN + qb + w * 16 + (l >> 2)) * S_LEN + (l & 3) * 2;

    issue(0, 0);

    for (int it = 0; it < S_LEN / 128; it++) {
        const int kb = it * 128;
        if (it + 1 < S_LEN / 128) { issue(it + 1, (it + 1) & 1); cp_wait<1>(); }
        else                      { cp_wait<0>(); }
        __syncthreads();

        bf16* sK  = sm_ + (it & 1) * ASTG;
        bf16* sVh = sK + 128 * 72;
        bf16* sVl = sVh + 64 * 136;

        // prefetch bias for this tile (hides under the S mma below)
        float2 bv0[16], bv1[16];
        #pragma unroll
        for (int nt = 0; nt < 16; nt++) {
            bv0[nt] = *(const float2*)(bp + kb + nt * 8);
            bv1[nt] = *(const float2*)(bp + kb + nt * 8 + 8 * S_LEN);
        }

        // S = Q @ K^T
        float s[16][4];
        #pragma unroll
        for (int a = 0; a < 16; a++)
            #pragma unroll
            for (int b = 0; b < 4; b++) s[a][b] = 0.f;
        #pragma unroll
        for (int dc = 0; dc < 4; dc++) {
            #pragma unroll
            for (int np = 0; np < 8; np++) {
                uint32_t r0, r1, r2, r3;
                ldm4(r0, r1, r2, r3,
                     cvta_s(sK + (np * 16 + (l & 15)) * 72 + dc * 16 + ((l >> 4) * 8)));
                mma_bf(s[2 * np],     qf[dc], r0, r2);
                mma_bf(s[2 * np + 1], qf[dc], r1, r3);
            }
        }

        // p = exp(s*SCALE + bias); row sums
        #pragma unroll
        for (int nt = 0; nt < 16; nt++) {
            float p0 = __expf(fmaf(s[nt][0], SCALE, bv0[nt].x));
            float p1 = __expf(fmaf(s[nt][1], SCALE, bv0[nt].y));
            float p2 = __expf(fmaf(s[nt][2], SCALE, bv1[nt].x));
            float p3 = __expf(fmaf(s[nt][3], SCALE, bv1[nt].y));
            rs_lo += p0 + p1;  rs_hi += p2 + p3;
            s[nt][0] = p0; s[nt][1] = p1; s[nt][2] = p2; s[nt][3] = p3;
        }

        // O += Ph@Vh + Pl@Vh + Ph@Vl
        #pragma unroll
        for (int kt = 0; kt < 8; kt++) {
            float x0 = s[2 * kt][0],     x1 = s[2 * kt][1];
            float x2 = s[2 * kt][2],     x3 = s[2 * kt][3];
            float y0 = s[2 * kt + 1][0], y1 = s[2 * kt + 1][1];
            float y2 = s[2 * kt + 1][2], y3 = s[2 * kt + 1][3];
            float hx0 = rbf(x0), hx1 = rbf(x1), hx2 = rbf(x2), hx3 = rbf(x3);
            float hy0 = rbf(y0), hy1 = rbf(y1), hy2 = rbf(y2), hy3 = rbf(y3);
            uint32_t ah[4], al[4];
            ah[0] = packbf(hx0, hx1);           ah[1] = packbf(hx2, hx3);
            ah[2] = packbf(hy0, hy1);           ah[3] = packbf(hy2, hy3);
            al[0] = packbf(x0 - hx0, x1 - hx1); al[1] = packbf(x2 - hx2, x3 - hx3);
            al[2] = packbf(y0 - hy0, y1 - hy1); al[3] = packbf(y2 - hy2, y3 - hy3);
            #pragma unroll
            for (int dp = 0; dp < 4; dp++) {
                uint32_t v0, v1, v2, v3, u0, u1, u2, u3;
                ldm4(v0, v1, v2, v3,
                     cvta_s(sVh + (dp * 16 + (l & 15)) * 136 + kt * 16 + ((l >> 4) * 8)));
                ldm4(u0, u1, u2, u3,
                     cvta_s(sVl + (dp * 16 + (l & 15)) * 136 + kt * 16 + ((l >> 4) * 8)));
                mma_bf(oacc[2 * dp],     ah, v0, v2);
                mma_bf(oacc[2 * dp + 1], ah, v1, v3);
                mma_bf(oacc[2 * dp],     al, v0, v2);
                mma_bf(oacc[2 * dp + 1], al, v1, v3);
                mma_bf(oacc[2 * dp],     ah, u0, u2);
                mma_bf(oacc[2 * dp + 1], ah, u1, u3);
            }
        }
        __syncthreads();
    }

    // finalize
    rs_lo += __shfl_xor_sync(0xffffffffu, rs_lo, 1);
    rs_lo += __shfl_xor_sync(0xffffffffu, rs_lo, 2);
    rs_hi += __shfl_xor_sync(0xffffffffu, rs_hi, 1);
    rs_hi += __shfl_xor_sync(0xffffffffu, rs_hi, 2);
    float il = 1.0f / rs_lo, ih = 1.0f / rs_hi;

    #pragma unroll
    for (int nt = 0; nt < 8; nt++) {
        int r = qb + w * 16 + (l >> 2);
        int c = h * DK + nt * 8 + (l & 3) * 2;
        float x0 = oacc[nt][0] * il, x1 = oacc[nt][1] * il;
        float x2 = oacc[nt][2] * ih, x3 = oacc[nt][3] * ih;
        float h0 = rbf(x0), h1 = rbf(x1), h2 = rbf(x2), h3 = rbf(x3);
        size_t i0 = ((size_t)r * DM + c) >> 1;
        size_t i1 = ((size_t)(r + 8) * DM + c) >> 1;
        ((uint32_t*)b_att_h)[i0] = packbf(h0, h1);
        ((uint32_t*)b_att_l)[i0] = packbf(x0 - h0, x1 - h1);
        ((uint32_t*)b_att_h)[i1] = packbf(h2, h3);
        ((uint32_t*)b_att_l)[i1] = packbf(x2 - h2, x3 - h3);
    }
}

// ---------------- launcher ----------------
extern "C" void kernel_launch(void* const* d_in, const int* in_sizes, int n_in,
                              void* d_out, int out_size)
{
    (void)in_sizes; (void)n_in; (void)out_size;
    const float* Qin  = (const float*)d_in[0];
    const float* Kin  = (const float*)d_in[1];
    const float* Vin  = (const float*)d_in[2];
    const float* bias = (const float*)d_in[3];
    const float* Wq   = (const float*)d_in[4];
    const float* Wk   = (const float*)d_in[5];
    const float* Wv   = (const float*)d_in[6];
    const float* Wo   = (const float*)d_in[7];
    float* out = (float*)d_out;

    bf16 *pbQin, *pbKin, *pbVinH, *pbVinL, *pbWq, *pbWk, *pbWvH, *pbWvL,
         *pbWoH, *pbWoL, *pQn, *pKn, *pAttH, *pAttL;
    cudaGetSymbolAddress((void**)&pbQin, b_Qin);
    cudaGetSymbolAddress((void**)&pbKin, b_Kin);
    cudaGetSymbolAddress((void**)&pbVinH, b_Vin_h);
    cudaGetSymbolAddress((void**)&pbVinL, b_Vin_l);
    cudaGetSymbolAddress((void**)&pbWq, b_Wq);
    cudaGetSymbolAddress((void**)&pbWk, b_Wk);
    cudaGetSymbolAddress((void**)&pbWvH, b_Wv_h);
    cudaGetSymbolAddress((void**)&pbWvL, b_Wv_l);
    cudaGetSymbolAddress((void**)&pbWoH, b_Wo_h);
    cudaGetSymbolAddress((void**)&pbWoL, b_Wo_l);
    cudaGetSymbolAddress((void**)&pQn, b_Qn);
    cudaGetSymbolAddress((void**)&pKn, b_Kn);
    cudaGetSymbolAddress((void**)&pAttH, b_att_h);
    cudaGetSymbolAddress((void**)&pAttL, b_att_l);

    const int NPREP = 3 * (S_LEN * DM / 4) + 4 * (DM * DM / 4);
    prep_all<<<NPREP / 256, 256>>>((const float4*)Qin, (const float4*)Kin,
                                   (const float4*)Vin, (const float4*)Wq,
                                   (const float4*)Wk, (const float4*)Wv,
                                   (const float4*)Wo);

    const int smem1 = 2 * (128 * 40 + 32 * 136) * 2;       // 37888 B
    const int smem3 = 2 * 2 * (128 * 40 + 32 * 136) * 2;   // 75776 B
    dim3 gp(DM / 128, S_LEN / 128);                         // (8, 16)
    dim3 gp2(DM / 128, S_LEN / 128, 2);

    cudaFuncSetAttribute(mma_gemm<3, 2>,
                         cudaFuncAttributeMaxDynamicSharedMemorySize, smem3);
    cudaFuncSetAttribute(mma_gemm<3, 0>,
                         cudaFuncAttributeMaxDynamicSharedMemorySize, smem3);

    // batched Q & K projections with fused L2 norm (z=0 -> Q, z=1 -> K)
    mma_gemm<1, 1><<<gp2, 256, smem1>>>(pbQin, nullptr, pbWq, nullptr, nullptr,
                                        pbKin, pbWk, pQn, pKn, S_LEN, DM, DM);
    // V projection (split, 3-term) with fused transpose+split emit
    mma_gemm<3, 2><<<gp, 256, smem3>>>(pbVinH, pbVinL, pbWvH, pbWvL, nullptr,
                                       nullptr, nullptr, nullptr, nullptr,
                                       S_LEN, DM, DM);

    const int smemA = 2 * ASTG * 2;                         // 106496 B
    cudaFuncSetAttribute(attn_mma,
                         cudaFuncAttributeMaxDynamicSharedMemorySize, smemA);
    attn_mma<<<dim3(S_LEN / 128, NH), 256, smemA>>>(bias);

    // output GEMM (split, 3-term), plain fp32 epilogue
    mma_gemm<3, 0><<<gp, 256, smem3>>>(pAttH, pAttL, pbWoH, pbWoL, out,
                                       nullptr, nullptr, nullptr, nullptr,
                                       S_LEN, DM, DM);
}

// round 6
// speedup vs baseline: 8.0228x; 1.2476x over previous
#include <cuda_runtime.h>
#include <cuda_bf16.h>
#include <math.h>
#include <stdint.h>

#define S_LEN 2048
#define DM    1024
#define NH    16
#define DK    64
#define SCALE 0.125f
#define EPSN  1e-6f

typedef __nv_bfloat16 bf16;

// ---------------- scratch (__device__ globals; allocation-free) ----------------
__device__ bf16 b_Qin[(size_t)S_LEN * DM];
__device__ bf16 b_Kin[(size_t)S_LEN * DM];
__device__ bf16 b_Vin_h[(size_t)S_LEN * DM];
__device__ bf16 b_Vin_l[(size_t)S_LEN * DM];
__device__ bf16 b_Wq[(size_t)DM * DM];
__device__ bf16 b_Wk[(size_t)DM * DM];
__device__ bf16 b_Wv_h[(size_t)DM * DM];
__device__ bf16 b_Wv_l[(size_t)DM * DM];
__device__ bf16 b_Wo_h[(size_t)DM * DM];
__device__ bf16 b_Wo_l[(size_t)DM * DM];

__device__ bf16 b_Qn[(size_t)NH * S_LEN * DK];     // normalized Q, [h][s][64]
__device__ bf16 b_Kn[(size_t)NH * S_LEN * DK];
__device__ bf16 b_Vt_h[(size_t)NH * DK * S_LEN];   // V^T split, [h][64][2048]
__device__ bf16 b_Vt_l[(size_t)NH * DK * S_LEN];

__device__ bf16 b_att_h[(size_t)S_LEN * DM];
__device__ bf16 b_att_l[(size_t)S_LEN * DM];

// ---------------- helpers ----------------
__device__ __forceinline__ uint32_t cvta_s(const void* p) {
    return (uint32_t)__cvta_generic_to_shared(p);
}
__device__ __forceinline__ void cp16(void* s, const void* g) {
    asm volatile("cp.async.cg.shared.global [%0],[%1],16;" ::
                 "r"(cvta_s(s)), "l"(g));
}
__device__ __forceinline__ void cp_commit() {
    asm volatile("cp.async.commit_group;");
}
template<int N>
__device__ __forceinline__ void cp_wait() {
    asm volatile("cp.async.wait_group %0;" :: "n"(N));
}
__device__ __forceinline__ void ldm4(uint32_t& r0, uint32_t& r1, uint32_t& r2, uint32_t& r3,
                                     uint32_t a) {
    asm volatile("ldmatrix.sync.aligned.m8n8.x4.shared.b16 {%0,%1,%2,%3},[%4];"
                 : "=r"(r0), "=r"(r1), "=r"(r2), "=r"(r3) : "r"(a));
}
__device__ __forceinline__ void ldm4t(uint32_t& r0, uint32_t& r1, uint32_t& r2, uint32_t& r3,
                                      uint32_t a) {
    asm volatile("ldmatrix.sync.aligned.m8n8.x4.trans.shared.b16 {%0,%1,%2,%3},[%4];"
                 : "=r"(r0), "=r"(r1), "=r"(r2), "=r"(r3) : "r"(a));
}
__device__ __forceinline__ void mma_bf(float c[4], const uint32_t a[4],
                                       uint32_t b0, uint32_t b1) {
    asm volatile(
        "mma.sync.aligned.m16n8k16.row.col.f32.bf16.bf16.f32 "
        "{%0,%1,%2,%3},{%4,%5,%6,%7},{%8,%9},{%0,%1,%2,%3};"
        : "+f"(c[0]), "+f"(c[1]), "+f"(c[2]), "+f"(c[3])
        : "r"(a[0]), "r"(a[1]), "r"(a[2]), "r"(a[3]), "r"(b0), "r"(b1));
}
// pack two fp32 -> bf16x2; first arg in low 16 bits
__device__ __forceinline__ uint32_t packbf(float lo, float hi) {
    uint32_t r;
    asm("cvt.rn.bf16x2.f32 %0,%1,%2;" : "=r"(r) : "f"(hi), "f"(lo));
    return r;
}
__device__ __forceinline__ float rbf(float x) {
    return __bfloat162float(__float2bfloat16(x));
}

// ---------------- fused conversions (one launch) ----------------
__device__ __forceinline__ void cvt1(const float4* x, uint32_t* y, int i) {
    float4 v = x[i];
    y[2 * i + 0] = packbf(v.x, v.y);
    y[2 * i + 1] = packbf(v.z, v.w);
}
__device__ __forceinline__ void split1(const float4* x, uint32_t* hi, uint32_t* lo, int i) {
    float4 v = x[i];
    float hx = rbf(v.x), hy = rbf(v.y), hz = rbf(v.z), hw = rbf(v.w);
    hi[2 * i + 0] = packbf(hx, hy);
    hi[2 * i + 1] = packbf(hz, hw);
    lo[2 * i + 0] = packbf(v.x - hx, v.y - hy);
    lo[2 * i + 1] = packbf(v.z - hz, v.w - hw);
}
__global__ void prep_all(const float4* Qin, const float4* Kin, const float4* Vin,
                         const float4* Wq, const float4* Wk, const float4* Wv,
                         const float4* Wo)
{
    const int NI = S_LEN * DM / 4;
    const int NW = DM * DM / 4;
    int i = blockIdx.x * 256 + threadIdx.x;
    if (i < NI) { cvt1(Qin, (uint32_t*)b_Qin, i); return; }
    i -= NI;
    if (i < NI) { cvt1(Kin, (uint32_t*)b_Kin, i); return; }
    i -= NI;
    if (i < NI) { split1(Vin, (uint32_t*)b_Vin_h, (uint32_t*)b_Vin_l, i); return; }
    i -= NI;
    if (i < NW) { cvt1(Wq, (uint32_t*)b_Wq, i); return; }
    i -= NW;
    if (i < NW) { cvt1(Wk, (uint32_t*)b_Wk, i); return; }
    i -= NW;
    if (i < NW) { split1(Wv, (uint32_t*)b_Wv_h, (uint32_t*)b_Wv_l, i); return; }
    i -= NW;
    split1(Wo, (uint32_t*)b_Wo_h, (uint32_t*)b_Wo_l, i);
}

// ---------------- GEMM via mma.sync, 2-stage cp.async pipeline ----------------
// C = A @ B. 128x128 tile, BK=32, 256 threads, warp tile 64x32.
// NTERM==3: Ah*Bh + Ah*Bl + Al*Bh.
// EPI==0: plain fp32 C.  EPI==1: fused L2-norm emit.  EPI==2: transpose+split emit.
template<int NTERM, int EPI>
__global__ void __launch_bounds__(256, 2)
mma_gemm(const bf16* __restrict__ Ah, const bf16* __restrict__ Al,
         const bf16* __restrict__ Bh, const bf16* __restrict__ Bl,
         float* __restrict__ C,
         const bf16* __restrict__ A2, const bf16* __restrict__ B2,
         bf16* __restrict__ eQ, bf16* __restrict__ eK,
         int M, int N, int K)
{
    extern __shared__ bf16 sm_[];
    const int STG = (NTERM == 3) ? 2 * (128 * 40 + 32 * 136) : (128 * 40 + 32 * 136);

    const bf16* Ap = (blockIdx.z == 0) ? Ah : A2;
    const bf16* Bp = (blockIdx.z == 0) ? Bh : B2;

    const int tid = threadIdx.x;
    const int w = tid >> 5, l = tid & 31;
    const int wm = (w >> 2) * 64, wn = (w & 3) * 32;
    const int row0 = blockIdx.y * 128, col0 = blockIdx.x * 128;
    const int NT = K / 32;

    auto issue = [&](int it, int stg) {
        bf16* dAh = sm_ + stg * STG;
        bf16* dBh = dAh + 128 * 40;
        bf16* dAl = dBh + 32 * 136;
        bf16* dBl = dAl + 128 * 40;
        int k0 = it * 32;
        #pragma unroll
        for (int i = 0; i < 2; i++) {
            int pos = tid + i * 256;
            int r = pos >> 2, c = (pos & 3) * 8;
            cp16(dAh + r * 40 + c, Ap + (size_t)(row0 + r) * K + k0 + c);
            if (NTERM == 3)
                cp16(dAl + r * 40 + c, Al + (size_t)(row0 + r) * K + k0 + c);
        }
        #pragma unroll
        for (int i = 0; i < 2; i++) {
            int pos = tid + i * 256;
            int r = pos >> 4, c = (pos & 15) * 8;
            cp16(dBh + r * 136 + c, Bp + (size_t)(k0 + r) * N + col0 + c);
            if (NTERM == 3)
                cp16(dBl + r * 136 + c, Bl + (size_t)(k0 + r) * N + col0 + c);
        }
        cp_commit();
    };

    float acc[4][4][4];
    #pragma unroll
    for (int a = 0; a < 4; a++)
        #pragma unroll
        for (int b = 0; b < 4; b++)
            #pragma unroll
            for (int c = 0; c < 4; c++) acc[a][b][c] = 0.f;

    issue(0, 0);

    for (int it = 0; it < NT; it++) {
        if (it + 1 < NT) { issue(it + 1, (it + 1) & 1); cp_wait<1>(); }
        else             { cp_wait<0>(); }
        __syncthreads();

        bf16* sAh = sm_ + (it & 1) * STG;
        bf16* sBh = sAh + 128 * 40;
        bf16* sAl = sBh + 32 * 136;
        bf16* sBl = sAl + 128 * 40;

        #pragma unroll
        for (int kc = 0; kc < 2; kc++) {
            uint32_t af[4][4], bfh[2][4];
            #pragma unroll
            for (int mt = 0; mt < 4; mt++)
                ldm4(af[mt][0], af[mt][1], af[mt][2], af[mt][3],
                     cvta_s(sAh + (wm + mt * 16 + (l & 15)) * 40 + kc * 16 + ((l >> 4) * 8)));
            #pragma unroll
            for (int np = 0; np < 2; np++)
                ldm4t(bfh[np][0], bfh[np][1], bfh[np][2], bfh[np][3],
                      cvta_s(sBh + (kc * 16 + (l & 15)) * 136 + wn + np * 16 + ((l >> 4) * 8)));
            #pragma unroll
            for (int mt = 0; mt < 4; mt++)
                #pragma unroll
                for (int nt = 0; nt < 4; nt++)
                    mma_bf(acc[mt][nt], af[mt],
                           bfh[nt >> 1][(nt & 1) * 2], bfh[nt >> 1][(nt & 1) * 2 + 1]);

            if (NTERM == 3) {
                uint32_t bfl[2][4];
                #pragma unroll
                for (int np = 0; np < 2; np++)
                    ldm4t(bfl[np][0], bfl[np][1], bfl[np][2], bfl[np][3],
                          cvta_s(sBl + (kc * 16 + (l & 15)) * 136 + wn + np * 16 + ((l >> 4) * 8)));
                #pragma unroll
                for (int mt = 0; mt < 4; mt++)
                    #pragma unroll
                    for (int nt = 0; nt < 4; nt++)
                        mma_bf(acc[mt][nt], af[mt],
                               bfl[nt >> 1][(nt & 1) * 2], bfl[nt >> 1][(nt & 1) * 2 + 1]);
                uint32_t afl[4][4];
                #pragma unroll
                for (int mt = 0; mt < 4; mt++)
                    ldm4(afl[mt][0], afl[mt][1], afl[mt][2], afl[mt][3],
                         cvta_s(sAl + (wm + mt * 16 + (l & 15)) * 40 + kc * 16 + ((l >> 4) * 8)));
                #pragma unroll
                for (int mt = 0; mt < 4; mt++)
                    #pragma unroll
                    for (int nt = 0; nt < 4; nt++)
                        mma_bf(acc[mt][nt], afl[mt],
                               bfh[nt >> 1][(nt & 1) * 2], bfh[nt >> 1][(nt & 1) * 2 + 1]);
            }
        }
        __syncthreads();
    }

    if (EPI == 0) {
        #pragma unroll
        for (int mt = 0; mt < 4; mt++) {
            int r = row0 + wm + mt * 16 + (l >> 2);
            #pragma unroll
            for (int nt = 0; nt < 4; nt++) {
                int c = col0 + wn + nt * 8 + (l & 3) * 2;
                *(float2*)&C[(size_t)r * N + c] =
                    make_float2(acc[mt][nt][0], acc[mt][nt][1]);
                *(float2*)&C[(size_t)(r + 8) * N + c] =
                    make_float2(acc[mt][nt][2], acc[mt][nt][3]);
            }
        }
    } else if (EPI == 1) {
        float* sq = (float*)sm_;                 // 128 rows x 16 (2 heads x 8 partials)
        const int cw = w & 3;
        const int hl = cw >> 1;
        const int slot = (cw & 1) * 4 + (l & 3);
        #pragma unroll
        for (int mt = 0; mt < 4; mt++) {
            float p0 = 0.f, p1 = 0.f;
            #pragma unroll
            for (int nt = 0; nt < 4; nt++) {
                p0 += acc[mt][nt][0] * acc[mt][nt][0] + acc[mt][nt][1] * acc[mt][nt][1];
                p1 += acc[mt][nt][2] * acc[mt][nt][2] + acc[mt][nt][3] * acc[mt][nt][3];
            }
            int rl = wm + mt * 16 + (l >> 2);
            sq[rl * 16 + hl * 8 + slot] = p0;
            sq[(rl + 8) * 16 + hl * 8 + slot] = p1;
        }
        __syncthreads();

        bf16* dst = (blockIdx.z == 0) ? eQ : eK;
        const int hg = (col0 >> 6) + hl;
        #pragma unroll
        for (int mt = 0; mt < 4; mt++) {
            int rl = wm + mt * 16 + (l >> 2);
            float ss0 = 0.f, ss1 = 0.f;
            #pragma unroll
            for (int s = 0; s < 8; s++) {
                ss0 += sq[rl * 16 + hl * 8 + s];
                ss1 += sq[(rl + 8) * 16 + hl * 8 + s];
            }
            float inv0 = 1.0f / (sqrtf(ss0) + EPSN);
            float inv1 = 1.0f / (sqrtf(ss1) + EPSN);
            #pragma unroll
            for (int nt = 0; nt < 4; nt++) {
                int d = (wn & 63) + nt * 8 + (l & 3) * 2;
                ((uint32_t*)dst)[((size_t)hg * S_LEN + row0 + rl) * 32 + (d >> 1)] =
                    packbf(acc[mt][nt][0] * inv0, acc[mt][nt][1] * inv0);
                ((uint32_t*)dst)[((size_t)hg * S_LEN + row0 + rl + 8) * 32 + (d >> 1)] =
                    packbf(acc[mt][nt][2] * inv1, acc[mt][nt][3] * inv1);
            }
        }
    } else {
        // EPI == 2: transpose + split, emit b_Vt_h/b_Vt_l [h][d][s]
        bf16* sh = sm_;
        bf16* sl = sm_ + 128 * 136;
        #pragma unroll
        for (int mt = 0; mt < 4; mt++) {
            int rl = wm + mt * 16 + (l >> 2);
            #pragma unroll
            for (int nt = 0; nt < 4; nt++) {
                int c0 = wn + nt * 8 + (l & 3) * 2;
                #pragma unroll
                for (int j = 0; j < 2; j++) {
                    float v0 = acc[mt][nt][j];
                    float v1 = acc[mt][nt][2 + j];
                    float h0 = rbf(v0), h1 = rbf(v1);
                    sh[(c0 + j) * 136 + rl] = __float2bfloat16(h0);
                    sl[(c0 + j) * 136 + rl] = __float2bfloat16(v0 - h0);
                    sh[(c0 + j) * 136 + rl + 8] = __float2bfloat16(h1);
                    sl[(c0 + j) * 136 + rl + 8] = __float2bfloat16(v1 - h1);
                }
            }
        }
        __syncthreads();
        int cl = tid >> 1, soff = (tid & 1) * 64;
        int hg = (col0 + cl) >> 6, d = (col0 + cl) & 63;
        size_t gbase = ((size_t)hg * DK + d) * S_LEN + row0 + soff;
        const uint4* srch = (const uint4*)(sh + cl * 136 + soff);
        const uint4* srcl = (const uint4*)(sl + cl * 136 + soff);
        uint4* gh = (uint4*)(b_Vt_h + gbase);
        uint4* gl = (uint4*)(b_Vt_l + gbase);
        #pragma unroll
        for (int i = 0; i < 8; i++) gh[i] = srch[i];
        #pragma unroll
        for (int i = 0; i < 8; i++) gl[i] = srcl[i];
    }
}

// ---------------- fused attention, k-tile=64, 2 CTAs/SM ----------------
#define ASTG (3 * 64 * 72)   // per-stage elems: K + Vh + Vl tiles = 13824

__global__ void __launch_bounds__(256, 2) attn_mma(const float* __restrict__ bias)
{
    extern __shared__ bf16 sm_[];

    const int tid = threadIdx.x, w = tid >> 5, l = tid & 31;
    const int h = blockIdx.y, qb = blockIdx.x * 128;

    // stage Q tile (128x64) through the 2-stage buffer area, grab fragments
    #pragma unroll
    for (int i = 0; i < 4; i++) {
        int pos = tid + i * 256;
        int r = pos >> 3, c = (pos & 7) * 8;
        *(uint4*)(sm_ + r * 72 + c) =
            *(const uint4*)(b_Qn + ((size_t)h * S_LEN + qb + r) * DK + c);
    }
    __syncthreads();
    uint32_t qf[4][4];
    #pragma unroll
    for (int dc = 0; dc < 4; dc++)
        ldm4(qf[dc][0], qf[dc][1], qf[dc][2], qf[dc][3],
             cvta_s(sm_ + (w * 16 + (l & 15)) * 72 + dc * 16 + ((l >> 4) * 8)));
    __syncthreads();

    auto issue = [&](int it, int stg) {
        bf16* dK  = sm_ + stg * ASTG;
        bf16* dVh = dK + 64 * 72;
        bf16* dVl = dVh + 64 * 72;
        int kb = it * 64;
        #pragma unroll
        for (int i = 0; i < 2; i++) {
            int pos = tid + i * 256;
            int r = pos >> 3, c = (pos & 7) * 8;
            cp16(dK + r * 72 + c, b_Kn + ((size_t)h * S_LEN + kb + r) * DK + c);
            size_t g = ((size_t)h * DK + r) * S_LEN + kb + c;
            cp16(dVh + r * 72 + c, b_Vt_h + g);
            cp16(dVl + r * 72 + c, b_Vt_l + g);
        }
        cp_commit();
    };

    float oacc[8][4];
    #pragma unroll
    for (int a = 0; a < 8; a++)
        #pragma unroll
        for (int b = 0; b < 4; b++) oacc[a][b] = 0.f;
    float rs_lo = 0.f, rs_hi = 0.f;

    const float* bp = bias + ((size_t)h * S_LEN + qb + w * 16 + (l >> 2)) * S_LEN + (l & 3) * 2;

    issue(0, 0);

    for (int it = 0; it < S_LEN / 64; it++) {
        const int kb = it * 64;
        if (it + 1 < S_LEN / 64) { issue(it + 1, (it + 1) & 1); cp_wait<1>(); }
        else                     { cp_wait<0>(); }
        __syncthreads();

        bf16* sK  = sm_ + (it & 1) * ASTG;
        bf16* sVh = sK + 64 * 72;
        bf16* sVl = sVh + 64 * 72;

        // prefetch bias for this tile (hides under the S mma below)
        float2 bv0[8], bv1[8];
        #pragma unroll
        for (int nt = 0; nt < 8; nt++) {
            bv0[nt] = *(const float2*)(bp + kb + nt * 8);
            bv1[nt] = *(const float2*)(bp + kb + nt * 8 + 8 * S_LEN);
        }

        // S = Q @ K^T (128 x 64 tile per block, 16 x 64 per warp)
        float s[8][4];
        #pragma unroll
        for (int a = 0; a < 8; a++)
            #pragma unroll
            for (int b = 0; b < 4; b++) s[a][b] = 0.f;
        #pragma unroll
        for (int dc = 0; dc < 4; dc++) {
            #pragma unroll
            for (int np = 0; np < 4; np++) {
                uint32_t r0, r1, r2, r3;
                ldm4(r0, r1, r2, r3,
                     cvta_s(sK + (np * 16 + (l & 15)) * 72 + dc * 16 + ((l >> 4) * 8)));
                mma_bf(s[2 * np],     qf[dc], r0, r2);
                mma_bf(s[2 * np + 1], qf[dc], r1, r3);
            }
        }

        // p = exp(s*SCALE + bias); row sums
        #pragma unroll
        for (int nt = 0; nt < 8; nt++) {
            float p0 = __expf(fmaf(s[nt][0], SCALE, bv0[nt].x));
            float p1 = __expf(fmaf(s[nt][1], SCALE, bv0[nt].y));
            float p2 = __expf(fmaf(s[nt][2], SCALE, bv1[nt].x));
            float p3 = __expf(fmaf(s[nt][3], SCALE, bv1[nt].y));
            rs_lo += p0 + p1;  rs_hi += p2 + p3;
            s[nt][0] = p0; s[nt][1] = p1; s[nt][2] = p2; s[nt][3] = p3;
        }

        // O += Ph@Vh + Pl@Vh + Ph@Vl
        #pragma unroll
        for (int kt = 0; kt < 4; kt++) {
            float x0 = s[2 * kt][0],     x1 = s[2 * kt][1];
            float x2 = s[2 * kt][2],     x3 = s[2 * kt][3];
            float y0 = s[2 * kt + 1][0], y1 = s[2 * kt + 1][1];
            float y2 = s[2 * kt + 1][2], y3 = s[2 * kt + 1][3];
            float hx0 = rbf(x0), hx1 = rbf(x1), hx2 = rbf(x2), hx3 = rbf(x3);
            float hy0 = rbf(y0), hy1 = rbf(y1), hy2 = rbf(y2), hy3 = rbf(y3);
            uint32_t ah[4], al[4];
            ah[0] = packbf(hx0, hx1);           ah[1] = packbf(hx2, hx3);
            ah[2] = packbf(hy0, hy1);           ah[3] = packbf(hy2, hy3);
            al[0] = packbf(x0 - hx0, x1 - hx1); al[1] = packbf(x2 - hx2, x3 - hx3);
            al[2] = packbf(y0 - hy0, y1 - hy1); al[3] = packbf(y2 - hy2, y3 - hy3);
            #pragma unroll
            for (int dp = 0; dp < 4; dp++) {
                uint32_t v0, v1, v2, v3, u0, u1, u2, u3;
                ldm4(v0, v1, v2, v3,
                     cvta_s(sVh + (dp * 16 + (l & 15)) * 72 + kt * 16 + ((l >> 4) * 8)));
                ldm4(u0, u1, u2, u3,
                     cvta_s(sVl + (dp * 16 + (l & 15)) * 72 + kt * 16 + ((l >> 4) * 8)));
                mma_bf(oacc[2 * dp],     ah, v0, v2);
                mma_bf(oacc[2 * dp + 1], ah, v1, v3);
                mma_bf(oacc[2 * dp],     al, v0, v2);
                mma_bf(oacc[2 * dp + 1], al, v1, v3);
                mma_bf(oacc[2 * dp],     ah, u0, u2);
                mma_bf(oacc[2 * dp + 1], ah, u1, u3);
            }
        }
        __syncthreads();
    }

    // finalize
    rs_lo += __shfl_xor_sync(0xffffffffu, rs_lo, 1);
    rs_lo += __shfl_xor_sync(0xffffffffu, rs_lo, 2);
    rs_hi += __shfl_xor_sync(0xffffffffu, rs_hi, 1);
    rs_hi += __shfl_xor_sync(0xffffffffu, rs_hi, 2);
    float il = 1.0f / rs_lo, ih = 1.0f / rs_hi;

    #pragma unroll
    for (int nt = 0; nt < 8; nt++) {
        int r = qb + w * 16 + (l >> 2);
        int c = h * DK + nt * 8 + (l & 3) * 2;
        float x0 = oacc[nt][0] * il, x1 = oacc[nt][1] * il;
        float x2 = oacc[nt][2] * ih, x3 = oacc[nt][3] * ih;
        float h0 = rbf(x0), h1 = rbf(x1), h2 = rbf(x2), h3 = rbf(x3);
        size_t i0 = ((size_t)r * DM + c) >> 1;
        size_t i1 = ((size_t)(r + 8) * DM + c) >> 1;
        ((uint32_t*)b_att_h)[i0] = packbf(h0, h1);
        ((uint32_t*)b_att_l)[i0] = packbf(x0 - h0, x1 - h1);
        ((uint32_t*)b_att_h)[i1] = packbf(h2, h3);
        ((uint32_t*)b_att_l)[i1] = packbf(x2 - h2, x3 - h3);
    }
}

// ---------------- launcher ----------------
extern "C" void kernel_launch(void* const* d_in, const int* in_sizes, int n_in,
                              void* d_out, int out_size)
{
    (void)in_sizes; (void)n_in; (void)out_size;
    const float* Qin  = (const float*)d_in[0];
    const float* Kin  = (const float*)d_in[1];
    const float* Vin  = (const float*)d_in[2];
    const float* bias = (const float*)d_in[3];
    const float* Wq   = (const float*)d_in[4];
    const float* Wk   = (const float*)d_in[5];
    const float* Wv   = (const float*)d_in[6];
    const float* Wo   = (const float*)d_in[7];
    float* out = (float*)d_out;

    bf16 *pbQin, *pbKin, *pbVinH, *pbVinL, *pbWq, *pbWk, *pbWvH, *pbWvL,
         *pbWoH, *pbWoL, *pQn, *pKn, *pAttH, *pAttL;
    cudaGetSymbolAddress((void**)&pbQin, b_Qin);
    cudaGetSymbolAddress((void**)&pbKin, b_Kin);
    cudaGetSymbolAddress((void**)&pbVinH, b_Vin_h);
    cudaGetSymbolAddress((void**)&pbVinL, b_Vin_l);
    cudaGetSymbolAddress((void**)&pbWq, b_Wq);
    cudaGetSymbolAddress((void**)&pbWk, b_Wk);
    cudaGetSymbolAddress((void**)&pbWvH, b_Wv_h);
    cudaGetSymbolAddress((void**)&pbWvL, b_Wv_l);
    cudaGetSymbolAddress((void**)&pbWoH, b_Wo_h);
    cudaGetSymbolAddress((void**)&pbWoL, b_Wo_l);
    cudaGetSymbolAddress((void**)&pQn, b_Qn);
    cudaGetSymbolAddress((void**)&pKn, b_Kn);
    cudaGetSymbolAddress((void**)&pAttH, b_att_h);
    cudaGetSymbolAddress((void**)&pAttL, b_att_l);

    const int NPREP = 3 * (S_LEN * DM / 4) + 4 * (DM * DM / 4);
    prep_all<<<NPREP / 256, 256>>>((const float4*)Qin, (const float4*)Kin,
                                   (const float4*)Vin, (const float4*)Wq,
                                   (const float4*)Wk, (const float4*)Wv,
                                   (const float4*)Wo);

    const int smem1 = 2 * (128 * 40 + 32 * 136) * 2;       // 37888 B
    const int smem3 = 2 * 2 * (128 * 40 + 32 * 136) * 2;   // 75776 B
    dim3 gp(DM / 128, S_LEN / 128);
    dim3 gp2(DM / 128, S_LEN / 128, 2);

    cudaFuncSetAttribute(mma_gemm<3, 2>,
                         cudaFuncAttributeMaxDynamicSharedMemorySize, smem3);
    cudaFuncSetAttribute(mma_gemm<3, 0>,
                         cudaFuncAttributeMaxDynamicSharedMemorySize, smem3);

    mma_gemm<1, 1><<<gp2, 256, smem1>>>(pbQin, nullptr, pbWq, nullptr, nullptr,
                                        pbKin, pbWk, pQn, pKn, S_LEN, DM, DM);
    mma_gemm<3, 2><<<gp, 256, smem3>>>(pbVinH, pbVinL, pbWvH, pbWvL, nullptr,
                                       nullptr, nullptr, nullptr, nullptr,
                                       S_LEN, DM, DM);

    const int smemA = 2 * ASTG * 2;                         // 55296 B
    cudaFuncSetAttribute(attn_mma,
                         cudaFuncAttributeMaxDynamicSharedMemorySize, smemA);
    attn_mma<<<dim3(S_LEN / 128, NH), 256, smemA>>>(bias);

    mma_gemm<3, 0><<<gp, 256, smem3>>>(pAttH, pAttL, pbWoH, pbWoL, out,
                                       nullptr, nullptr, nullptr, nullptr,
                                       S_LEN, DM, DM);
}

// round 7
// speedup vs baseline: 8.7105x; 1.0857x over previous
#include <cuda_runtime.h>
#include <cuda_bf16.h>
#include <cuda_fp16.h>
#include <math.h>
#include <stdint.h>

#define S_LEN 2048
#define DM    1024
#define NH    16
#define DK    64
#define SCALE 0.125f
#define EPSN  1e-6f

typedef __nv_bfloat16 bf16;

// ---------------- scratch (__device__ globals; allocation-free) ----------------
__device__ bf16 b_Qin[(size_t)S_LEN * DM];
__device__ bf16 b_Kin[(size_t)S_LEN * DM];
__device__ bf16 b_Vin_h[(size_t)S_LEN * DM];
__device__ bf16 b_Vin_l[(size_t)S_LEN * DM];
__device__ bf16 b_Wq[(size_t)DM * DM];
__device__ bf16 b_Wk[(size_t)DM * DM];
__device__ bf16 b_Wv_h[(size_t)DM * DM];
__device__ bf16 b_Wv_l[(size_t)DM * DM];
__device__ bf16 b_Wo_h[(size_t)DM * DM];
__device__ bf16 b_Wo_l[(size_t)DM * DM];

__device__ bf16 b_Qn[(size_t)NH * S_LEN * DK];     // normalized Q, [h][s][64]
__device__ bf16 b_Kn[(size_t)NH * S_LEN * DK];
__device__ __half v_Vt_h[(size_t)NH * DK * S_LEN]; // V^T fp16 split, [h][64][2048]
__device__ __half v_Vt_l[(size_t)NH * DK * S_LEN];

__device__ bf16 b_att_h[(size_t)S_LEN * DM];
__device__ bf16 b_att_l[(size_t)S_LEN * DM];

// ---------------- helpers ----------------
__device__ __forceinline__ uint32_t cvta_s(const void* p) {
    return (uint32_t)__cvta_generic_to_shared(p);
}
__device__ __forceinline__ void cp16(void* s, const void* g) {
    asm volatile("cp.async.cg.shared.global [%0],[%1],16;" ::
                 "r"(cvta_s(s)), "l"(g));
}
__device__ __forceinline__ void cp_commit() {
    asm volatile("cp.async.commit_group;");
}
template<int N>
__device__ __forceinline__ void cp_wait() {
    asm volatile("cp.async.wait_group %0;" :: "n"(N));
}
__device__ __forceinline__ void ldm4(uint32_t& r0, uint32_t& r1, uint32_t& r2, uint32_t& r3,
                                     uint32_t a) {
    asm volatile("ldmatrix.sync.aligned.m8n8.x4.shared.b16 {%0,%1,%2,%3},[%4];"
                 : "=r"(r0), "=r"(r1), "=r"(r2), "=r"(r3) : "r"(a));
}
__device__ __forceinline__ void ldm4t(uint32_t& r0, uint32_t& r1, uint32_t& r2, uint32_t& r3,
                                      uint32_t a) {
    asm volatile("ldmatrix.sync.aligned.m8n8.x4.trans.shared.b16 {%0,%1,%2,%3},[%4];"
                 : "=r"(r0), "=r"(r1), "=r"(r2), "=r"(r3) : "r"(a));
}
__device__ __forceinline__ void mma_bf(float c[4], const uint32_t a[4],
                                       uint32_t b0, uint32_t b1) {
    asm volatile(
        "mma.sync.aligned.m16n8k16.row.col.f32.bf16.bf16.f32 "
        "{%0,%1,%2,%3},{%4,%5,%6,%7},{%8,%9},{%0,%1,%2,%3};"
        : "+f"(c[0]), "+f"(c[1]), "+f"(c[2]), "+f"(c[3])
        : "r"(a[0]), "r"(a[1]), "r"(a[2]), "r"(a[3]), "r"(b0), "r"(b1));
}
__device__ __forceinline__ void mma_hf(float c[4], const uint32_t a[4],
                                       uint32_t b0, uint32_t b1) {
    asm volatile(
        "mma.sync.aligned.m16n8k16.row.col.f32.f16.f16.f32 "
        "{%0,%1,%2,%3},{%4,%5,%6,%7},{%8,%9},{%0,%1,%2,%3};"
        : "+f"(c[0]), "+f"(c[1]), "+f"(c[2]), "+f"(c[3])
        : "r"(a[0]), "r"(a[1]), "r"(a[2]), "r"(a[3]), "r"(b0), "r"(b1));
}
// pack two fp32 -> bf16x2 / f16x2; first arg in low 16 bits
__device__ __forceinline__ uint32_t packbf(float lo, float hi) {
    uint32_t r;
    asm("cvt.rn.bf16x2.f32 %0,%1,%2;" : "=r"(r) : "f"(hi), "f"(lo));
    return r;
}
__device__ __forceinline__ uint32_t packhf(float lo, float hi) {
    uint32_t r;
    asm("cvt.rn.f16x2.f32 %0,%1,%2;" : "=r"(r) : "f"(hi), "f"(lo));
    return r;
}
__device__ __forceinline__ float rbf(float x) {
    return __bfloat162float(__float2bfloat16(x));
}

// ---------------- fused conversions (one launch) ----------------
__device__ __forceinline__ void cvt1(const float4* x, uint32_t* y, int i) {
    float4 v = x[i];
    y[2 * i + 0] = packbf(v.x, v.y);
    y[2 * i + 1] = packbf(v.z, v.w);
}
__device__ __forceinline__ void split1(const float4* x, uint32_t* hi, uint32_t* lo, int i) {
    float4 v = x[i];
    float hx = rbf(v.x), hy = rbf(v.y), hz = rbf(v.z), hw = rbf(v.w);
    hi[2 * i + 0] = packbf(hx, hy);
    hi[2 * i + 1] = packbf(hz, hw);
    lo[2 * i + 0] = packbf(v.x - hx, v.y - hy);
    lo[2 * i + 1] = packbf(v.z - hz, v.w - hw);
}
__global__ void prep_all(const float4* Qin, const float4* Kin, const float4* Vin,
                         const float4* Wq, const float4* Wk, const float4* Wv,
                         const float4* Wo)
{
    const int NI = S_LEN * DM / 4;
    const int NW = DM * DM / 4;
    int i = blockIdx.x * 256 + threadIdx.x;
    if (i < NI) { cvt1(Qin, (uint32_t*)b_Qin, i); return; }
    i -= NI;
    if (i < NI) { cvt1(Kin, (uint32_t*)b_Kin, i); return; }
    i -= NI;
    if (i < NI) { split1(Vin, (uint32_t*)b_Vin_h, (uint32_t*)b_Vin_l, i); return; }
    i -= NI;
    if (i < NW) { cvt1(Wq, (uint32_t*)b_Wq, i); return; }
    i -= NW;
    if (i < NW) { cvt1(Wk, (uint32_t*)b_Wk, i); return; }
    i -= NW;
    if (i < NW) { split1(Wv, (uint32_t*)b_Wv_h, (uint32_t*)b_Wv_l, i); return; }
    i -= NW;
    split1(Wo, (uint32_t*)b_Wo_h, (uint32_t*)b_Wo_l, i);
}

// ---------------- GEMM via mma.sync, 2-stage cp.async, 1 sync/iter ----------------
// C = A @ B. 128x128 tile, BK=32, 256 threads, warp tile 64x32.
// NTERM==3: Ah*Bh + Ah*Bl + Al*Bh.
// EPI==0: fp32 C.  EPI==1: fused L2-norm emit (bf16).  EPI==2: transpose+split emit (fp16).
template<int NTERM, int EPI>
__global__ void __launch_bounds__(256, 2)
mma_gemm(const bf16* __restrict__ Ah, const bf16* __restrict__ Al,
         const bf16* __restrict__ Bh, const bf16* __restrict__ Bl,
         float* __restrict__ C,
         const bf16* __restrict__ A2, const bf16* __restrict__ B2,
         bf16* __restrict__ eQ, bf16* __restrict__ eK,
         int M, int N, int K)
{
    extern __shared__ bf16 sm_[];
    const int STG = (NTERM == 3) ? 2 * (128 * 40 + 32 * 136) : (128 * 40 + 32 * 136);

    const bf16* Ap = (blockIdx.z == 0) ? Ah : A2;
    const bf16* Bp = (blockIdx.z == 0) ? Bh : B2;

    const int tid = threadIdx.x;
    const int w = tid >> 5, l = tid & 31;
    const int wm = (w >> 2) * 64, wn = (w & 3) * 32;
    const int row0 = blockIdx.y * 128, col0 = blockIdx.x * 128;
    const int NT = K / 32;

    auto issue = [&](int it, int stg) {
        bf16* dAh = sm_ + stg * STG;
        bf16* dBh = dAh + 128 * 40;
        bf16* dAl = dBh + 32 * 136;
        bf16* dBl = dAl + 128 * 40;
        int k0 = it * 32;
        #pragma unroll
        for (int i = 0; i < 2; i++) {
            int pos = tid + i * 256;
            int r = pos >> 2, c = (pos & 3) * 8;
            cp16(dAh + r * 40 + c, Ap + (size_t)(row0 + r) * K + k0 + c);
            if (NTERM == 3)
                cp16(dAl + r * 40 + c, Al + (size_t)(row0 + r) * K + k0 + c);
        }
        #pragma unroll
        for (int i = 0; i < 2; i++) {
            int pos = tid + i * 256;
            int r = pos >> 4, c = (pos & 15) * 8;
            cp16(dBh + r * 136 + c, Bp + (size_t)(k0 + r) * N + col0 + c);
            if (NTERM == 3)
                cp16(dBl + r * 136 + c, Bl + (size_t)(k0 + r) * N + col0 + c);
        }
        cp_commit();
    };

    float acc[4][4][4];
    #pragma unroll
    for (int a = 0; a < 4; a++)
        #pragma unroll
        for (int b = 0; b < 4; b++)
            #pragma unroll
            for (int c = 0; c < 4; c++) acc[a][b][c] = 0.f;

    issue(0, 0);

    for (int it = 0; it < NT; it++) {
        cp_wait<0>();
        __syncthreads();
        if (it + 1 < NT) issue(it + 1, (it + 1) & 1);

        bf16* sAh = sm_ + (it & 1) * STG;
        bf16* sBh = sAh + 128 * 40;
        bf16* sAl = sBh + 32 * 136;
        bf16* sBl = sAl + 128 * 40;

        #pragma unroll
        for (int kc = 0; kc < 2; kc++) {
            uint32_t af[4][4], bfh[2][4];
            #pragma unroll
            for (int mt = 0; mt < 4; mt++)
                ldm4(af[mt][0], af[mt][1], af[mt][2], af[mt][3],
                     cvta_s(sAh + (wm + mt * 16 + (l & 15)) * 40 + kc * 16 + ((l >> 4) * 8)));
            #pragma unroll
            for (int np = 0; np < 2; np++)
                ldm4t(bfh[np][0], bfh[np][1], bfh[np][2], bfh[np][3],
                      cvta_s(sBh + (kc * 16 + (l & 15)) * 136 + wn + np * 16 + ((l >> 4) * 8)));
            #pragma unroll
            for (int mt = 0; mt < 4; mt++)
                #pragma unroll
                for (int nt = 0; nt < 4; nt++)
                    mma_bf(acc[mt][nt], af[mt],
                           bfh[nt >> 1][(nt & 1) * 2], bfh[nt >> 1][(nt & 1) * 2 + 1]);

            if (NTERM == 3) {
                uint32_t bfl[2][4];
                #pragma unroll
                for (int np = 0; np < 2; np++)
                    ldm4t(bfl[np][0], bfl[np][1], bfl[np][2], bfl[np][3],
                          cvta_s(sBl + (kc * 16 + (l & 15)) * 136 + wn + np * 16 + ((l >> 4) * 8)));
                #pragma unroll
                for (int mt = 0; mt < 4; mt++)
                    #pragma unroll
                    for (int nt = 0; nt < 4; nt++)
                        mma_bf(acc[mt][nt], af[mt],
                               bfl[nt >> 1][(nt & 1) * 2], bfl[nt >> 1][(nt & 1) * 2 + 1]);
                uint32_t afl[4][4];
                #pragma unroll
                for (int mt = 0; mt < 4; mt++)
                    ldm4(afl[mt][0], afl[mt][1], afl[mt][2], afl[mt][3],
                         cvta_s(sAl + (wm + mt * 16 + (l & 15)) * 40 + kc * 16 + ((l >> 4) * 8)));
                #pragma unroll
                for (int mt = 0; mt < 4; mt++)
                    #pragma unroll
                    for (int nt = 0; nt < 4; nt++)
                        mma_bf(acc[mt][nt], afl[mt],
                               bfh[nt >> 1][(nt & 1) * 2], bfh[nt >> 1][(nt & 1) * 2 + 1]);
            }
        }
    }
    __syncthreads();   // protect smem reuse in epilogues

    if (EPI == 0) {
        #pragma unroll
        for (int mt = 0; mt < 4; mt++) {
            int r = row0 + wm + mt * 16 + (l >> 2);
            #pragma unroll
            for (int nt = 0; nt < 4; nt++) {
                int c = col0 + wn + nt * 8 + (l & 3) * 2;
                *(float2*)&C[(size_t)r * N + c] =
                    make_float2(acc[mt][nt][0], acc[mt][nt][1]);
                *(float2*)&C[(size_t)(r + 8) * N + c] =
                    make_float2(acc[mt][nt][2], acc[mt][nt][3]);
            }
        }
    } else if (EPI == 1) {
        float* sq = (float*)sm_;                 // 128 rows x 16 (2 heads x 8 partials)
        const int cw = w & 3;
        const int hl = cw >> 1;
        const int slot = (cw & 1) * 4 + (l & 3);
        #pragma unroll
        for (int mt = 0; mt < 4; mt++) {
            float p0 = 0.f, p1 = 0.f;
            #pragma unroll
            for (int nt = 0; nt < 4; nt++) {
                p0 += acc[mt][nt][0] * acc[mt][nt][0] + acc[mt][nt][1] * acc[mt][nt][1];
                p1 += acc[mt][nt][2] * acc[mt][nt][2] + acc[mt][nt][3] * acc[mt][nt][3];
            }
            int rl = wm + mt * 16 + (l >> 2);
            sq[rl * 16 + hl * 8 + slot] = p0;
            sq[(rl + 8) * 16 + hl * 8 + slot] = p1;
        }
        __syncthreads();

        bf16* dst = (blockIdx.z == 0) ? eQ : eK;
        const int hg = (col0 >> 6) + hl;
        #pragma unroll
        for (int mt = 0; mt < 4; mt++) {
            int rl = wm + mt * 16 + (l >> 2);
            float ss0 = 0.f, ss1 = 0.f;
            #pragma unroll
            for (int s = 0; s < 8; s++) {
                ss0 += sq[rl * 16 + hl * 8 + s];
                ss1 += sq[(rl + 8) * 16 + hl * 8 + s];
            }
            float inv0 = 1.0f / (sqrtf(ss0) + EPSN);
            float inv1 = 1.0f / (sqrtf(ss1) + EPSN);
            #pragma unroll
            for (int nt = 0; nt < 4; nt++) {
                int d = (wn & 63) + nt * 8 + (l & 3) * 2;
                ((uint32_t*)dst)[((size_t)hg * S_LEN + row0 + rl) * 32 + (d >> 1)] =
                    packbf(acc[mt][nt][0] * inv0, acc[mt][nt][1] * inv0);
                ((uint32_t*)dst)[((size_t)hg * S_LEN + row0 + rl + 8) * 32 + (d >> 1)] =
                    packbf(acc[mt][nt][2] * inv1, acc[mt][nt][3] * inv1);
            }
        }
    } else {
        // EPI == 2: transpose + fp16 split, emit v_Vt_h/v_Vt_l [h][d][s]
        __half* sh = (__half*)sm_;
        __half* sl = (__half*)sm_ + 128 * 136;
        #pragma unroll
        for (int mt = 0; mt < 4; mt++) {
            int rl = wm + mt * 16 + (l >> 2);
            #pragma unroll
            for (int nt = 0; nt < 4; nt++) {
                int c0 = wn + nt * 8 + (l & 3) * 2;
                #pragma unroll
                for (int j = 0; j < 2; j++) {
                    float v0 = acc[mt][nt][j];
                    float v1 = acc[mt][nt][2 + j];
                    __half h0 = __float2half(v0), h1 = __float2half(v1);
                    sh[(c0 + j) * 136 + rl] = h0;
                    sl[(c0 + j) * 136 + rl] = __float2half(v0 - __half2float(h0));
                    sh[(c0 + j) * 136 + rl + 8] = h1;
                    sl[(c0 + j) * 136 + rl + 8] = __float2half(v1 - __half2float(h1));
                }
            }
        }
        __syncthreads();
        int cl = tid >> 1, soff = (tid & 1) * 64;
        int hg = (col0 + cl) >> 6, d = (col0 + cl) & 63;
        size_t gbase = ((size_t)hg * DK + d) * S_LEN + row0 + soff;
        const uint4* srch = (const uint4*)(sh + cl * 136 + soff);
        const uint4* srcl = (const uint4*)(sl + cl * 136 + soff);
        uint4* gh = (uint4*)(v_Vt_h + gbase);
        uint4* gl = (uint4*)(v_Vt_l + gbase);
        #pragma unroll
        for (int i = 0; i < 8; i++) gh[i] = srch[i];
        #pragma unroll
        for (int i = 0; i < 8; i++) gl[i] = srcl[i];
    }
}

// ---------------- fused attention: fp16 P, 3-stage cp.async, 1 sync/tile ----------------
#define ASTG (3 * 64 * 72)   // per-stage elems (K bf16 + Vh f16 + Vl f16) = 13824

__global__ void __launch_bounds__(256, 2) attn_mma(const float* __restrict__ bias)
{
    extern __shared__ bf16 sm_[];

    const int tid = threadIdx.x, w = tid >> 5, l = tid & 31;
    const int h = blockIdx.y, qb = blockIdx.x * 128;

    // stage Q tile (128x64) through stage-0 area, grab fragments
    #pragma unroll
    for (int i = 0; i < 4; i++) {
        int pos = tid + i * 256;
        int r = pos >> 3, c = (pos & 7) * 8;
        *(uint4*)(sm_ + r * 72 + c) =
            *(const uint4*)(b_Qn + ((size_t)h * S_LEN + qb + r) * DK + c);
    }
    __syncthreads();
    uint32_t qf[4][4];
    #pragma unroll
    for (int dc = 0; dc < 4; dc++)
        ldm4(qf[dc][0], qf[dc][1], qf[dc][2], qf[dc][3],
             cvta_s(sm_ + (w * 16 + (l & 15)) * 72 + dc * 16 + ((l >> 4) * 8)));
    __syncthreads();

    auto issue = [&](int it, int stg) {
        bf16*  dK  = sm_ + stg * ASTG;
        __half* dVh = (__half*)(dK + 64 * 72);
        __half* dVl = dVh + 64 * 72;
        int kb = it * 64;
        #pragma unroll
        for (int i = 0; i < 2; i++) {
            int pos = tid + i * 256;
            int r = pos >> 3, c = (pos & 7) * 8;
            cp16(dK + r * 72 + c, b_Kn + ((size_t)h * S_LEN + kb + r) * DK + c);
            size_t g = ((size_t)h * DK + r) * S_LEN + kb + c;
            cp16(dVh + r * 72 + c, v_Vt_h + g);
            cp16(dVl + r * 72 + c, v_Vt_l + g);
        }
        cp_commit();
    };

    float oacc[8][4];
    #pragma unroll
    for (int a = 0; a < 8; a++)
        #pragma unroll
        for (int b = 0; b < 4; b++) oacc[a][b] = 0.f;
    float rs_lo = 0.f, rs_hi = 0.f;

    const float* bp = bias + ((size_t)h * S_LEN + qb + w * 16 + (l >> 2)) * S_LEN + (l & 3) * 2;

    issue(0, 0);
    issue(1, 1);

    const int NT = S_LEN / 64;
    for (int it = 0; it < NT; it++) {
        const int kb = it * 64;
        cp_wait<1>();
        __syncthreads();
        if (it + 2 < NT) issue(it + 2, (it + 2) % 3);

        bf16*  sK  = sm_ + (it % 3) * ASTG;
        __half* sVh = (__half*)(sK + 64 * 72);
        __half* sVl = sVh + 64 * 72;

        // prefetch bias for this tile (hides under the S mma below)
        float2 bv0[8], bv1[8];
        #pragma unroll
        for (int nt = 0; nt < 8; nt++) {
            bv0[nt] = *(const float2*)(bp + kb + nt * 8);
            bv1[nt] = *(const float2*)(bp + kb + nt * 8 + 8 * S_LEN);
        }

        // S = Q @ K^T (128 x 64 tile per block, 16 x 64 per warp)
        float s[8][4];
        #pragma unroll
        for (int a = 0; a < 8; a++)
            #pragma unroll
            for (int b = 0; b < 4; b++) s[a][b] = 0.f;
        #pragma unroll
        for (int dc = 0; dc < 4; dc++) {
            #pragma unroll
            for (int np = 0; np < 4; np++) {
                uint32_t r0, r1, r2, r3;
                ldm4(r0, r1, r2, r3,
                     cvta_s(sK + (np * 16 + (l & 15)) * 72 + dc * 16 + ((l >> 4) * 8)));
                mma_bf(s[2 * np],     qf[dc], r0, r2);
                mma_bf(s[2 * np + 1], qf[dc], r1, r3);
            }
        }

        // p = exp(s*SCALE + bias); row sums
        #pragma unroll
        for (int nt = 0; nt < 8; nt++) {
            float p0 = __expf(fmaf(s[nt][0], SCALE, bv0[nt].x));
            float p1 = __expf(fmaf(s[nt][1], SCALE, bv0[nt].y));
            float p2 = __expf(fmaf(s[nt][2], SCALE, bv1[nt].x));
            float p3 = __expf(fmaf(s[nt][3], SCALE, bv1[nt].y));
            rs_lo += p0 + p1;  rs_hi += p2 + p3;
            s[nt][0] = p0; s[nt][1] = p1; s[nt][2] = p2; s[nt][3] = p3;
        }

        // O += P@Vh + P@Vl  (P single fp16, V fp16 split)
        #pragma unroll
        for (int kt = 0; kt < 4; kt++) {
            uint32_t a[4];
            a[0] = packhf(s[2 * kt][0],     s[2 * kt][1]);
            a[1] = packhf(s[2 * kt][2],     s[2 * kt][3]);
            a[2] = packhf(s[2 * kt + 1][0], s[2 * kt + 1][1]);
            a[3] = packhf(s[2 * kt + 1][2], s[2 * kt + 1][3]);
            #pragma unroll
            for (int dp = 0; dp < 4; dp++) {
                uint32_t v0, v1, v2, v3, u0, u1, u2, u3;
                ldm4(v0, v1, v2, v3,
                     cvta_s(sVh + (dp * 16 + (l & 15)) * 72 + kt * 16 + ((l >> 4) * 8)));
                ldm4(u0, u1, u2, u3,
                     cvta_s(sVl + (dp * 16 + (l & 15)) * 72 + kt * 16 + ((l >> 4) * 8)));
                mma_hf(oacc[2 * dp],     a, v0, v2);
                mma_hf(oacc[2 * dp + 1], a, v1, v3);
                mma_hf(oacc[2 * dp],     a, u0, u2);
                mma_hf(oacc[2 * dp + 1], a, u1, u3);
            }
        }
    }

    // finalize
    rs_lo += __shfl_xor_sync(0xffffffffu, rs_lo, 1);
    rs_lo += __shfl_xor_sync(0xffffffffu, rs_lo, 2);
    rs_hi += __shfl_xor_sync(0xffffffffu, rs_hi, 1);
    rs_hi += __shfl_xor_sync(0xffffffffu, rs_hi, 2);
    float il = 1.0f / rs_lo, ih = 1.0f / rs_hi;

    #pragma unroll
    for (int nt = 0; nt < 8; nt++) {
        int r = qb + w * 16 + (l >> 2);
        int c = h * DK + nt * 8 + (l & 3) * 2;
        float x0 = oacc[nt][0] * il, x1 = oacc[nt][1] * il;
        float x2 = oacc[nt][2] * ih, x3 = oacc[nt][3] * ih;
        float h0 = rbf(x0), h1 = rbf(x1), h2 = rbf(x2), h3 = rbf(x3);
        size_t i0 = ((size_t)r * DM + c) >> 1;
        size_t i1 = ((size_t)(r + 8) * DM + c) >> 1;
        ((uint32_t*)b_att_h)[i0] = packbf(h0, h1);
        ((uint32_t*)b_att_l)[i0] = packbf(x0 - h0, x1 - h1);
        ((uint32_t*)b_att_h)[i1] = packbf(h2, h3);
        ((uint32_t*)b_att_l)[i1] = packbf(x2 - h2, x3 - h3);
    }
}

// ---------------- launcher ----------------
extern "C" void kernel_launch(void* const* d_in, const int* in_sizes, int n_in,
                              void* d_out, int out_size)
{
    (void)in_sizes; (void)n_in; (void)out_size;
    const float* Qin  = (const float*)d_in[0];
    const float* Kin  = (const float*)d_in[1];
    const float* Vin  = (const float*)d_in[2];
    const float* bias = (const float*)d_in[3];
    const float* Wq   = (const float*)d_in[4];
    const float* Wk   = (const float*)d_in[5];
    const float* Wv   = (const float*)d_in[6];
    const float* Wo   = (const float*)d_in[7];
    float* out = (float*)d_out;

    bf16 *pbQin, *pbKin, *pbVinH, *pbVinL, *pbWq, *pbWk, *pbWvH, *pbWvL,
         *pbWoH, *pbWoL, *pQn, *pKn, *pAttH, *pAttL;
    cudaGetSymbolAddress((void**)&pbQin, b_Qin);
    cudaGetSymbolAddress((void**)&pbKin, b_Kin);
    cudaGetSymbolAddress((void**)&pbVinH, b_Vin_h);
    cudaGetSymbolAddress((void**)&pbVinL, b_Vin_l);
    cudaGetSymbolAddress((void**)&pbWq, b_Wq);
    cudaGetSymbolAddress((void**)&pbWk, b_Wk);
    cudaGetSymbolAddress((void**)&pbWvH, b_Wv_h);
    cudaGetSymbolAddress((void**)&pbWvL, b_Wv_l);
    cudaGetSymbolAddress((void**)&pbWoH, b_Wo_h);
    cudaGetSymbolAddress((void**)&pbWoL, b_Wo_l);
    cudaGetSymbolAddress((void**)&pQn, b_Qn);
    cudaGetSymbolAddress((void**)&pKn, b_Kn);
    cudaGetSymbolAddress((void**)&pAttH, b_att_h);
    cudaGetSymbolAddress((void**)&pAttL, b_att_l);

    const int NPREP = 3 * (S_LEN * DM / 4) + 4 * (DM * DM / 4);
    prep_all<<<NPREP / 256, 256>>>((const float4*)Qin, (const float4*)Kin,
                                   (const float4*)Vin, (const float4*)Wq,
                                   (const float4*)Wk, (const float4*)Wv,
                                   (const float4*)Wo);

    const int smem1 = 2 * (128 * 40 + 32 * 136) * 2;       // 37888 B
    const int smem3 = 2 * 2 * (128 * 40 + 32 * 136) * 2;   // 75776 B
    dim3 gp(DM / 128, S_LEN / 128);
    dim3 gp2(DM / 128, S_LEN / 128, 2);

    cudaFuncSetAttribute(mma_gemm<3, 2>,
                         cudaFuncAttributeMaxDynamicSharedMemorySize, smem3);
    cudaFuncSetAttribute(mma_gemm<3, 0>,
                         cudaFuncAttributeMaxDynamicSharedMemorySize, smem3);

    mma_gemm<1, 1><<<gp2, 256, smem1>>>(pbQin, nullptr, pbWq, nullptr, nullptr,
                                        pbKin, pbWk, pQn, pKn, S_LEN, DM, DM);
    mma_gemm<3, 2><<<gp, 256, smem3>>>(pbVinH, pbVinL, pbWvH, pbWvL, nullptr,
                                       nullptr, nullptr, nullptr, nullptr,
                                       S_LEN, DM, DM);

    const int smemA = 3 * ASTG * 2;                         // 82944 B
    cudaFuncSetAttribute(attn_mma,
                         cudaFuncAttributeMaxDynamicSharedMemorySize, smemA);
    attn_mma<<<dim3(S_LEN / 128, NH), 256, smemA>>>(bias);

    mma_gemm<3, 0><<<gp, 256, smem3>>>(pAttH, pAttL, pbWoH, pbWoL, out,
                                       nullptr, nullptr, nullptr, nullptr,
                                       S_LEN, DM, DM);
}

// round 8
// speedup vs baseline: 9.7967x; 1.1247x over previous
#include <cuda_runtime.h>
#include <cuda_bf16.h>
#include <cuda_fp16.h>
#include <math.h>
#include <stdint.h>

#define S_LEN 2048
#define DM    1024
#define NH    16
#define DK    64
#define SCALE 0.125f
#define EPSN  1e-6f

typedef __nv_bfloat16 bf16;

// ---------------- scratch (__device__ globals; allocation-free) ----------------
__device__ bf16 b_Qin[(size_t)S_LEN * DM];
__device__ bf16 b_Kin[(size_t)S_LEN * DM];
__device__ bf16 b_Vin_h[(size_t)S_LEN * DM];
__device__ bf16 b_Vin_l[(size_t)S_LEN * DM];
__device__ bf16 b_Wq[(size_t)DM * DM];
__device__ bf16 b_Wk[(size_t)DM * DM];
__device__ bf16 b_Wv_h[(size_t)DM * DM];
__device__ bf16 b_Wv_l[(size_t)DM * DM];
__device__ bf16 b_Wo_h[(size_t)DM * DM];
__device__ bf16 b_Wo_l[(size_t)DM * DM];

__device__ bf16 b_Qn[(size_t)NH * S_LEN * DK];     // normalized Q, [h][s][64]
__device__ bf16 b_Kn[(size_t)NH * S_LEN * DK];
__device__ __half v_Vt[(size_t)NH * DK * S_LEN];   // V^T fp16, [h][64][2048]

__device__ bf16 b_att_h[(size_t)S_LEN * DM];
__device__ bf16 b_att_l[(size_t)S_LEN * DM];

// ---------------- helpers ----------------
__device__ __forceinline__ uint32_t cvta_s(const void* p) {
    return (uint32_t)__cvta_generic_to_shared(p);
}
__device__ __forceinline__ void cp16(void* s, const void* g) {
    asm volatile("cp.async.cg.shared.global [%0],[%1],16;" ::
                 "r"(cvta_s(s)), "l"(g));
}
__device__ __forceinline__ void cp_commit() {
    asm volatile("cp.async.commit_group;");
}
template<int N>
__device__ __forceinline__ void cp_wait() {
    asm volatile("cp.async.wait_group %0;" :: "n"(N));
}
__device__ __forceinline__ void ldm4(uint32_t& r0, uint32_t& r1, uint32_t& r2, uint32_t& r3,
                                     uint32_t a) {
    asm volatile("ldmatrix.sync.aligned.m8n8.x4.shared.b16 {%0,%1,%2,%3},[%4];"
                 : "=r"(r0), "=r"(r1), "=r"(r2), "=r"(r3) : "r"(a));
}
__device__ __forceinline__ void ldm4t(uint32_t& r0, uint32_t& r1, uint32_t& r2, uint32_t& r3,
                                      uint32_t a) {
    asm volatile("ldmatrix.sync.aligned.m8n8.x4.trans.shared.b16 {%0,%1,%2,%3},[%4];"
                 : "=r"(r0), "=r"(r1), "=r"(r2), "=r"(r3) : "r"(a));
}
__device__ __forceinline__ void mma_bf(float c[4], const uint32_t a[4],
                                       uint32_t b0, uint32_t b1) {
    asm volatile(
        "mma.sync.aligned.m16n8k16.row.col.f32.bf16.bf16.f32 "
        "{%0,%1,%2,%3},{%4,%5,%6,%7},{%8,%9},{%0,%1,%2,%3};"
        : "+f"(c[0]), "+f"(c[1]), "+f"(c[2]), "+f"(c[3])
        : "r"(a[0]), "r"(a[1]), "r"(a[2]), "r"(a[3]), "r"(b0), "r"(b1));
}
__device__ __forceinline__ void mma_hf(float c[4], const uint32_t a[4],
                                       uint32_t b0, uint32_t b1) {
    asm volatile(
        "mma.sync.aligned.m16n8k16.row.col.f32.f16.f16.f32 "
        "{%0,%1,%2,%3},{%4,%5,%6,%7},{%8,%9},{%0,%1,%2,%3};"
        : "+f"(c[0]), "+f"(c[1]), "+f"(c[2]), "+f"(c[3])
        : "r"(a[0]), "r"(a[1]), "r"(a[2]), "r"(a[3]), "r"(b0), "r"(b1));
}
// pack two fp32 -> bf16x2 / f16x2; first arg in low 16 bits
__device__ __forceinline__ uint32_t packbf(float lo, float hi) {
    uint32_t r;
    asm("cvt.rn.bf16x2.f32 %0,%1,%2;" : "=r"(r) : "f"(hi), "f"(lo));
    return r;
}
__device__ __forceinline__ uint32_t packhf(float lo, float hi) {
    uint32_t r;
    asm("cvt.rn.f16x2.f32 %0,%1,%2;" : "=r"(r) : "f"(hi), "f"(lo));
    return r;
}
__device__ __forceinline__ float rbf(float x) {
    return __bfloat162float(__float2bfloat16(x));
}

// ---------------- fused conversions (one launch) ----------------
__device__ __forceinline__ void cvt1(const float4* x, uint32_t* y, int i) {
    float4 v = x[i];
    y[2 * i + 0] = packbf(v.x, v.y);
    y[2 * i + 1] = packbf(v.z, v.w);
}
__device__ __forceinline__ void split1(const float4* x, uint32_t* hi, uint32_t* lo, int i) {
    float4 v = x[i];
    float hx = rbf(v.x), hy = rbf(v.y), hz = rbf(v.z), hw = rbf(v.w);
    hi[2 * i + 0] = packbf(hx, hy);
    hi[2 * i + 1] = packbf(hz, hw);
    lo[2 * i + 0] = packbf(v.x - hx, v.y - hy);
    lo[2 * i + 1] = packbf(v.z - hz, v.w - hw);
}
__global__ void prep_all(const float4* Qin, const float4* Kin, const float4* Vin,
                         const float4* Wq, const float4* Wk, const float4* Wv,
                         const float4* Wo)
{
    const int NI = S_LEN * DM / 4;
    const int NW = DM * DM / 4;
    int i = blockIdx.x * 256 + threadIdx.x;
    if (i < NI) { cvt1(Qin, (uint32_t*)b_Qin, i); return; }
    i -= NI;
    if (i < NI) { cvt1(Kin, (uint32_t*)b_Kin, i); return; }
    i -= NI;
    if (i < NI) { split1(Vin, (uint32_t*)b_Vin_h, (uint32_t*)b_Vin_l, i); return; }
    i -= NI;
    if (i < NW) { cvt1(Wq, (uint32_t*)b_Wq, i); return; }
    i -= NW;
    if (i < NW) { cvt1(Wk, (uint32_t*)b_Wk, i); return; }
    i -= NW;
    if (i < NW) { split1(Wv, (uint32_t*)b_Wv_h, (uint32_t*)b_Wv_l, i); return; }
    i -= NW;
    split1(Wo, (uint32_t*)b_Wo_h, (uint32_t*)b_Wo_l, i);
}

// ---------------- GEMM via mma.sync, 2-stage cp.async, 1 sync/iter ----------------
// C = A @ B. 128x128 tile, BK=32, 256 threads, warp tile 64x32.
// NTERM==3: Ah*Bh + Ah*Bl + Al*Bh.
// EPI==0: fp32 C.  EPI==1: fused L2-norm emit (bf16).  EPI==2: transpose emit (fp16).
template<int NTERM, int EPI>
__global__ void __launch_bounds__(256, 2)
mma_gemm(const bf16* __restrict__ Ah, const bf16* __restrict__ Al,
         const bf16* __restrict__ Bh, const bf16* __restrict__ Bl,
         float* __restrict__ C,
         const bf16* __restrict__ A2, const bf16* __restrict__ B2,
         bf16* __restrict__ eQ, bf16* __restrict__ eK,
         int M, int N, int K)
{
    extern __shared__ bf16 sm_[];
    const int STG = (NTERM == 3) ? 2 * (128 * 40 + 32 * 136) : (128 * 40 + 32 * 136);

    const bf16* Ap = (blockIdx.z == 0) ? Ah : A2;
    const bf16* Bp = (blockIdx.z == 0) ? Bh : B2;

    const int tid = threadIdx.x;
    const int w = tid >> 5, l = tid & 31;
    const int wm = (w >> 2) * 64, wn = (w & 3) * 32;
    const int row0 = blockIdx.y * 128, col0 = blockIdx.x * 128;
    const int NT = K / 32;

    auto issue = [&](int it, int stg) {
        bf16* dAh = sm_ + stg * STG;
        bf16* dBh = dAh + 128 * 40;
        bf16* dAl = dBh + 32 * 136;
        bf16* dBl = dAl + 128 * 40;
        int k0 = it * 32;
        #pragma unroll
        for (int i = 0; i < 2; i++) {
            int pos = tid + i * 256;
            int r = pos >> 2, c = (pos & 3) * 8;
            cp16(dAh + r * 40 + c, Ap + (size_t)(row0 + r) * K + k0 + c);
            if (NTERM == 3)
                cp16(dAl + r * 40 + c, Al + (size_t)(row0 + r) * K + k0 + c);
        }
        #pragma unroll
        for (int i = 0; i < 2; i++) {
            int pos = tid + i * 256;
            int r = pos >> 4, c = (pos & 15) * 8;
            cp16(dBh + r * 136 + c, Bp + (size_t)(k0 + r) * N + col0 + c);
            if (NTERM == 3)
                cp16(dBl + r * 136 + c, Bl + (size_t)(k0 + r) * N + col0 + c);
        }
        cp_commit();
    };

    float acc[4][4][4];
    #pragma unroll
    for (int a = 0; a < 4; a++)
        #pragma unroll
        for (int b = 0; b < 4; b++)
            #pragma unroll
            for (int c = 0; c < 4; c++) acc[a][b][c] = 0.f;

    issue(0, 0);

    for (int it = 0; it < NT; it++) {
        cp_wait<0>();
        __syncthreads();
        if (it + 1 < NT) issue(it + 1, (it + 1) & 1);

        bf16* sAh = sm_ + (it & 1) * STG;
        bf16* sBh = sAh + 128 * 40;
        bf16* sAl = sBh + 32 * 136;
        bf16* sBl = sAl + 128 * 40;

        #pragma unroll
        for (int kc = 0; kc < 2; kc++) {
            uint32_t af[4][4], bfh[2][4];
            #pragma unroll
            for (int mt = 0; mt < 4; mt++)
                ldm4(af[mt][0], af[mt][1], af[mt][2], af[mt][3],
                     cvta_s(sAh + (wm + mt * 16 + (l & 15)) * 40 + kc * 16 + ((l >> 4) * 8)));
            #pragma unroll
            for (int np = 0; np < 2; np++)
                ldm4t(bfh[np][0], bfh[np][1], bfh[np][2], bfh[np][3],
                      cvta_s(sBh + (kc * 16 + (l & 15)) * 136 + wn + np * 16 + ((l >> 4) * 8)));
            #pragma unroll
            for (int mt = 0; mt < 4; mt++)
                #pragma unroll
                for (int nt = 0; nt < 4; nt++)
                    mma_bf(acc[mt][nt], af[mt],
                           bfh[nt >> 1][(nt & 1) * 2], bfh[nt >> 1][(nt & 1) * 2 + 1]);

            if (NTERM == 3) {
                uint32_t bfl[2][4];
                #pragma unroll
                for (int np = 0; np < 2; np++)
                    ldm4t(bfl[np][0], bfl[np][1], bfl[np][2], bfl[np][3],
                          cvta_s(sBl + (kc * 16 + (l & 15)) * 136 + wn + np * 16 + ((l >> 4) * 8)));
                #pragma unroll
                for (int mt = 0; mt < 4; mt++)
                    #pragma unroll
                    for (int nt = 0; nt < 4; nt++)
                        mma_bf(acc[mt][nt], af[mt],
                               bfl[nt >> 1][(nt & 1) * 2], bfl[nt >> 1][(nt & 1) * 2 + 1]);
                uint32_t afl[4][4];
                #pragma unroll
                for (int mt = 0; mt < 4; mt++)
                    ldm4(afl[mt][0], afl[mt][1], afl[mt][2], afl[mt][3],
                         cvta_s(sAl + (wm + mt * 16 + (l & 15)) * 40 + kc * 16 + ((l >> 4) * 8)));
                #pragma unroll
                for (int mt = 0; mt < 4; mt++)
                    #pragma unroll
                    for (int nt = 0; nt < 4; nt++)
                        mma_bf(acc[mt][nt], afl[mt],
                               bfh[nt >> 1][(nt & 1) * 2], bfh[nt >> 1][(nt & 1) * 2 + 1]);
            }
        }
    }
    __syncthreads();   // protect smem reuse in epilogues

    if (EPI == 0) {
        #pragma unroll
        for (int mt = 0; mt < 4; mt++) {
            int r = row0 + wm + mt * 16 + (l >> 2);
            #pragma unroll
            for (int nt = 0; nt < 4; nt++) {
                int c = col0 + wn + nt * 8 + (l & 3) * 2;
                *(float2*)&C[(size_t)r * N + c] =
                    make_float2(acc[mt][nt][0], acc[mt][nt][1]);
                *(float2*)&C[(size_t)(r + 8) * N + c] =
                    make_float2(acc[mt][nt][2], acc[mt][nt][3]);
            }
        }
    } else if (EPI == 1) {
        float* sq = (float*)sm_;                 // 128 rows x 16 (2 heads x 8 partials)
        const int cw = w & 3;
        const int hl = cw >> 1;
        const int slot = (cw & 1) * 4 + (l & 3);
        #pragma unroll
        for (int mt = 0; mt < 4; mt++) {
            float p0 = 0.f, p1 = 0.f;
            #pragma unroll
            for (int nt = 0; nt < 4; nt++) {
                p0 += acc[mt][nt][0] * acc[mt][nt][0] + acc[mt][nt][1] * acc[mt][nt][1];
                p1 += acc[mt][nt][2] * acc[mt][nt][2] + acc[mt][nt][3] * acc[mt][nt][3];
            }
            int rl = wm + mt * 16 + (l >> 2);
            sq[rl * 16 + hl * 8 + slot] = p0;
            sq[(rl + 8) * 16 + hl * 8 + slot] = p1;
        }
        __syncthreads();

        bf16* dst = (blockIdx.z == 0) ? eQ : eK;
        const int hg = (col0 >> 6) + hl;
        #pragma unroll
        for (int mt = 0; mt < 4; mt++) {
            int rl = wm + mt * 16 + (l >> 2);
            float ss0 = 0.f, ss1 = 0.f;
            #pragma unroll
            for (int s = 0; s < 8; s++) {
                ss0 += sq[rl * 16 + hl * 8 + s];
                ss1 += sq[(rl + 8) * 16 + hl * 8 + s];
            }
            float inv0 = 1.0f / (sqrtf(ss0) + EPSN);
            float inv1 = 1.0f / (sqrtf(ss1) + EPSN);
            #pragma unroll
            for (int nt = 0; nt < 4; nt++) {
                int d = (wn & 63) + nt * 8 + (l & 3) * 2;
                ((uint32_t*)dst)[((size_t)hg * S_LEN + row0 + rl) * 32 + (d >> 1)] =
                    packbf(acc[mt][nt][0] * inv0, acc[mt][nt][1] * inv0);
                ((uint32_t*)dst)[((size_t)hg * S_LEN + row0 + rl + 8) * 32 + (d >> 1)] =
                    packbf(acc[mt][nt][2] * inv1, acc[mt][nt][3] * inv1);
            }
        }
    } else {
        // EPI == 2: transpose, emit v_Vt (single fp16) [h][d][s]
        __half* sh = (__half*)sm_;
        #pragma unroll
        for (int mt = 0; mt < 4; mt++) {
            int rl = wm + mt * 16 + (l >> 2);
            #pragma unroll
            for (int nt = 0; nt < 4; nt++) {
                int c0 = wn + nt * 8 + (l & 3) * 2;
                #pragma unroll
                for (int j = 0; j < 2; j++) {
                    sh[(c0 + j) * 136 + rl]     = __float2half(acc[mt][nt][j]);
                    sh[(c0 + j) * 136 + rl + 8] = __float2half(acc[mt][nt][2 + j]);
                }
            }
        }
        __syncthreads();
        int cl = tid >> 1, soff = (tid & 1) * 64;
        int hg = (col0 + cl) >> 6, d = (col0 + cl) & 63;
        size_t gbase = ((size_t)hg * DK + d) * S_LEN + row0 + soff;
        const uint4* srch = (const uint4*)(sh + cl * 136 + soff);
        uint4* gh = (uint4*)(v_Vt + gbase);
        #pragma unroll
        for (int i = 0; i < 8; i++) gh[i] = srch[i];
    }
}

// ---------------- fused attention: fp16 P & V, 4-stage cp.async, 1 sync/tile ----------------
#define ASTG (2 * 64 * 72)   // per-stage elems (K bf16 + V f16) = 9216

__global__ void __launch_bounds__(256, 2) attn_mma(const float* __restrict__ bias)
{
    extern __shared__ bf16 sm_[];

    const int tid = threadIdx.x, w = tid >> 5, l = tid & 31;
    const int h = blockIdx.y, qb = blockIdx.x * 128;

    // stage Q tile (128x64) through stage-0/1 area, grab fragments
    #pragma unroll
    for (int i = 0; i < 4; i++) {
        int pos = tid + i * 256;
        int r = pos >> 3, c = (pos & 7) * 8;
        *(uint4*)(sm_ + r * 72 + c) =
            *(const uint4*)(b_Qn + ((size_t)h * S_LEN + qb + r) * DK + c);
    }
    __syncthreads();
    uint32_t qf[4][4];
    #pragma unroll
    for (int dc = 0; dc < 4; dc++)
        ldm4(qf[dc][0], qf[dc][1], qf[dc][2], qf[dc][3],
             cvta_s(sm_ + (w * 16 + (l & 15)) * 72 + dc * 16 + ((l >> 4) * 8)));
    __syncthreads();

    auto issue = [&](int it, int stg) {
        bf16*   dK = sm_ + stg * ASTG;
        __half* dV = (__half*)(dK + 64 * 72);
        int kb = it * 64;
        #pragma unroll
        for (int i = 0; i < 2; i++) {
            int pos = tid + i * 256;
            int r = pos >> 3, c = (pos & 7) * 8;
            cp16(dK + r * 72 + c, b_Kn + ((size_t)h * S_LEN + kb + r) * DK + c);
            cp16(dV + r * 72 + c, v_Vt + ((size_t)h * DK + r) * S_LEN + kb + c);
        }
        cp_commit();
    };

    float oacc[8][4];
    #pragma unroll
    for (int a = 0; a < 8; a++)
        #pragma unroll
        for (int b = 0; b < 4; b++) oacc[a][b] = 0.f;
    float rs_lo = 0.f, rs_hi = 0.f;

    const float* bp = bias + ((size_t)h * S_LEN + qb + w * 16 + (l >> 2)) * S_LEN + (l & 3) * 2;

    issue(0, 0);
    issue(1, 1);
    issue(2, 2);

    const int NT = S_LEN / 64;
    for (int it = 0; it < NT; it++) {
        const int kb = it * 64;
        cp_wait<2>();
        __syncthreads();
        if (it + 3 < NT) issue(it + 3, (it + 3) & 3);

        bf16*   sK = sm_ + (it & 3) * ASTG;
        __half* sV = (__half*)(sK + 64 * 72);

        // prefetch bias for this tile (hides under the S mma below)
        float2 bv0[8], bv1[8];
        #pragma unroll
        for (int nt = 0; nt < 8; nt++) {
            bv0[nt] = *(const float2*)(bp + kb + nt * 8);
            bv1[nt] = *(const float2*)(bp + kb + nt * 8 + 8 * S_LEN);
        }

        // S = Q @ K^T (128 x 64 tile per block, 16 x 64 per warp)
        float s[8][4];
        #pragma unroll
        for (int a = 0; a < 8; a++)
            #pragma unroll
            for (int b = 0; b < 4; b++) s[a][b] = 0.f;
        #pragma unroll
        for (int dc = 0; dc < 4; dc++) {
            #pragma unroll
            for (int np = 0; np < 4; np++) {
                uint32_t r0, r1, r2, r3;
                ldm4(r0, r1, r2, r3,
                     cvta_s(sK + (np * 16 + (l & 15)) * 72 + dc * 16 + ((l >> 4) * 8)));
                mma_bf(s[2 * np],     qf[dc], r0, r2);
                mma_bf(s[2 * np + 1], qf[dc], r1, r3);
            }
        }

        // p = exp(s*SCALE + bias); row sums
        #pragma unroll
        for (int nt = 0; nt < 8; nt++) {
            float p0 = __expf(fmaf(s[nt][0], SCALE, bv0[nt].x));
            float p1 = __expf(fmaf(s[nt][1], SCALE, bv0[nt].y));
            float p2 = __expf(fmaf(s[nt][2], SCALE, bv1[nt].x));
            float p3 = __expf(fmaf(s[nt][3], SCALE, bv1[nt].y));
            rs_lo += p0 + p1;  rs_hi += p2 + p3;
            s[nt][0] = p0; s[nt][1] = p1; s[nt][2] = p2; s[nt][3] = p3;
        }

        // O += P @ V  (single fp16 each)
        #pragma unroll
        for (int kt = 0; kt < 4; kt++) {
            uint32_t a[4];
            a[0] = packhf(s[2 * kt][0],     s[2 * kt][1]);
            a[1] = packhf(s[2 * kt][2],     s[2 * kt][3]);
            a[2] = packhf(s[2 * kt + 1][0], s[2 * kt + 1][1]);
            a[3] = packhf(s[2 * kt + 1][2], s[2 * kt + 1][3]);
            #pragma unroll
            for (int dp = 0; dp < 4; dp++) {
                uint32_t v0, v1, v2, v3;
                ldm4(v0, v1, v2, v3,
                     cvta_s(sV + (dp * 16 + (l & 15)) * 72 + kt * 16 + ((l >> 4) * 8)));
                mma_hf(oacc[2 * dp],     a, v0, v2);
                mma_hf(oacc[2 * dp + 1], a, v1, v3);
            }
        }
    }

    // finalize
    rs_lo += __shfl_xor_sync(0xffffffffu, rs_lo, 1);
    rs_lo += __shfl_xor_sync(0xffffffffu, rs_lo, 2);
    rs_hi += __shfl_xor_sync(0xffffffffu, rs_hi, 1);
    rs_hi += __shfl_xor_sync(0xffffffffu, rs_hi, 2);
    float il = 1.0f / rs_lo, ih = 1.0f / rs_hi;

    #pragma unroll
    for (int nt = 0; nt < 8; nt++) {
        int r = qb + w * 16 + (l >> 2);
        int c = h * DK + nt * 8 + (l & 3) * 2;
        float x0 = oacc[nt][0] * il, x1 = oacc[nt][1] * il;
        float x2 = oacc[nt][2] * ih, x3 = oacc[nt][3] * ih;
        float h0 = rbf(x0), h1 = rbf(x1), h2 = rbf(x2), h3 = rbf(x3);
        size_t i0 = ((size_t)r * DM + c) >> 1;
        size_t i1 = ((size_t)(r + 8) * DM + c) >> 1;
        ((uint32_t*)b_att_h)[i0] = packbf(h0, h1);
        ((uint32_t*)b_att_l)[i0] = packbf(x0 - h0, x1 - h1);
        ((uint32_t*)b_att_h)[i1] = packbf(h2, h3);
        ((uint32_t*)b_att_l)[i1] = packbf(x2 - h2, x3 - h3);
    }
}

// ---------------- launcher ----------------
extern "C" void kernel_launch(void* const* d_in, const int* in_sizes, int n_in,
                              void* d_out, int out_size)
{
    (void)in_sizes; (void)n_in; (void)out_size;
    const float* Qin  = (const float*)d_in[0];
    const float* Kin  = (const float*)d_in[1];
    const float* Vin  = (const float*)d_in[2];
    const float* bias = (const float*)d_in[3];
    const float* Wq   = (const float*)d_in[4];
    const float* Wk   = (const float*)d_in[5];
    const float* Wv   = (const float*)d_in[6];
    const float* Wo   = (const float*)d_in[7];
    float* out = (float*)d_out;

    bf16 *pbQin, *pbKin, *pbVinH, *pbVinL, *pbWq, *pbWk, *pbWvH, *pbWvL,
         *pbWoH, *pbWoL, *pQn, *pKn, *pAttH, *pAttL;
    cudaGetSymbolAddress((void**)&pbQin, b_Qin);
    cudaGetSymbolAddress((void**)&pbKin, b_Kin);
    cudaGetSymbolAddress((void**)&pbVinH, b_Vin_h);
    cudaGetSymbolAddress((void**)&pbVinL, b_Vin_l);
    cudaGetSymbolAddress((void**)&pbWq, b_Wq);
    cudaGetSymbolAddress((void**)&pbWk, b_Wk);
    cudaGetSymbolAddress((void**)&pbWvH, b_Wv_h);
    cudaGetSymbolAddress((void**)&pbWvL, b_Wv_l);
    cudaGetSymbolAddress((void**)&pbWoH, b_Wo_h);
    cudaGetSymbolAddress((void**)&pbWoL, b_Wo_l);
    cudaGetSymbolAddress((void**)&pQn, b_Qn);
    cudaGetSymbolAddress((void**)&pKn, b_Kn);
    cudaGetSymbolAddress((void**)&pAttH, b_att_h);
    cudaGetSymbolAddress((void**)&pAttL, b_att_l);

    const int NPREP = 3 * (S_LEN * DM / 4) + 4 * (DM * DM / 4);
    prep_all<<<NPREP / 256, 256>>>((const float4*)Qin, (const float4*)Kin,
                                   (const float4*)Vin, (const float4*)Wq,
                                   (const float4*)Wk, (const float4*)Wv,
                                   (const float4*)Wo);

    const int smem1 = 2 * (128 * 40 + 32 * 136) * 2;       // 37888 B
    const int smem3 = 2 * 2 * (128 * 40 + 32 * 136) * 2;   // 75776 B
    dim3 gp(DM / 128, S_LEN / 128);
    dim3 gp2(DM / 128, S_LEN / 128, 2);

    cudaFuncSetAttribute(mma_gemm<3, 2>,
                         cudaFuncAttributeMaxDynamicSharedMemorySize, smem3);
    cudaFuncSetAttribute(mma_gemm<3, 0>,
                         cudaFuncAttributeMaxDynamicSharedMemorySize, smem3);

    mma_gemm<1, 1><<<gp2, 256, smem1>>>(pbQin, nullptr, pbWq, nullptr, nullptr,
                                        pbKin, pbWk, pQn, pKn, S_LEN, DM, DM);
    mma_gemm<3, 2><<<gp, 256, smem3>>>(pbVinH, pbVinL, pbWvH, pbWvL, nullptr,
                                       nullptr, nullptr, nullptr, nullptr,
                                       S_LEN, DM, DM);

    const int smemA = 4 * ASTG * 2;                         // 73728 B
    cudaFuncSetAttribute(attn_mma,
                         cudaFuncAttributeMaxDynamicSharedMemorySize, smemA);
    attn_mma<<<dim3(S_LEN / 128, NH), 256, smemA>>>(bias);

    mma_gemm<3, 0><<<gp, 256, smem3>>>(pAttH, pAttL, pbWoH, pbWoL, out,
                                       nullptr, nullptr, nullptr, nullptr,
                                       S_LEN, DM, DM);
}

// round 9
// speedup vs baseline: 10.6402x; 1.0861x over previous
#include <cuda_runtime.h>
#include <cuda_bf16.h>
#include <cuda_fp16.h>
#include <math.h>
#include <stdint.h>

#define S_LEN 2048
#define DM    1024
#define NH    16
#define DK    64
#define SCALE 0.125f
#define EPSN  1e-6f

typedef __nv_bfloat16 bf16;

// ---------------- scratch (__device__ globals; allocation-free) ----------------
__device__ bf16 b_Qin[(size_t)S_LEN * DM];
__device__ bf16 b_Kin[(size_t)S_LEN * DM];
__device__ bf16 b_Vin_h[(size_t)S_LEN * DM];
__device__ bf16 b_Vin_l[(size_t)S_LEN * DM];
__device__ bf16 b_Wq[(size_t)DM * DM];
__device__ bf16 b_Wk[(size_t)DM * DM];
__device__ bf16 b_Wv_h[(size_t)DM * DM];
__device__ bf16 b_Wv_l[(size_t)DM * DM];
__device__ __half h_Wo_h[(size_t)DM * DM];         // W_o split into fp16 hi/lo
__device__ __half h_Wo_l[(size_t)DM * DM];

__device__ bf16 b_Qn[(size_t)NH * S_LEN * DK];     // normalized Q, [h][s][64]
__device__ bf16 b_Kn[(size_t)NH * S_LEN * DK];
__device__ __half v_Vt[(size_t)NH * DK * S_LEN];   // V^T fp16, [h][64][2048]

__device__ __half v_att[(size_t)S_LEN * DM];       // attended, single fp16

// ---------------- helpers ----------------
__device__ __forceinline__ uint32_t cvta_s(const void* p) {
    return (uint32_t)__cvta_generic_to_shared(p);
}
__device__ __forceinline__ void cp16(void* s, const void* g) {
    asm volatile("cp.async.cg.shared.global [%0],[%1],16;" ::
                 "r"(cvta_s(s)), "l"(g));
}
__device__ __forceinline__ void cp_commit() {
    asm volatile("cp.async.commit_group;");
}
template<int N>
__device__ __forceinline__ void cp_wait() {
    asm volatile("cp.async.wait_group %0;" :: "n"(N));
}
__device__ __forceinline__ void ldm4(uint32_t& r0, uint32_t& r1, uint32_t& r2, uint32_t& r3,
                                     uint32_t a) {
    asm volatile("ldmatrix.sync.aligned.m8n8.x4.shared.b16 {%0,%1,%2,%3},[%4];"
                 : "=r"(r0), "=r"(r1), "=r"(r2), "=r"(r3) : "r"(a));
}
__device__ __forceinline__ void ldm4t(uint32_t& r0, uint32_t& r1, uint32_t& r2, uint32_t& r3,
                                      uint32_t a) {
    asm volatile("ldmatrix.sync.aligned.m8n8.x4.trans.shared.b16 {%0,%1,%2,%3},[%4];"
                 : "=r"(r0), "=r"(r1), "=r"(r2), "=r"(r3) : "r"(a));
}
__device__ __forceinline__ void mma_bf(float c[4], const uint32_t a[4],
                                       uint32_t b0, uint32_t b1) {
    asm volatile(
        "mma.sync.aligned.m16n8k16.row.col.f32.bf16.bf16.f32 "
        "{%0,%1,%2,%3},{%4,%5,%6,%7},{%8,%9},{%0,%1,%2,%3};"
        : "+f"(c[0]), "+f"(c[1]), "+f"(c[2]), "+f"(c[3])
        : "r"(a[0]), "r"(a[1]), "r"(a[2]), "r"(a[3]), "r"(b0), "r"(b1));
}
__device__ __forceinline__ void mma_hf(float c[4], const uint32_t a[4],
                                       uint32_t b0, uint32_t b1) {
    asm volatile(
        "mma.sync.aligned.m16n8k16.row.col.f32.f16.f16.f32 "
        "{%0,%1,%2,%3},{%4,%5,%6,%7},{%8,%9},{%0,%1,%2,%3};"
        : "+f"(c[0]), "+f"(c[1]), "+f"(c[2]), "+f"(c[3])
        : "r"(a[0]), "r"(a[1]), "r"(a[2]), "r"(a[3]), "r"(b0), "r"(b1));
}
// pack two fp32 -> bf16x2 / f16x2; first arg in low 16 bits
__device__ __forceinline__ uint32_t packbf(float lo, float hi) {
    uint32_t r;
    asm("cvt.rn.bf16x2.f32 %0,%1,%2;" : "=r"(r) : "f"(hi), "f"(lo));
    return r;
}
__device__ __forceinline__ uint32_t packhf(float lo, float hi) {
    uint32_t r;
    asm("cvt.rn.f16x2.f32 %0,%1,%2;" : "=r"(r) : "f"(hi), "f"(lo));
    return r;
}
__device__ __forceinline__ float rbf(float x) {
    return __bfloat162float(__float2bfloat16(x));
}
__device__ __forceinline__ float rhf(float x) {
    return __half2float(__float2half(x));
}

// ---------------- fused conversions (one launch) ----------------
__device__ __forceinline__ void cvt1(const float4* x, uint32_t* y, int i) {
    float4 v = x[i];
    y[2 * i + 0] = packbf(v.x, v.y);
    y[2 * i + 1] = packbf(v.z, v.w);
}
__device__ __forceinline__ void split1(const float4* x, uint32_t* hi, uint32_t* lo, int i) {
    float4 v = x[i];
    float hx = rbf(v.x), hy = rbf(v.y), hz = rbf(v.z), hw = rbf(v.w);
    hi[2 * i + 0] = packbf(hx, hy);
    hi[2 * i + 1] = packbf(hz, hw);
    lo[2 * i + 0] = packbf(v.x - hx, v.y - hy);
    lo[2 * i + 1] = packbf(v.z - hz, v.w - hw);
}
__device__ __forceinline__ void split1h(const float4* x, uint32_t* hi, uint32_t* lo, int i) {
    float4 v = x[i];
    float hx = rhf(v.x), hy = rhf(v.y), hz = rhf(v.z), hw = rhf(v.w);
    hi[2 * i + 0] = packhf(hx, hy);
    hi[2 * i + 1] = packhf(hz, hw);
    lo[2 * i + 0] = packhf(v.x - hx, v.y - hy);
    lo[2 * i + 1] = packhf(v.z - hz, v.w - hw);
}
__global__ void prep_all(const float4* Qin, const float4* Kin, const float4* Vin,
                         const float4* Wq, const float4* Wk, const float4* Wv,
                         const float4* Wo)
{
    const int NI = S_LEN * DM / 4;
    const int NW = DM * DM / 4;
    int i = blockIdx.x * 256 + threadIdx.x;
    if (i < NI) { cvt1(Qin, (uint32_t*)b_Qin, i); return; }
    i -= NI;
    if (i < NI) { cvt1(Kin, (uint32_t*)b_Kin, i); return; }
    i -= NI;
    if (i < NI) { split1(Vin, (uint32_t*)b_Vin_h, (uint32_t*)b_Vin_l, i); return; }
    i -= NI;
    if (i < NW) { cvt1(Wq, (uint32_t*)b_Wq, i); return; }
    i -= NW;
    if (i < NW) { cvt1(Wk, (uint32_t*)b_Wk, i); return; }
    i -= NW;
    if (i < NW) { split1(Wv, (uint32_t*)b_Wv_h, (uint32_t*)b_Wv_l, i); return; }
    i -= NW;
    split1h(Wo, (uint32_t*)h_Wo_h, (uint32_t*)h_Wo_l, i);
}

// ---------------- fused QKV projection GEMM (one launch, z selects role) ----------------
// z==0: Q = Qin@Wq (1-term)  -> L2-norm bf16 emit to b_Qn
// z==1: K = Kin@Wk (1-term)  -> L2-norm bf16 emit to b_Kn
// z==2: V = Vin@Wv (3-term split) -> transpose fp16 emit to v_Vt
#define GSTG (2 * (128 * 40 + 32 * 136))   // elems per stage (hi+lo slots)

__global__ void __launch_bounds__(256, 2)
qkv_gemm()
{
    extern __shared__ bf16 sm_[];
    const int z = blockIdx.z;
    const bool three = (z == 2);
    const bf16* Ap = (z == 0) ? b_Qin : (z == 1) ? b_Kin : b_Vin_h;
    const bf16* Bp = (z == 0) ? b_Wq  : (z == 1) ? b_Wk  : b_Wv_h;

    const int tid = threadIdx.x;
    const int w = tid >> 5, l = tid & 31;
    const int wm = (w >> 2) * 64, wn = (w & 3) * 32;
    const int row0 = blockIdx.y * 128, col0 = blockIdx.x * 128;
    const int NT = DM / 32;

    auto issue = [&](int it, int stg) {
        bf16* dAh = sm_ + stg * GSTG;
        bf16* dBh = dAh + 128 * 40;
        bf16* dAl = dBh + 32 * 136;
        bf16* dBl = dAl + 128 * 40;
        int k0 = it * 32;
        #pragma unroll
        for (int i = 0; i < 2; i++) {
            int pos = tid + i * 256;
            int r = pos >> 2, c = (pos & 3) * 8;
            cp16(dAh + r * 40 + c, Ap + (size_t)(row0 + r) * DM + k0 + c);
            if (three)
                cp16(dAl + r * 40 + c, b_Vin_l + (size_t)(row0 + r) * DM + k0 + c);
        }
        #pragma unroll
        for (int i = 0; i < 2; i++) {
            int pos = tid + i * 256;
            int r = pos >> 4, c = (pos & 15) * 8;
            cp16(dBh + r * 136 + c, Bp + (size_t)(k0 + r) * DM + col0 + c);
            if (three)
                cp16(dBl + r * 136 + c, b_Wv_l + (size_t)(k0 + r) * DM + col0 + c);
        }
        cp_commit();
    };

    float acc[4][4][4];
    #pragma unroll
    for (int a = 0; a < 4; a++)
        #pragma unroll
        for (int b = 0; b < 4; b++)
            #pragma unroll
            for (int c = 0; c < 4; c++) acc[a][b][c] = 0.f;

    issue(0, 0);

    for (int it = 0; it < NT; it++) {
        cp_wait<0>();
        __syncthreads();
        if (it + 1 < NT) issue(it + 1, (it + 1) & 1);

        bf16* sAh = sm_ + (it & 1) * GSTG;
        bf16* sBh = sAh + 128 * 40;
        bf16* sAl = sBh + 32 * 136;
        bf16* sBl = sAl + 128 * 40;

        #pragma unroll
        for (int kc = 0; kc < 2; kc++) {
            uint32_t af[4][4], bfh[2][4];
            #pragma unroll
            for (int mt = 0; mt < 4; mt++)
                ldm4(af[mt][0], af[mt][1], af[mt][2], af[mt][3],
                     cvta_s(sAh + (wm + mt * 16 + (l & 15)) * 40 + kc * 16 + ((l >> 4) * 8)));
            #pragma unroll
            for (int np = 0; np < 2; np++)
                ldm4t(bfh[np][0], bfh[np][1], bfh[np][2], bfh[np][3],
                      cvta_s(sBh + (kc * 16 + (l & 15)) * 136 + wn + np * 16 + ((l >> 4) * 8)));
            #pragma unroll
            for (int mt = 0; mt < 4; mt++)
                #pragma unroll
                for (int nt = 0; nt < 4; nt++)
                    mma_bf(acc[mt][nt], af[mt],
                           bfh[nt >> 1][(nt & 1) * 2], bfh[nt >> 1][(nt & 1) * 2 + 1]);

            if (three) {
                uint32_t bfl[2][4];
                #pragma unroll
                for (int np = 0; np < 2; np++)
                    ldm4t(bfl[np][0], bfl[np][1], bfl[np][2], bfl[np][3],
                          cvta_s(sBl + (kc * 16 + (l & 15)) * 136 + wn + np * 16 + ((l >> 4) * 8)));
                #pragma unroll
                for (int mt = 0; mt < 4; mt++)
                    #pragma unroll
                    for (int nt = 0; nt < 4; nt++)
                        mma_bf(acc[mt][nt], af[mt],
                               bfl[nt >> 1][(nt & 1) * 2], bfl[nt >> 1][(nt & 1) * 2 + 1]);
                uint32_t afl[4][4];
                #pragma unroll
                for (int mt = 0; mt < 4; mt++)
                    ldm4(afl[mt][0], afl[mt][1], afl[mt][2], afl[mt][3],
                         cvta_s(sAl + (wm + mt * 16 + (l & 15)) * 40 + kc * 16 + ((l >> 4) * 8)));
                #pragma unroll
                for (int mt = 0; mt < 4; mt++)
                    #pragma unroll
                    for (int nt = 0; nt < 4; nt++)
                        mma_bf(acc[mt][nt], afl[mt],
                               bfh[nt >> 1][(nt & 1) * 2], bfh[nt >> 1][(nt & 1) * 2 + 1]);
            }
        }
    }
    __syncthreads();   // protect smem reuse in epilogues

    if (!three) {
        // fused L2 norm over d (two 64-wide heads inside this 128-col tile)
        float* sq = (float*)sm_;                 // 128 rows x 16 (2 heads x 8 partials)
        const int cw = w & 3;
        const int hl = cw >> 1;
        const int slot = (cw & 1) * 4 + (l & 3);
        #pragma unroll
        for (int mt = 0; mt < 4; mt++) {
            float p0 = 0.f, p1 = 0.f;
            #pragma unroll
            for (int nt = 0; nt < 4; nt++) {
                p0 += acc[mt][nt][0] * acc[mt][nt][0] + acc[mt][nt][1] * acc[mt][nt][1];
                p1 += acc[mt][nt][2] * acc[mt][nt][2] + acc[mt][nt][3] * acc[mt][nt][3];
            }
            int rl = wm + mt * 16 + (l >> 2);
            sq[rl * 16 + hl * 8 + slot] = p0;
            sq[(rl + 8) * 16 + hl * 8 + slot] = p1;
        }
        __syncthreads();

        bf16* dst = (z == 0) ? b_Qn : b_Kn;
        const int hg = (col0 >> 6) + hl;
        #pragma unroll
        for (int mt = 0; mt < 4; mt++) {
            int rl = wm + mt * 16 + (l >> 2);
            float ss0 = 0.f, ss1 = 0.f;
            #pragma unroll
            for (int s = 0; s < 8; s++) {
                ss0 += sq[rl * 16 + hl * 8 + s];
                ss1 += sq[(rl + 8) * 16 + hl * 8 + s];
            }
            float inv0 = 1.0f / (sqrtf(ss0) + EPSN);
            float inv1 = 1.0f / (sqrtf(ss1) + EPSN);
            #pragma unroll
            for (int nt = 0; nt < 4; nt++) {
                int d = (wn & 63) + nt * 8 + (l & 3) * 2;
                ((uint32_t*)dst)[((size_t)hg * S_LEN + row0 + rl) * 32 + (d >> 1)] =
                    packbf(acc[mt][nt][0] * inv0, acc[mt][nt][1] * inv0);
                ((uint32_t*)dst)[((size_t)hg * S_LEN + row0 + rl + 8) * 32 + (d >> 1)] =
                    packbf(acc[mt][nt][2] * inv1, acc[mt][nt][3] * inv1);
            }
        }
    } else {
        // transpose, emit v_Vt (single fp16) [h][d][s]
        __half* sh = (__half*)sm_;
        #pragma unroll
        for (int mt = 0; mt < 4; mt++) {
            int rl = wm + mt * 16 + (l >> 2);
            #pragma unroll
            for (int nt = 0; nt < 4; nt++) {
                int c0 = wn + nt * 8 + (l & 3) * 2;
                #pragma unroll
                for (int j = 0; j < 2; j++) {
                    sh[(c0 + j) * 136 + rl]     = __float2half(acc[mt][nt][j]);
                    sh[(c0 + j) * 136 + rl + 8] = __float2half(acc[mt][nt][2 + j]);
                }
            }
        }
        __syncthreads();
        int cl = tid >> 1, soff = (tid & 1) * 64;
        int hg = (col0 + cl) >> 6, d = (col0 + cl) & 63;
        size_t gbase = ((size_t)hg * DK + d) * S_LEN + row0 + soff;
        const uint4* srch = (const uint4*)(sh + cl * 136 + soff);
        uint4* gh = (uint4*)(v_Vt + gbase);
        #pragma unroll
        for (int i = 0; i < 8; i++) gh[i] = srch[i];
    }
}

// ---------------- out GEMM: out = att(f16) @ (Wo_h + Wo_l)(f16), 2-term ----------------
#define OSTG (128 * 40 + 2 * 32 * 136)   // elems per stage: A + Bh + Bl = 13824

__global__ void __launch_bounds__(256, 2)
out_gemm(float* __restrict__ out)
{
    extern __shared__ __half smh_[];

    const int tid = threadIdx.x;
    const int w = tid >> 5, l = tid & 31;
    const int wm = (w >> 2) * 64, wn = (w & 3) * 32;
    const int row0 = blockIdx.y * 128, col0 = blockIdx.x * 128;
    const int NT = DM / 32;

    auto issue = [&](int it, int stg) {
        __half* dA  = smh_ + stg * OSTG;
        __half* dBh = dA + 128 * 40;
        __half* dBl = dBh + 32 * 136;
        int k0 = it * 32;
        #pragma unroll
        for (int i = 0; i < 2; i++) {
            int pos = tid + i * 256;
            int r = pos >> 2, c = (pos & 3) * 8;
            cp16(dA + r * 40 + c, v_att + (size_t)(row0 + r) * DM + k0 + c);
        }
        #pragma unroll
        for (int i = 0; i < 2; i++) {
            int pos = tid + i * 256;
            int r = pos >> 4, c = (pos & 15) * 8;
            cp16(dBh + r * 136 + c, h_Wo_h + (size_t)(k0 + r) * DM + col0 + c);
            cp16(dBl + r * 136 + c, h_Wo_l + (size_t)(k0 + r) * DM + col0 + c);
        }
        cp_commit();
    };

    float acc[4][4][4];
    #pragma unroll
    for (int a = 0; a < 4; a++)
        #pragma unroll
        for (int b = 0; b < 4; b++)
            #pragma unroll
            for (int c = 0; c < 4; c++) acc[a][b][c] = 0.f;

    issue(0, 0);

    for (int it = 0; it < NT; it++) {
        cp_wait<0>();
        __syncthreads();
        if (it + 1 < NT) issue(it + 1, (it + 1) & 1);

        __half* sA  = smh_ + (it & 1) * OSTG;
        __half* sBh = sA + 128 * 40;
        __half* sBl = sBh + 32 * 136;

        #pragma unroll
        for (int kc = 0; kc < 2; kc++) {
            uint32_t af[4][4], bh[2][4], bl[2][4];
            #pragma unroll
            for (int mt = 0; mt < 4; mt++)
                ldm4(af[mt][0], af[mt][1], af[mt][2], af[mt][3],
                     cvta_s(sA + (wm + mt * 16 + (l & 15)) * 40 + kc * 16 + ((l >> 4) * 8)));
            #pragma unroll
            for (int np = 0; np < 2; np++) {
                ldm4t(bh[np][0], bh[np][1], bh[np][2], bh[np][3],
                      cvta_s(sBh + (kc * 16 + (l & 15)) * 136 + wn + np * 16 + ((l >> 4) * 8)));
                ldm4t(bl[np][0], bl[np][1], bl[np][2], bl[np][3],
                      cvta_s(sBl + (kc * 16 + (l & 15)) * 136 + wn + np * 16 + ((l >> 4) * 8)));
            }
            #pragma unroll
            for (int mt = 0; mt < 4; mt++)
                #pragma unroll
                for (int nt = 0; nt < 4; nt++) {
                    mma_hf(acc[mt][nt], af[mt],
                           bh[nt >> 1][(nt & 1) * 2], bh[nt >> 1][(nt & 1) * 2 + 1]);
                    mma_hf(acc[mt][nt], af[mt],
                           bl[nt >> 1][(nt & 1) * 2], bl[nt >> 1][(nt & 1) * 2 + 1]);
                }
        }
    }

    #pragma unroll
    for (int mt = 0; mt < 4; mt++) {
        int r = row0 + wm + mt * 16 + (l >> 2);
        #pragma unroll
        for (int nt = 0; nt < 4; nt++) {
            int c = col0 + wn + nt * 8 + (l & 3) * 2;
            *(float2*)&out[(size_t)r * DM + c] =
                make_float2(acc[mt][nt][0], acc[mt][nt][1]);
            *(float2*)&out[(size_t)(r + 8) * DM + c] =
                make_float2(acc[mt][nt][2], acc[mt][nt][3]);
        }
    }
}

// ---------------- fused attention: fp16 P & V, 4-stage cp.async, 1 sync/tile ----------------
#define ASTG (2 * 64 * 72)   // per-stage elems (K bf16 + V f16) = 9216

__global__ void __launch_bounds__(256, 2) attn_mma(const float* __restrict__ bias)
{
    extern __shared__ bf16 sm_[];

    const int tid = threadIdx.x, w = tid >> 5, l = tid & 31;
    const int h = blockIdx.y, qb = blockIdx.x * 128;

    // stage Q tile (128x64) through stage-0/1 area, grab fragments
    #pragma unroll
    for (int i = 0; i < 4; i++) {
        int pos = tid + i * 256;
        int r = pos >> 3, c = (pos & 7) * 8;
        *(uint4*)(sm_ + r * 72 + c) =
            *(const uint4*)(b_Qn + ((size_t)h * S_LEN + qb + r) * DK + c);
    }
    __syncthreads();
    uint32_t qf[4][4];
    #pragma unroll
    for (int dc = 0; dc < 4; dc++)
        ldm4(qf[dc][0], qf[dc][1], qf[dc][2], qf[dc][3],
             cvta_s(sm_ + (w * 16 + (l & 15)) * 72 + dc * 16 + ((l >> 4) * 8)));
    __syncthreads();

    auto issue = [&](int it, int stg) {
        bf16*   dK = sm_ + stg * ASTG;
        __half* dV = (__half*)(dK + 64 * 72);
        int kb = it * 64;
        #pragma unroll
        for (int i = 0; i < 2; i++) {
            int pos = tid + i * 256;
            int r = pos >> 3, c = (pos & 7) * 8;
            cp16(dK + r * 72 + c, b_Kn + ((size_t)h * S_LEN + kb + r) * DK + c);
            cp16(dV + r * 72 + c, v_Vt + ((size_t)h * DK + r) * S_LEN + kb + c);
        }
        cp_commit();
    };

    float oacc[8][4];
    #pragma unroll
    for (int a = 0; a < 8; a++)
        #pragma unroll
        for (int b = 0; b < 4; b++) oacc[a][b] = 0.f;
    float rs_lo = 0.f, rs_hi = 0.f;

    const float* bp = bias + ((size_t)h * S_LEN + qb + w * 16 + (l >> 2)) * S_LEN + (l & 3) * 2;

    issue(0, 0);
    issue(1, 1);
    issue(2, 2);

    const int NT = S_LEN / 64;
    for (int it = 0; it < NT; it++) {
        const int kb = it * 64;
        cp_wait<2>();
        __syncthreads();
        if (it + 3 < NT) issue(it + 3, (it + 3) & 3);

        bf16*   sK = sm_ + (it & 3) * ASTG;
        __half* sV = (__half*)(sK + 64 * 72);

        // prefetch bias for this tile (hides under the S mma below)
        float2 bv0[8], bv1[8];
        #pragma unroll
        for (int nt = 0; nt < 8; nt++) {
            bv0[nt] = *(const float2*)(bp + kb + nt * 8);
            bv1[nt] = *(const float2*)(bp + kb + nt * 8 + 8 * S_LEN);
        }

        // S = Q @ K^T (128 x 64 tile per block, 16 x 64 per warp)
        float s[8][4];
        #pragma unroll
        for (int a = 0; a < 8; a++)
            #pragma unroll
            for (int b = 0; b < 4; b++) s[a][b] = 0.f;
        #pragma unroll
        for (int dc = 0; dc < 4; dc++) {
            #pragma unroll
            for (int np = 0; np < 4; np++) {
                uint32_t r0, r1, r2, r3;
                ldm4(r0, r1, r2, r3,
                     cvta_s(sK + (np * 16 + (l & 15)) * 72 + dc * 16 + ((l >> 4) * 8)));
                mma_bf(s[2 * np],     qf[dc], r0, r2);
                mma_bf(s[2 * np + 1], qf[dc], r1, r3);
            }
        }

        // p = exp(s*SCALE + bias); row sums
        #pragma unroll
        for (int nt = 0; nt < 8; nt++) {
            float p0 = __expf(fmaf(s[nt][0], SCALE, bv0[nt].x));
            float p1 = __expf(fmaf(s[nt][1], SCALE, bv0[nt].y));
            float p2 = __expf(fmaf(s[nt][2], SCALE, bv1[nt].x));
            float p3 = __expf(fmaf(s[nt][3], SCALE, bv1[nt].y));
            rs_lo += p0 + p1;  rs_hi += p2 + p3;
            s[nt][0] = p0; s[nt][1] = p1; s[nt][2] = p2; s[nt][3] = p3;
        }

        // O += P @ V  (single fp16 each)
        #pragma unroll
        for (int kt = 0; kt < 4; kt++) {
            uint32_t a[4];
            a[0] = packhf(s[2 * kt][0],     s[2 * kt][1]);
            a[1] = packhf(s[2 * kt][2],     s[2 * kt][3]);
            a[2] = packhf(s[2 * kt + 1][0], s[2 * kt + 1][1]);
            a[3] = packhf(s[2 * kt + 1][2], s[2 * kt + 1][3]);
            #pragma unroll
            for (int dp = 0; dp < 4; dp++) {
                uint32_t v0, v1, v2, v3;
                ldm4(v0, v1, v2, v3,
                     cvta_s(sV + (dp * 16 + (l & 15)) * 72 + kt * 16 + ((l >> 4) * 8)));
                mma_hf(oacc[2 * dp],     a, v0, v2);
                mma_hf(oacc[2 * dp + 1], a, v1, v3);
            }
        }
    }

    // finalize: quad-reduce row sums, normalize, emit fp16 att
    rs_lo += __shfl_xor_sync(0xffffffffu, rs_lo, 1);
    rs_lo += __shfl_xor_sync(0xffffffffu, rs_lo, 2);
    rs_hi += __shfl_xor_sync(0xffffffffu, rs_hi, 1);
    rs_hi += __shfl_xor_sync(0xffffffffu, rs_hi, 2);
    float il = 1.0f / rs_lo, ih = 1.0f / rs_hi;

    #pragma unroll
    for (int nt = 0; nt < 8; nt++) {
        int r = qb + w * 16 + (l >> 2);
        int c = h * DK + nt * 8 + (l & 3) * 2;
        size_t i0 = ((size_t)r * DM + c) >> 1;
        size_t i1 = ((size_t)(r + 8) * DM + c) >> 1;
        ((uint32_t*)v_att)[i0] = packhf(oacc[nt][0] * il, oacc[nt][1] * il);
        ((uint32_t*)v_att)[i1] = packhf(oacc[nt][2] * ih, oacc[nt][3] * ih);
    }
}

// ---------------- launcher ----------------
extern "C" void kernel_launch(void* const* d_in, const int* in_sizes, int n_in,
                              void* d_out, int out_size)
{
    (void)in_sizes; (void)n_in; (void)out_size;
    const float* Qin  = (const float*)d_in[0];
    const float* Kin  = (const float*)d_in[1];
    const float* Vin  = (const float*)d_in[2];
    const float* bias = (const float*)d_in[3];
    const float* Wq   = (const float*)d_in[4];
    const float* Wk   = (const float*)d_in[5];
    const float* Wv   = (const float*)d_in[6];
    const float* Wo   = (const float*)d_in[7];
    float* out = (float*)d_out;

    const int NPREP = 3 * (S_LEN * DM / 4) + 4 * (DM * DM / 4);
    prep_all<<<NPREP / 256, 256>>>((const float4*)Qin, (const float4*)Kin,
                                   (const float4*)Vin, (const float4*)Wq,
                                   (const float4*)Wk, (const float4*)Wv,
                                   (const float4*)Wo);

    // fused QKV projections: z=0 Q, z=1 K, z=2 V(3-term)
    const int smemG = 2 * GSTG * 2;                        // 75776 B
    cudaFuncSetAttribute(qkv_gemm,
                         cudaFuncAttributeMaxDynamicSharedMemorySize, smemG);
    qkv_gemm<<<dim3(DM / 128, S_LEN / 128, 3), 256, smemG>>>();

    const int smemA = 4 * ASTG * 2;                        // 73728 B
    cudaFuncSetAttribute(attn_mma,
                         cudaFuncAttributeMaxDynamicSharedMemorySize, smemA);
    attn_mma<<<dim3(S_LEN / 128, NH), 256, smemA>>>(bias);

    const int smemO = 2 * OSTG * 2;                        // 55296 B
    cudaFuncSetAttribute(out_gemm,
                         cudaFuncAttributeMaxDynamicSharedMemorySize, smemO);
    out_gemm<<<dim3(DM / 128, S_LEN / 128), 256, smemO>>>(out);
}

// round 10
// speedup vs baseline: 11.1678x; 1.0496x over previous
#include <cuda_runtime.h>
#include <cuda_bf16.h>
#include <cuda_fp16.h>
#include <math.h>
#include <stdint.h>

#define S_LEN 2048
#define DM    1024
#define NH    16
#define DK    64
#define SCALE 0.125f
#define EPSN  1e-6f

typedef __nv_bfloat16 bf16;

// ---------------- scratch (__device__ globals; allocation-free) ----------------
__device__ bf16   b_Qin[(size_t)S_LEN * DM];
__device__ bf16   b_Kin[(size_t)S_LEN * DM];
__device__ __half h_Vin[(size_t)S_LEN * DM];       // V input, single fp16
__device__ bf16   b_Wq[(size_t)DM * DM];
__device__ bf16   b_Wk[(size_t)DM * DM];
__device__ __half h_Wv_h[(size_t)DM * DM];         // W_v split fp16 hi/lo
__device__ __half h_Wv_l[(size_t)DM * DM];
__device__ __half h_Wo_h[(size_t)DM * DM];         // W_o split fp16 hi/lo
__device__ __half h_Wo_l[(size_t)DM * DM];

__device__ bf16   b_Qn[(size_t)NH * S_LEN * DK];   // normalized Q, [h][s][64]
__device__ bf16   b_Kn[(size_t)NH * S_LEN * DK];
__device__ __half v_Vt[(size_t)NH * DK * S_LEN];   // V^T fp16, [h][64][2048]

__device__ __half v_att[(size_t)S_LEN * DM];       // attended, single fp16

// ---------------- helpers ----------------
__device__ __forceinline__ uint32_t cvta_s(const void* p) {
    return (uint32_t)__cvta_generic_to_shared(p);
}
__device__ __forceinline__ void cp16(void* s, const void* g) {
    asm volatile("cp.async.cg.shared.global [%0],[%1],16;" ::
                 "r"(cvta_s(s)), "l"(g));
}
__device__ __forceinline__ void cp_commit() {
    asm volatile("cp.async.commit_group;");
}
template<int N>
__device__ __forceinline__ void cp_wait() {
    asm volatile("cp.async.wait_group %0;" :: "n"(N));
}
__device__ __forceinline__ void ldm4(uint32_t& r0, uint32_t& r1, uint32_t& r2, uint32_t& r3,
                                     uint32_t a) {
    asm volatile("ldmatrix.sync.aligned.m8n8.x4.shared.b16 {%0,%1,%2,%3},[%4];"
                 : "=r"(r0), "=r"(r1), "=r"(r2), "=r"(r3) : "r"(a));
}
__device__ __forceinline__ void ldm4t(uint32_t& r0, uint32_t& r1, uint32_t& r2, uint32_t& r3,
                                      uint32_t a) {
    asm volatile("ldmatrix.sync.aligned.m8n8.x4.trans.shared.b16 {%0,%1,%2,%3},[%4];"
                 : "=r"(r0), "=r"(r1), "=r"(r2), "=r"(r3) : "r"(a));
}
__device__ __forceinline__ void mma_bf(float c[4], const uint32_t a[4],
                                       uint32_t b0, uint32_t b1) {
    asm volatile(
        "mma.sync.aligned.m16n8k16.row.col.f32.bf16.bf16.f32 "
        "{%0,%1,%2,%3},{%4,%5,%6,%7},{%8,%9},{%0,%1,%2,%3};"
        : "+f"(c[0]), "+f"(c[1]), "+f"(c[2]), "+f"(c[3])
        : "r"(a[0]), "r"(a[1]), "r"(a[2]), "r"(a[3]), "r"(b0), "r"(b1));
}
__device__ __forceinline__ void mma_hf(float c[4], const uint32_t a[4],
                                       uint32_t b0, uint32_t b1) {
    asm volatile(
        "mma.sync.aligned.m16n8k16.row.col.f32.f16.f16.f32 "
        "{%0,%1,%2,%3},{%4,%5,%6,%7},{%8,%9},{%0,%1,%2,%3};"
        : "+f"(c[0]), "+f"(c[1]), "+f"(c[2]), "+f"(c[3])
        : "r"(a[0]), "r"(a[1]), "r"(a[2]), "r"(a[3]), "r"(b0), "r"(b1));
}
// pack two fp32 -> bf16x2 / f16x2; first arg in low 16 bits
__device__ __forceinline__ uint32_t packbf(float lo, float hi) {
    uint32_t r;
    asm("cvt.rn.bf16x2.f32 %0,%1,%2;" : "=r"(r) : "f"(hi), "f"(lo));
    return r;
}
__device__ __forceinline__ uint32_t packhf(float lo, float hi) {
    uint32_t r;
    asm("cvt.rn.f16x2.f32 %0,%1,%2;" : "=r"(r) : "f"(hi), "f"(lo));
    return r;
}
__device__ __forceinline__ float rbf(float x) {
    return __bfloat162float(__float2bfloat16(x));
}
__device__ __forceinline__ float rhf(float x) {
    return __half2float(__float2half(x));
}

// ---------------- fused conversions (one launch) ----------------
__device__ __forceinline__ void cvt1(const float4* x, uint32_t* y, int i) {
    float4 v = x[i];
    y[2 * i + 0] = packbf(v.x, v.y);
    y[2 * i + 1] = packbf(v.z, v.w);
}
__device__ __forceinline__ void cvt1h(const float4* x, uint32_t* y, int i) {
    float4 v = x[i];
    y[2 * i + 0] = packhf(v.x, v.y);
    y[2 * i + 1] = packhf(v.z, v.w);
}
__device__ __forceinline__ void split1h(const float4* x, uint32_t* hi, uint32_t* lo, int i) {
    float4 v = x[i];
    float hx = rhf(v.x), hy = rhf(v.y), hz = rhf(v.z), hw = rhf(v.w);
    hi[2 * i + 0] = packhf(hx, hy);
    hi[2 * i + 1] = packhf(hz, hw);
    lo[2 * i + 0] = packhf(v.x - hx, v.y - hy);
    lo[2 * i + 1] = packhf(v.z - hz, v.w - hw);
}
__global__ void prep_all(const float4* Qin, const float4* Kin, const float4* Vin,
                         const float4* Wq, const float4* Wk, const float4* Wv,
                         const float4* Wo)
{
    const int NI = S_LEN * DM / 4;
    const int NW = DM * DM / 4;
    int i = blockIdx.x * 256 + threadIdx.x;
    if (i < NI) { cvt1(Qin, (uint32_t*)b_Qin, i); return; }
    i -= NI;
    if (i < NI) { cvt1(Kin, (uint32_t*)b_Kin, i); return; }
    i -= NI;
    if (i < NI) { cvt1h(Vin, (uint32_t*)h_Vin, i); return; }
    i -= NI;
    if (i < NW) { cvt1(Wq, (uint32_t*)b_Wq, i); return; }
    i -= NW;
    if (i < NW) { cvt1(Wk, (uint32_t*)b_Wk, i); return; }
    i -= NW;
    if (i < NW) { split1h(Wv, (uint32_t*)h_Wv_h, (uint32_t*)h_Wv_l, i); return; }
    i -= NW;
    split1h(Wo, (uint32_t*)h_Wo_h, (uint32_t*)h_Wo_l, i);
}

// ---------------- fused QKV projection GEMM (one launch, z selects role) ----------------
// z==0: V = Vin(f16) @ (Wv_h + Wv_l)(f16), 2-term -> transpose fp16 emit to v_Vt
//       (heavy role scheduled FIRST: lowest block ids)
// z==1: Q = Qin@Wq (bf16 1-term) -> L2-norm bf16 emit to b_Qn
// z==2: K = Kin@Wk (bf16 1-term) -> L2-norm bf16 emit to b_Kn
#define GSTG (128 * 40 + 2 * 32 * 136)   // elems/stage: A + Bh + Bl = 13824

__global__ void __launch_bounds__(256, 2)
qkv_gemm()
{
    extern __shared__ bf16 sm_[];
    const int z = blockIdx.z;
    const bool vrole = (z == 0);
    const char* Ap = vrole ? (const char*)h_Vin : (z == 1) ? (const char*)b_Qin
                                                           : (const char*)b_Kin;
    const char* Bp = vrole ? (const char*)h_Wv_h : (z == 1) ? (const char*)b_Wq
                                                            : (const char*)b_Wk;

    const int tid = threadIdx.x;
    const int w = tid >> 5, l = tid & 31;
    const int wm = (w >> 2) * 64, wn = (w & 3) * 32;
    const int row0 = blockIdx.y * 128, col0 = blockIdx.x * 128;
    const int NT = DM / 32;

    auto issue = [&](int it, int stg) {
        bf16* dA  = sm_ + stg * GSTG;
        bf16* dBh = dA + 128 * 40;
        bf16* dBl = dBh + 32 * 136;
        int k0 = it * 32;
        #pragma unroll
        for (int i = 0; i < 2; i++) {
            int pos = tid + i * 256;
            int r = pos >> 2, c = (pos & 3) * 8;
            cp16(dA + r * 40 + c, Ap + ((size_t)(row0 + r) * DM + k0 + c) * 2);
        }
        #pragma unroll
        for (int i = 0; i < 2; i++) {
            int pos = tid + i * 256;
            int r = pos >> 4, c = (pos & 15) * 8;
            cp16(dBh + r * 136 + c, Bp + ((size_t)(k0 + r) * DM + col0 + c) * 2);
            if (vrole)
                cp16(dBl + r * 136 + c, h_Wv_l + (size_t)(k0 + r) * DM + col0 + c);
        }
        cp_commit();
    };

    float acc[4][4][4];
    #pragma unroll
    for (int a = 0; a < 4; a++)
        #pragma unroll
        for (int b = 0; b < 4; b++)
            #pragma unroll
            for (int c = 0; c < 4; c++) acc[a][b][c] = 0.f;

    issue(0, 0);

    for (int it = 0; it < NT; it++) {
        cp_wait<0>();
        __syncthreads();
        if (it + 1 < NT) issue(it + 1, (it + 1) & 1);

        bf16* sA  = sm_ + (it & 1) * GSTG;
        bf16* sBh = sA + 128 * 40;
        bf16* sBl = sBh + 32 * 136;

        #pragma unroll
        for (int kc = 0; kc < 2; kc++) {
            uint32_t af[4][4], bfh[2][4];
            #pragma unroll
            for (int mt = 0; mt < 4; mt++)
                ldm4(af[mt][0], af[mt][1], af[mt][2], af[mt][3],
                     cvta_s(sA + (wm + mt * 16 + (l & 15)) * 40 + kc * 16 + ((l >> 4) * 8)));
            #pragma unroll
            for (int np = 0; np < 2; np++)
                ldm4t(bfh[np][0], bfh[np][1], bfh[np][2], bfh[np][3],
                      cvta_s(sBh + (kc * 16 + (l & 15)) * 136 + wn + np * 16 + ((l >> 4) * 8)));
            if (!vrole) {
                #pragma unroll
                for (int mt = 0; mt < 4; mt++)
                    #pragma unroll
                    for (int nt = 0; nt < 4; nt++)
                        mma_bf(acc[mt][nt], af[mt],
                               bfh[nt >> 1][(nt & 1) * 2], bfh[nt >> 1][(nt & 1) * 2 + 1]);
            } else {
                uint32_t bfl[2][4];
                #pragma unroll
                for (int np = 0; np < 2; np++)
                    ldm4t(bfl[np][0], bfl[np][1], bfl[np][2], bfl[np][3],
                          cvta_s(sBl + (kc * 16 + (l & 15)) * 136 + wn + np * 16 + ((l >> 4) * 8)));
                #pragma unroll
                for (int mt = 0; mt < 4; mt++)
                    #pragma unroll
                    for (int nt = 0; nt < 4; nt++) {
                        mma_hf(acc[mt][nt], af[mt],
                               bfh[nt >> 1][(nt & 1) * 2], bfh[nt >> 1][(nt & 1) * 2 + 1]);
                        mma_hf(acc[mt][nt], af[mt],
                               bfl[nt >> 1][(nt & 1) * 2], bfl[nt >> 1][(nt & 1) * 2 + 1]);
                    }
            }
        }
    }
    __syncthreads();   // protect smem reuse in epilogues

    if (!vrole) {
        // fused L2 norm over d (two 64-wide heads inside this 128-col tile)
        float* sq = (float*)sm_;                 // 128 rows x 16 (2 heads x 8 partials)
        const int cw = w & 3;
        const int hl = cw >> 1;
        const int slot = (cw & 1) * 4 + (l & 3);
        #pragma unroll
        for (int mt = 0; mt < 4; mt++) {
            float p0 = 0.f, p1 = 0.f;
            #pragma unroll
            for (int nt = 0; nt < 4; nt++) {
                p0 += acc[mt][nt][0] * acc[mt][nt][0] + acc[mt][nt][1] * acc[mt][nt][1];
                p1 += acc[mt][nt][2] * acc[mt][nt][2] + acc[mt][nt][3] * acc[mt][nt][3];
            }
            int rl = wm + mt * 16 + (l >> 2);
            sq[rl * 16 + hl * 8 + slot] = p0;
            sq[(rl + 8) * 16 + hl * 8 + slot] = p1;
        }
        __syncthreads();

        bf16* dst = (z == 1) ? b_Qn : b_Kn;
        const int hg = (col0 >> 6) + hl;
        #pragma unroll
        for (int mt = 0; mt < 4; mt++) {
            int rl = wm + mt * 16 + (l >> 2);
            float ss0 = 0.f, ss1 = 0.f;
            #pragma unroll
            for (int s = 0; s < 8; s++) {
                ss0 += sq[rl * 16 + hl * 8 + s];
                ss1 += sq[(rl + 8) * 16 + hl * 8 + s];
            }
            float inv0 = 1.0f / (sqrtf(ss0) + EPSN);
            float inv1 = 1.0f / (sqrtf(ss1) + EPSN);
            #pragma unroll
            for (int nt = 0; nt < 4; nt++) {
                int d = (wn & 63) + nt * 8 + (l & 3) * 2;
                ((uint32_t*)dst)[((size_t)hg * S_LEN + row0 + rl) * 32 + (d >> 1)] =
                    packbf(acc[mt][nt][0] * inv0, acc[mt][nt][1] * inv0);
                ((uint32_t*)dst)[((size_t)hg * S_LEN + row0 + rl + 8) * 32 + (d >> 1)] =
                    packbf(acc[mt][nt][2] * inv1, acc[mt][nt][3] * inv1);
            }
        }
    } else {
        // transpose, emit v_Vt (single fp16) [h][d][s]
        __half* sh = (__half*)sm_;
        #pragma unroll
        for (int mt = 0; mt < 4; mt++) {
            int rl = wm + mt * 16 + (l >> 2);
            #pragma unroll
            for (int nt = 0; nt < 4; nt++) {
                int c0 = wn + nt * 8 + (l & 3) * 2;
                #pragma unroll
                for (int j = 0; j < 2; j++) {
                    sh[(c0 + j) * 136 + rl]     = __float2half(acc[mt][nt][j]);
                    sh[(c0 + j) * 136 + rl + 8] = __float2half(acc[mt][nt][2 + j]);
                }
            }
        }
        __syncthreads();
        int cl = tid >> 1, soff = (tid & 1) * 64;
        int hg = (col0 + cl) >> 6, d = (col0 + cl) & 63;
        size_t gbase = ((size_t)hg * DK + d) * S_LEN + row0 + soff;
        const uint4* srch = (const uint4*)(sh + cl * 136 + soff);
        uint4* gh = (uint4*)(v_Vt + gbase);
        #pragma unroll
        for (int i = 0; i < 8; i++) gh[i] = srch[i];
    }
}

// ---------------- out GEMM: 128x64 tiles (grid 256), 2-term fp16 ----------------
#define OSTG (128 * 40 + 2 * 32 * 72)    // elems/stage: A + Bh + Bl = 9728

__global__ void __launch_bounds__(256, 2)
out_gemm(float* __restrict__ out)
{
    extern __shared__ __half smh_[];

    const int tid = threadIdx.x;
    const int w = tid >> 5, l = tid & 31;
    const int wm = (w & 3) * 32, wn = (w >> 2) * 32;     // 4 M-warps x 2 N-warps
    const int row0 = blockIdx.y * 128, col0 = blockIdx.x * 64;
    const int NT = DM / 32;

    auto issue = [&](int it, int stg) {
        __half* dA  = smh_ + stg * OSTG;
        __half* dBh = dA + 128 * 40;
        __half* dBl = dBh + 32 * 72;
        int k0 = it * 32;
        #pragma unroll
        for (int i = 0; i < 2; i++) {
            int pos = tid + i * 256;
            int r = pos >> 2, c = (pos & 3) * 8;
            cp16(dA + r * 40 + c, v_att + (size_t)(row0 + r) * DM + k0 + c);
        }
        {
            int r = tid >> 3, c = (tid & 7) * 8;
            cp16(dBh + r * 72 + c, h_Wo_h + (size_t)(k0 + r) * DM + col0 + c);
            cp16(dBl + r * 72 + c, h_Wo_l + (size_t)(k0 + r) * DM + col0 + c);
        }
        cp_commit();
    };

    float acc[2][4][4];
    #pragma unroll
    for (int a = 0; a < 2; a++)
        #pragma unroll
        for (int b = 0; b < 4; b++)
            #pragma unroll
            for (int c = 0; c < 4; c++) acc[a][b][c] = 0.f;

    issue(0, 0);

    for (int it = 0; it < NT; it++) {
        cp_wait<0>();
        __syncthreads();
        if (it + 1 < NT) issue(it + 1, (it + 1) & 1);

        __half* sA  = smh_ + (it & 1) * OSTG;
        __half* sBh = sA + 128 * 40;
        __half* sBl = sBh + 32 * 72;

        #pragma unroll
        for (int kc = 0; kc < 2; kc++) {
            uint32_t af[2][4], bh[2][4], bl[2][4];
            #pragma unroll
            for (int mt = 0; mt < 2; mt++)
                ldm4(af[mt][0], af[mt][1], af[mt][2], af[mt][3],
                     cvta_s(sA + (wm + mt * 16 + (l & 15)) * 40 + kc * 16 + ((l >> 4) * 8)));
            #pragma unroll
            for (int np = 0; np < 2; np++) {
                ldm4t(bh[np][0], bh[np][1], bh[np][2], bh[np][3],
                      cvta_s(sBh + (kc * 16 + (l & 15)) * 72 + wn + np * 16 + ((l >> 4) * 8)));
                ldm4t(bl[np][0], bl[np][1], bl[np][2], bl[np][3],
                      cvta_s(sBl + (kc * 16 + (l & 15)) * 72 + wn + np * 16 + ((l >> 4) * 8)));
            }
            #pragma unroll
            for (int mt = 0; mt < 2; mt++)
                #pragma unroll
                for (int nt = 0; nt < 4; nt++) {
                    mma_hf(acc[mt][nt], af[mt],
                           bh[nt >> 1][(nt & 1) * 2], bh[nt >> 1][(nt & 1) * 2 + 1]);
                    mma_hf(acc[mt][nt], af[mt],
                           bl[nt >> 1][(nt & 1) * 2], bl[nt >> 1][(nt & 1) * 2 + 1]);
                }
        }
    }

    #pragma unroll
    for (int mt = 0; mt < 2; mt++) {
        int r = row0 + wm + mt * 16 + (l >> 2);
        #pragma unroll
        for (int nt = 0; nt < 4; nt++) {
            int c = col0 + wn + nt * 8 + (l & 3) * 2;
            *(float2*)&out[(size_t)r * DM + c] =
                make_float2(acc[mt][nt][0], acc[mt][nt][1]);
            *(float2*)&out[(size_t)(r + 8) * DM + c] =
                make_float2(acc[mt][nt][2], acc[mt][nt][3]);
        }
    }
}

// ---------------- fused attention: fp16 P & V, 4-stage cp.async, 1 sync/tile ----------------
#define ASTG (2 * 64 * 72)   // per-stage elems (K bf16 + V f16) = 9216

__global__ void __launch_bounds__(256, 2) attn_mma(const float* __restrict__ bias)
{
    extern __shared__ bf16 sm_[];

    const int tid = threadIdx.x, w = tid >> 5, l = tid & 31;
    const int h = blockIdx.y, qb = blockIdx.x * 128;

    // stage Q tile (128x64) through stage-0/1 area, grab fragments
    #pragma unroll
    for (int i = 0; i < 4; i++) {
        int pos = tid + i * 256;
        int r = pos >> 3, c = (pos & 7) * 8;
        *(uint4*)(sm_ + r * 72 + c) =
            *(const uint4*)(b_Qn + ((size_t)h * S_LEN + qb + r) * DK + c);
    }
    __syncthreads();
    uint32_t qf[4][4];
    #pragma unroll
    for (int dc = 0; dc < 4; dc++)
        ldm4(qf[dc][0], qf[dc][1], qf[dc][2], qf[dc][3],
             cvta_s(sm_ + (w * 16 + (l & 15)) * 72 + dc * 16 + ((l >> 4) * 8)));
    __syncthreads();

    auto issue = [&](int it, int stg) {
        bf16*   dK = sm_ + stg * ASTG;
        __half* dV = (__half*)(dK + 64 * 72);
        int kb = it * 64;
        #pragma unroll
        for (int i = 0; i < 2; i++) {
            int pos = tid + i * 256;
            int r = pos >> 3, c = (pos & 7) * 8;
            cp16(dK + r * 72 + c, b_Kn + ((size_t)h * S_LEN + kb + r) * DK + c);
            cp16(dV + r * 72 + c, v_Vt + ((size_t)h * DK + r) * S_LEN + kb + c);
        }
        cp_commit();
    };

    float oacc[8][4];
    #pragma unroll
    for (int a = 0; a < 8; a++)
        #pragma unroll
        for (int b = 0; b < 4; b++) oacc[a][b] = 0.f;
    float rs_lo = 0.f, rs_hi = 0.f;

    const float* bp = bias + ((size_t)h * S_LEN + qb + w * 16 + (l >> 2)) * S_LEN + (l & 3) * 2;

    issue(0, 0);
    issue(1, 1);
    issue(2, 2);

    const int NT = S_LEN / 64;
    for (int it = 0; it < NT; it++) {
        const int kb = it * 64;
        cp_wait<2>();
        __syncthreads();
        if (it + 3 < NT) issue(it + 3, (it + 3) & 3);

        bf16*   sK = sm_ + (it & 3) * ASTG;
        __half* sV = (__half*)(sK + 64 * 72);

        // prefetch bias for this tile (hides under the S mma below)
        float2 bv0[8], bv1[8];
        #pragma unroll
        for (int nt = 0; nt < 8; nt++) {
            bv0[nt] = *(const float2*)(bp + kb + nt * 8);
            bv1[nt] = *(const float2*)(bp + kb + nt * 8 + 8 * S_LEN);
        }

        // S = Q @ K^T (128 x 64 tile per block, 16 x 64 per warp)
        float s[8][4];
        #pragma unroll
        for (int a = 0; a < 8; a++)
            #pragma unroll
            for (int b = 0; b < 4; b++) s[a][b] = 0.f;
        #pragma unroll
        for (int dc = 0; dc < 4; dc++) {
            #pragma unroll
            for (int np = 0; np < 4; np++) {
                uint32_t r0, r1, r2, r3;
                ldm4(r0, r1, r2, r3,
                     cvta_s(sK + (np * 16 + (l & 15)) * 72 + dc * 16 + ((l >> 4) * 8)));
                mma_bf(s[2 * np],     qf[dc], r0, r2);
                mma_bf(s[2 * np + 1], qf[dc], r1, r3);
            }
        }

        // p = exp(s*SCALE + bias); row sums
        #pragma unroll
        for (int nt = 0; nt < 8; nt++) {
            float p0 = __expf(fmaf(s[nt][0], SCALE, bv0[nt].x));
            float p1 = __expf(fmaf(s[nt][1], SCALE, bv0[nt].y));
            float p2 = __expf(fmaf(s[nt][2], SCALE, bv1[nt].x));
            float p3 = __expf(fmaf(s[nt][3], SCALE, bv1[nt].y));
            rs_lo += p0 + p1;  rs_hi += p2 + p3;
            s[nt][0] = p0; s[nt][1] = p1; s[nt][2] = p2; s[nt][3] = p3;
        }

        // O += P @ V  (single fp16 each)
        #pragma unroll
        for (int kt = 0; kt < 4; kt++) {
            uint32_t a[4];
            a[0] = packhf(s[2 * kt][0],     s[2 * kt][1]);
            a[1] = packhf(s[2 * kt][2],     s[2 * kt][3]);
            a[2] = packhf(s[2 * kt + 1][0], s[2 * kt + 1][1]);
            a[3] = packhf(s[2 * kt + 1][2], s[2 * kt + 1][3]);
            #pragma unroll
            for (int dp = 0; dp < 4; dp++) {
                uint32_t v0, v1, v2, v3;
                ldm4(v0, v1, v2, v3,
                     cvta_s(sV + (dp * 16 + (l & 15)) * 72 + kt * 16 + ((l >> 4) * 8)));
                mma_hf(oacc[2 * dp],     a, v0, v2);
                mma_hf(oacc[2 * dp + 1], a, v1, v3);
            }
        }
    }

    // finalize: quad-reduce row sums, normalize, emit fp16 att
    rs_lo += __shfl_xor_sync(0xffffffffu, rs_lo, 1);
    rs_lo += __shfl_xor_sync(0xffffffffu, rs_lo, 2);
    rs_hi += __shfl_xor_sync(0xffffffffu, rs_hi, 1);
    rs_hi += __shfl_xor_sync(0xffffffffu, rs_hi, 2);
    float il = 1.0f / rs_lo, ih = 1.0f / rs_hi;

    #pragma unroll
    for (int nt = 0; nt < 8; nt++) {
        int r = qb + w * 16 + (l >> 2);
        int c = h * DK + nt * 8 + (l & 3) * 2;
        size_t i0 = ((size_t)r * DM + c) >> 1;
        size_t i1 = ((size_t)(r + 8) * DM + c) >> 1;
        ((uint32_t*)v_att)[i0] = packhf(oacc[nt][0] * il, oacc[nt][1] * il);
        ((uint32_t*)v_att)[i1] = packhf(oacc[nt][2] * ih, oacc[nt][3] * ih);
    }
}

// ---------------- launcher ----------------
extern "C" void kernel_launch(void* const* d_in, const int* in_sizes, int n_in,
                              void* d_out, int out_size)
{
    (void)in_sizes; (void)n_in; (void)out_size;
    const float* Qin  = (const float*)d_in[0];
    const float* Kin  = (const float*)d_in[1];
    const float* Vin  = (const float*)d_in[2];
    const float* bias = (const float*)d_in[3];
    const float* Wq   = (const float*)d_in[4];
    const float* Wk   = (const float*)d_in[5];
    const float* Wv   = (const float*)d_in[6];
    const float* Wo   = (const float*)d_in[7];
    float* out = (float*)d_out;

    const int NPREP = 3 * (S_LEN * DM / 4) + 4 * (DM * DM / 4);
    prep_all<<<NPREP / 256, 256>>>((const float4*)Qin, (const float4*)Kin,
                                   (const float4*)Vin, (const float4*)Wq,
                                   (const float4*)Wk, (const float4*)Wv,
                                   (const float4*)Wo);

    // fused QKV projections: z=0 V (heavy, scheduled first), z=1 Q, z=2 K
    const int smemG = 2 * GSTG * 2;                        // 55296 B
    cudaFuncSetAttribute(qkv_gemm,
                         cudaFuncAttributeMaxDynamicSharedMemorySize, smemG);
    qkv_gemm<<<dim3(DM / 128, S_LEN / 128, 3), 256, smemG>>>();

    const int smemA = 4 * ASTG * 2;                        // 73728 B
    cudaFuncSetAttribute(attn_mma,
                         cudaFuncAttributeMaxDynamicSharedMemorySize, smemA);
    attn_mma<<<dim3(S_LEN / 128, NH), 256, smemA>>>(bias);

    const int smemO = 2 * OSTG * 2;                        // 38912 B
    cudaFuncSetAttribute(out_gemm,
                         cudaFuncAttributeMaxDynamicSharedMemorySize, smemO);
    out_gemm<<<dim3(DM / 64, S_LEN / 128), 256, smemO>>>(out);
}